// round 7
// baseline (speedup 1.0000x reference)
#include <cuda_runtime.h>
#include <cuda_fp16.h>
#include <stdint.h>

#define NN 100000
#define EE 1600000
#define DD 128

#define SCAN_CH  1024
#define SCAN_NB  ((NN + SCAN_CH - 1) / SCAN_CH)   // 98

#define HT_STRIDE 132
#define BS_STRIDE 136
#define FUSED_SMEM  (128 * HT_STRIDE * 4 + 32 * BS_STRIDE * 4)   // 84992
#define FUSED5_SMEM (128 * HT_STRIDE * 4)                        // 67584

// ---------------- scratch (static __device__, no allocation) ----------------
__device__ float  g_deg[NN];            // deg, then dinv in place
__device__ int    g_cnt[NN];
__device__ int    g_rowptr[NN + 1];
__device__ int    g_fill[NN];
__device__ int    g_bsum[SCAN_NB];
__device__ int    g_boff[SCAN_NB];
__device__ __align__(16) int2 g_pair[EE + NN];   // packed {col, val_bits}
__device__ __half g_ZhA[NN * DD];       // ping-pong fp16 feature buffers
__device__ __half g_ZhB[NN * DD];
__device__ float  g_Z5[NN * 2];

// ---------------- graph preprocessing ----------------
__global__ void init_kernel() {
    int i = blockIdx.x * blockDim.x + threadIdx.x;
    if (i < NN) {
        g_deg[i]  = 1.0f;   // self-loop weight
        g_cnt[i]  = 1;      // self-loop edge
        g_fill[i] = 0;
    }
}

__global__ void deg_cnt_kernel(const int* __restrict__ ei,
                               const float* __restrict__ w) {
    int e = blockIdx.x * blockDim.x + threadIdx.x;
    if (e >= EE) return;
    int d = ei[EE + e];
    atomicAdd(&g_deg[d], w[e]);
    atomicAdd(&g_cnt[d], 1);
}

__global__ void dinv_kernel() {
    int i = blockIdx.x * blockDim.x + threadIdx.x;
    if (i < NN) g_deg[i] = rsqrtf(g_deg[i]);   // deg >= 1 always (self-loop)
}

// ---- 3-phase exclusive scan of g_cnt -> g_rowptr ----
__global__ __launch_bounds__(SCAN_CH) void scanA_kernel() {
    __shared__ int s[SCAN_CH];
    int t = threadIdx.x;
    int idx = blockIdx.x * SCAN_CH + t;
    s[t] = (idx < NN) ? g_cnt[idx] : 0;
    __syncthreads();
    for (int off = SCAN_CH >> 1; off > 0; off >>= 1) {
        if (t < off) s[t] += s[t + off];
        __syncthreads();
    }
    if (t == 0) g_bsum[blockIdx.x] = s[0];
}

__global__ void scanB_kernel() {
    __shared__ int s[SCAN_NB];
    int t = threadIdx.x;
    if (t < SCAN_NB) s[t] = g_bsum[t];
    __syncthreads();
    if (t == 0) {
        int run = 0;
        for (int i = 0; i < SCAN_NB; i++) { int v = s[i]; s[i] = run; run += v; }
    }
    __syncthreads();
    if (t < SCAN_NB) g_boff[t] = s[t];
}

__global__ __launch_bounds__(SCAN_CH) void scanC_kernel() {
    __shared__ int s[SCAN_CH];
    int t = threadIdx.x;
    int idx = blockIdx.x * SCAN_CH + t;
    int my = (idx < NN) ? g_cnt[idx] : 0;
    s[t] = my;
    __syncthreads();
    for (int off = 1; off < SCAN_CH; off <<= 1) {
        int u = 0;
        if (t >= off) u = s[t - off];
        __syncthreads();
        s[t] += u;
        __syncthreads();
    }
    if (idx < NN) g_rowptr[idx] = g_boff[blockIdx.x] + s[t] - my;  // exclusive
    if (idx == NN - 1) g_rowptr[NN] = EE + NN;                      // known total
}

__global__ void csr_fill_kernel(const int* __restrict__ ei,
                                const float* __restrict__ w) {
    int e = blockIdx.x * blockDim.x + threadIdx.x;
    if (e < EE) {
        int s = ei[e];
        int d = ei[EE + e];
        int pos = g_rowptr[d] + atomicAdd(&g_fill[d], 1);
        float v = g_deg[s] * w[e] * g_deg[d];       // g_deg holds dinv now
        g_pair[pos] = make_int2(s, __float_as_int(v));
    } else if (e < EE + NN) {
        int i = e - EE;
        int pos = g_rowptr[i] + atomicAdd(&g_fill[i], 1);
        float di = g_deg[i];
        g_pair[pos] = make_int2(i, __float_as_int(di * di));
    }
}

__device__ __forceinline__ uint32_t f2tf32(float f) {
    uint32_t u;
    asm("cvt.rna.tf32.f32 %0, %1;" : "=r"(u) : "f"(f));
    return u;
}

// ---- shared device helper: warp-aggregate one node into a float4 (lane slice) --
__device__ __forceinline__ float4 warp_agg_node(const __half* __restrict__ Zl, int node) {
    int i   = g_rowptr[node];
    int end = g_rowptr[node + 1];
    float4 acc = make_float4(0.f, 0.f, 0.f, 0.f);
    if ((i & 1) && i < end) {
        int2 p = g_pair[i];
        float v = __int_as_float(p.y);
        const __half2* q = reinterpret_cast<const __half2*>(Zl + (size_t)p.x * DD);
        __half2 a = q[0], d = q[1];
        float2 f;
        f = __half22float2(a); acc.x = fmaf(v, f.x, acc.x); acc.y = fmaf(v, f.y, acc.y);
        f = __half22float2(d); acc.z = fmaf(v, f.x, acc.z); acc.w = fmaf(v, f.y, acc.w);
        i++;
    }
    for (; i + 4 <= end; i += 4) {
        int4 pA = *reinterpret_cast<const int4*>(&g_pair[i]);
        int4 pB = *reinterpret_cast<const int4*>(&g_pair[i + 2]);
        float v0 = __int_as_float(pA.y), v1 = __int_as_float(pA.w);
        float v2 = __int_as_float(pB.y), v3 = __int_as_float(pB.w);
        const __half2* p0 = reinterpret_cast<const __half2*>(Zl + (size_t)pA.x * DD);
        const __half2* p1 = reinterpret_cast<const __half2*>(Zl + (size_t)pA.z * DD);
        const __half2* p2 = reinterpret_cast<const __half2*>(Zl + (size_t)pB.x * DD);
        const __half2* p3 = reinterpret_cast<const __half2*>(Zl + (size_t)pB.z * DD);
        __half2 a0 = p0[0], b0 = p0[1];
        __half2 a1 = p1[0], b1 = p1[1];
        __half2 a2 = p2[0], b2 = p2[1];
        __half2 a3 = p3[0], b3 = p3[1];
        float2 f;
        f = __half22float2(a0); acc.x = fmaf(v0, f.x, acc.x); acc.y = fmaf(v0, f.y, acc.y);
        f = __half22float2(b0); acc.z = fmaf(v0, f.x, acc.z); acc.w = fmaf(v0, f.y, acc.w);
        f = __half22float2(a1); acc.x = fmaf(v1, f.x, acc.x); acc.y = fmaf(v1, f.y, acc.y);
        f = __half22float2(b1); acc.z = fmaf(v1, f.x, acc.z); acc.w = fmaf(v1, f.y, acc.w);
        f = __half22float2(a2); acc.x = fmaf(v2, f.x, acc.x); acc.y = fmaf(v2, f.y, acc.y);
        f = __half22float2(b2); acc.z = fmaf(v2, f.x, acc.z); acc.w = fmaf(v2, f.y, acc.w);
        f = __half22float2(a3); acc.x = fmaf(v3, f.x, acc.x); acc.y = fmaf(v3, f.y, acc.y);
        f = __half22float2(b3); acc.z = fmaf(v3, f.x, acc.z); acc.w = fmaf(v3, f.y, acc.w);
    }
    for (; i < end; i++) {
        int2 p = g_pair[i];
        float v = __int_as_float(p.y);
        const __half2* q = reinterpret_cast<const __half2*>(Zl + (size_t)p.x * DD);
        __half2 a = q[0], d = q[1];
        float2 f;
        f = __half22float2(a); acc.x = fmaf(v, f.x, acc.x); acc.y = fmaf(v, f.y, acc.y);
        f = __half22float2(d); acc.z = fmaf(v, f.x, acc.z); acc.w = fmaf(v, f.y, acc.w);
    }
    return acc;
}

// ---------------- tf32 tensor-core GEMM (layer 1): Zh = A @ B, A fp32 gmem ----
#define GBM 128
#define GBK 32
#define AS_STRIDE 36

__global__ __launch_bounds__(256) void gemm_tf32_kernel(const float* __restrict__ A,
                                                        const float* __restrict__ B,
                                                        __half* __restrict__ C, int M) {
    __shared__ uint32_t As[GBM * AS_STRIDE];   // [m][k]
    __shared__ uint32_t Bs[GBK * BS_STRIDE];   // [k][n]
    const int tid  = threadIdx.x;
    const int wid  = tid >> 5;
    const int lane = tid & 31;
    const int g    = lane >> 2;
    const int tig  = lane & 3;
    const int warp_m = wid & 3;
    const int warp_n = wid >> 2;
    const int m0 = blockIdx.x * GBM;

    float acc[2][8][4];
#pragma unroll
    for (int mi = 0; mi < 2; mi++)
#pragma unroll
        for (int ni = 0; ni < 8; ni++)
#pragma unroll
            for (int q = 0; q < 4; q++) acc[mi][ni][q] = 0.0f;

    for (int k0 = 0; k0 < 128; k0 += GBK) {
#pragma unroll
        for (int it = 0; it < 4; it++) {
            int idx = tid + it * 256;
            int row = idx >> 3;
            int c4  = (idx & 7) * 4;
            float4 a = make_float4(0.f, 0.f, 0.f, 0.f);
            if (m0 + row < M)
                a = *reinterpret_cast<const float4*>(A + (size_t)(m0 + row) * DD + k0 + c4);
            uint4 u = make_uint4(f2tf32(a.x), f2tf32(a.y), f2tf32(a.z), f2tf32(a.w));
            *reinterpret_cast<uint4*>(&As[row * AS_STRIDE + c4]) = u;
        }
#pragma unroll
        for (int it = 0; it < 4; it++) {
            int idx = tid + it * 256;
            int row = idx >> 5;
            int c4  = (idx & 31) * 4;
            float4 b = *reinterpret_cast<const float4*>(B + (size_t)(k0 + row) * 128 + c4);
            uint4 u = make_uint4(f2tf32(b.x), f2tf32(b.y), f2tf32(b.z), f2tf32(b.w));
            *reinterpret_cast<uint4*>(&Bs[row * BS_STRIDE + c4]) = u;
        }
        __syncthreads();
#pragma unroll
        for (int ks = 0; ks < 4; ks++) {
            const int kk = ks * 8;
            uint32_t af[2][4], bf[8][2];
#pragma unroll
            for (int mi = 0; mi < 2; mi++) {
                int rm = warp_m * 32 + mi * 16;
                af[mi][0] = As[(rm + g    ) * AS_STRIDE + kk + tig    ];
                af[mi][1] = As[(rm + g + 8) * AS_STRIDE + kk + tig    ];
                af[mi][2] = As[(rm + g    ) * AS_STRIDE + kk + tig + 4];
                af[mi][3] = As[(rm + g + 8) * AS_STRIDE + kk + tig + 4];
            }
#pragma unroll
            for (int ni = 0; ni < 8; ni++) {
                int nb = warp_n * 64 + ni * 8;
                bf[ni][0] = Bs[(kk + tig    ) * BS_STRIDE + nb + g];
                bf[ni][1] = Bs[(kk + tig + 4) * BS_STRIDE + nb + g];
            }
#pragma unroll
            for (int mi = 0; mi < 2; mi++)
#pragma unroll
                for (int ni = 0; ni < 8; ni++) {
                    asm volatile(
                        "mma.sync.aligned.m16n8k8.row.col.f32.tf32.tf32.f32 "
                        "{%0,%1,%2,%3}, {%4,%5,%6,%7}, {%8,%9}, {%0,%1,%2,%3};\n"
                        : "+f"(acc[mi][ni][0]), "+f"(acc[mi][ni][1]),
                          "+f"(acc[mi][ni][2]), "+f"(acc[mi][ni][3])
                        : "r"(af[mi][0]), "r"(af[mi][1]), "r"(af[mi][2]), "r"(af[mi][3]),
                          "r"(bf[ni][0]), "r"(bf[ni][1]));
                }
        }
        __syncthreads();
    }
#pragma unroll
    for (int mi = 0; mi < 2; mi++) {
        int row0 = m0 + warp_m * 32 + mi * 16 + g;
#pragma unroll
        for (int ni = 0; ni < 8; ni++) {
            int col = warp_n * 64 + ni * 8 + tig * 2;
            if (row0 < M)
                *reinterpret_cast<__half2*>(C + (size_t)row0 * DD + col) =
                    __floats2half2_rn(acc[mi][ni][0], acc[mi][ni][1]);
            if (row0 + 8 < M)
                *reinterpret_cast<__half2*>(C + (size_t)(row0 + 8) * DD + col) =
                    __floats2half2_rn(acc[mi][ni][2], acc[mi][ni][3]);
        }
    }
}

// ---------------- fused agg_k -> gemm_{k+1}: Zn = (relu(S@Zp + b)) @ W --------
template <bool RELU>
__global__ __launch_bounds__(256, 2) void fused_agg_gemm_kernel(
    const __half* __restrict__ Zp, const float* __restrict__ bias,
    const float* __restrict__ W, __half* __restrict__ Zn) {
    extern __shared__ float sm[];
    float*    Ht = sm;                                    // [128][HT_STRIDE]
    uint32_t* Bs = (uint32_t*)(sm + 128 * HT_STRIDE);     // [32][BS_STRIDE]
    const int tid  = threadIdx.x;
    const int wid  = tid >> 5;
    const int lane = tid & 31;
    const int m0 = blockIdx.x * 128;
    const __half* Zl = Zp + lane * 4;
    const float4 bb = *reinterpret_cast<const float4*>(bias + lane * 4);

    // ---- phase 1: aggregate 16 nodes per warp into smem tile ----
#pragma unroll 1
    for (int t = 0; t < 16; t++) {
        int r = wid * 16 + t;
        int node = m0 + r;
        float4 acc = make_float4(0.f, 0.f, 0.f, 0.f);
        if (node < NN) {
            acc = warp_agg_node(Zl, node);
            acc.x += bb.x; acc.y += bb.y; acc.z += bb.z; acc.w += bb.w;
            if (RELU) {
                acc.x = fmaxf(acc.x, 0.f); acc.y = fmaxf(acc.y, 0.f);
                acc.z = fmaxf(acc.z, 0.f); acc.w = fmaxf(acc.w, 0.f);
            }
        }
        *reinterpret_cast<float4*>(Ht + r * HT_STRIDE + lane * 4) = acc;
    }
    __syncthreads();

    // ---- phase 2: tf32 MMA, A from Ht (fp32, cvt at load), W streamed in k-chunks
    const int g    = lane >> 2;
    const int tig  = lane & 3;
    const int warp_m = wid & 3;
    const int warp_n = wid >> 2;

    float acc[2][8][4];
#pragma unroll
    for (int mi = 0; mi < 2; mi++)
#pragma unroll
        for (int ni = 0; ni < 8; ni++)
#pragma unroll
            for (int q = 0; q < 4; q++) acc[mi][ni][q] = 0.0f;

    for (int k0 = 0; k0 < 128; k0 += GBK) {
#pragma unroll
        for (int it = 0; it < 4; it++) {
            int idx = tid + it * 256;
            int row = idx >> 5;
            int c4  = (idx & 31) * 4;
            float4 b = *reinterpret_cast<const float4*>(W + (size_t)(k0 + row) * 128 + c4);
            uint4 u = make_uint4(f2tf32(b.x), f2tf32(b.y), f2tf32(b.z), f2tf32(b.w));
            *reinterpret_cast<uint4*>(&Bs[row * BS_STRIDE + c4]) = u;
        }
        __syncthreads();
#pragma unroll
        for (int ks = 0; ks < 4; ks++) {
            const int kk = k0 + ks * 8;
            uint32_t af[2][4], bf[8][2];
#pragma unroll
            for (int mi = 0; mi < 2; mi++) {
                int rm = warp_m * 32 + mi * 16;
                af[mi][0] = f2tf32(Ht[(rm + g    ) * HT_STRIDE + kk + tig    ]);
                af[mi][1] = f2tf32(Ht[(rm + g + 8) * HT_STRIDE + kk + tig    ]);
                af[mi][2] = f2tf32(Ht[(rm + g    ) * HT_STRIDE + kk + tig + 4]);
                af[mi][3] = f2tf32(Ht[(rm + g + 8) * HT_STRIDE + kk + tig + 4]);
            }
#pragma unroll
            for (int ni = 0; ni < 8; ni++) {
                int nb = warp_n * 64 + ni * 8;
                bf[ni][0] = Bs[(ks * 8 + tig    ) * BS_STRIDE + nb + g];
                bf[ni][1] = Bs[(ks * 8 + tig + 4) * BS_STRIDE + nb + g];
            }
#pragma unroll
            for (int mi = 0; mi < 2; mi++)
#pragma unroll
                for (int ni = 0; ni < 8; ni++) {
                    asm volatile(
                        "mma.sync.aligned.m16n8k8.row.col.f32.tf32.tf32.f32 "
                        "{%0,%1,%2,%3}, {%4,%5,%6,%7}, {%8,%9}, {%0,%1,%2,%3};\n"
                        : "+f"(acc[mi][ni][0]), "+f"(acc[mi][ni][1]),
                          "+f"(acc[mi][ni][2]), "+f"(acc[mi][ni][3])
                        : "r"(af[mi][0]), "r"(af[mi][1]), "r"(af[mi][2]), "r"(af[mi][3]),
                          "r"(bf[ni][0]), "r"(bf[ni][1]));
                }
        }
        __syncthreads();
    }
#pragma unroll
    for (int mi = 0; mi < 2; mi++) {
        int row0 = m0 + warp_m * 32 + mi * 16 + g;
#pragma unroll
        for (int ni = 0; ni < 8; ni++) {
            int col = warp_n * 64 + ni * 8 + tig * 2;
            if (row0 < NN)
                *reinterpret_cast<__half2*>(Zn + (size_t)row0 * DD + col) =
                    __floats2half2_rn(acc[mi][ni][0], acc[mi][ni][1]);
            if (row0 + 8 < NN)
                *reinterpret_cast<__half2*>(Zn + (size_t)(row0 + 8) * DD + col) =
                    __floats2half2_rn(acc[mi][ni][2], acc[mi][ni][3]);
        }
    }
}

// ---------------- fused agg4 -> gemm5 (128 -> 2): Z5 = (S@Zp + b4) @ W5 -------
__global__ __launch_bounds__(256, 2) void fused_agg_gemm5_kernel(
    const __half* __restrict__ Zp, const float* __restrict__ bias,
    const float* __restrict__ W5, float* __restrict__ Z5) {
    extern __shared__ float sm[];
    float* Ht = sm;                                   // [128][HT_STRIDE]
    const int tid  = threadIdx.x;
    const int wid  = tid >> 5;
    const int lane = tid & 31;
    const int m0 = blockIdx.x * 128;
    const __half* Zl = Zp + lane * 4;
    const float4 bb = *reinterpret_cast<const float4*>(bias + lane * 4);
    // W5 row-major [128][2]: lane covers k = 4*lane .. 4*lane+3
    const float4 w0 = *reinterpret_cast<const float4*>(W5 + lane * 8);
    const float4 w1 = *reinterpret_cast<const float4*>(W5 + lane * 8 + 4);

#pragma unroll 1
    for (int t = 0; t < 16; t++) {
        int r = wid * 16 + t;
        int node = m0 + r;
        float4 acc = make_float4(0.f, 0.f, 0.f, 0.f);
        if (node < NN) {
            acc = warp_agg_node(Zl, node);
            acc.x += bb.x; acc.y += bb.y; acc.z += bb.z; acc.w += bb.w;
        }
        // directly reduce to 2 outputs (no smem round-trip needed per node)
        float p0 = acc.x * w0.x + acc.y * w0.z + acc.z * w1.x + acc.w * w1.z;
        float p1 = acc.x * w0.y + acc.y * w0.w + acc.z * w1.y + acc.w * w1.w;
#pragma unroll
        for (int off = 16; off > 0; off >>= 1) {
            p0 += __shfl_down_sync(0xffffffffu, p0, off);
            p1 += __shfl_down_sync(0xffffffffu, p1, off);
        }
        if (lane == 0 && node < NN) {
            Z5[(size_t)node * 2]     = p0;
            Z5[(size_t)node * 2 + 1] = p1;
        }
    }
    // Ht unused in this variant; kept for smem-size symmetry (not required)
    (void)Ht;
}

// ---------------- final aggregation on 2-wide Z5 ------------------------------
__global__ __launch_bounds__(256) void agg5_kernel(const float* __restrict__ Z5,
                                                   const float* __restrict__ b5,
                                                   float* __restrict__ out) {
    int n = blockIdx.x * blockDim.x + threadIdx.x;
    if (n >= NN) return;
    float a0 = 0.f, a1 = 0.f;
    int i = g_rowptr[n];
    int end = g_rowptr[n + 1];
    for (; i < end; i++) {
        int2 p = g_pair[i];
        float v = __int_as_float(p.y);
        const float2 z = *reinterpret_cast<const float2*>(Z5 + (size_t)p.x * 2);
        a0 = fmaf(v, z.x, a0);
        a1 = fmaf(v, z.y, a1);
    }
    out[(size_t)n * 2]     = a0 + b5[0];
    out[(size_t)n * 2 + 1] = a1 + b5[1];
}

// ---------------- driver ----------------
extern "C" void kernel_launch(void* const* d_in, const int* in_sizes, int n_in,
                              void* d_out, int out_size) {
    const float* x  = (const float*)d_in[0];
    const int*   ei = (const int*)d_in[1];       // int32 (JAX default, x64 disabled)
    const float* ew = (const float*)d_in[2];
    const float* W1 = (const float*)d_in[3];  const float* b1 = (const float*)d_in[4];
    const float* W2 = (const float*)d_in[5];  const float* b2 = (const float*)d_in[6];
    const float* W3 = (const float*)d_in[7];  const float* b3 = (const float*)d_in[8];
    const float* W4 = (const float*)d_in[9];  const float* b4 = (const float*)d_in[10];
    const float* W5 = (const float*)d_in[11]; const float* b5 = (const float*)d_in[12];
    float* out = (float*)d_out;

    __half *ZA, *ZB; float *Z5;
    cudaGetSymbolAddress((void**)&ZA, g_ZhA);
    cudaGetSymbolAddress((void**)&ZB, g_ZhB);
    cudaGetSymbolAddress((void**)&Z5, g_Z5);

    cudaFuncSetAttribute(fused_agg_gemm_kernel<true>,
                         cudaFuncAttributeMaxDynamicSharedMemorySize, FUSED_SMEM);
    cudaFuncSetAttribute(fused_agg_gemm_kernel<false>,
                         cudaFuncAttributeMaxDynamicSharedMemorySize, FUSED_SMEM);
    cudaFuncSetAttribute(fused_agg_gemm5_kernel,
                         cudaFuncAttributeMaxDynamicSharedMemorySize, FUSED5_SMEM);

    const int TB = 256;
    // graph preprocessing
    init_kernel<<<(NN + TB - 1) / TB, TB>>>();
    deg_cnt_kernel<<<(EE + TB - 1) / TB, TB>>>(ei, ew);
    dinv_kernel<<<(NN + TB - 1) / TB, TB>>>();
    scanA_kernel<<<SCAN_NB, SCAN_CH>>>();
    scanB_kernel<<<1, 128>>>();
    scanC_kernel<<<SCAN_NB, SCAN_CH>>>();
    csr_fill_kernel<<<(EE + NN + TB - 1) / TB, TB>>>(ei, ew);

    const int blocks = (NN + 127) / 128;   // 782

    // layer 1 gemm
    gemm_tf32_kernel<<<blocks, 256>>>(x, W1, ZA, NN);
    // fused boundaries: agg1+gemm2, agg2+gemm3, agg3+gemm4
    fused_agg_gemm_kernel<true><<<blocks, 256, FUSED_SMEM>>>(ZA, b1, W2, ZB);
    fused_agg_gemm_kernel<true><<<blocks, 256, FUSED_SMEM>>>(ZB, b2, W3, ZA);
    fused_agg_gemm_kernel<true><<<blocks, 256, FUSED_SMEM>>>(ZA, b3, W4, ZB);
    // agg4 (no relu) + gemm5 (128->2)
    fused_agg_gemm5_kernel<<<blocks, 256, FUSED5_SMEM>>>(ZB, b4, W5, Z5);
    // final 2-wide aggregation
    agg5_kernel<<<(NN + TB - 1) / TB, TB>>>(Z5, b5, out);
}

// round 8
// speedup vs baseline: 1.4999x; 1.4999x over previous
#include <cuda_runtime.h>
#include <cuda_fp16.h>
#include <stdint.h>

#define NN 100000
#define EE 1600000
#define DD 128

#define SCAN_CH  1024
#define SCAN_NB  ((NN + SCAN_CH - 1) / SCAN_CH)   // 98

// ---------------- scratch (static __device__, no allocation) ----------------
__device__ float  g_deg[NN];            // deg, then dinv in place
__device__ int    g_cnt[NN];
__device__ int    g_rowptr[NN + 1];
__device__ int    g_fill[NN];
__device__ int    g_bsum[SCAN_NB];
__device__ int    g_boff[SCAN_NB];
__device__ __align__(16) int2 g_pair[EE + NN];   // packed {col, val_bits}
__device__ __half g_Zh[NN * DD];        // post-GEMM features (gather source)
__device__ __half g_HA[NN * DD];        // post-agg features, fp16
__device__ __half g_HB[NN * DD];
__device__ float  g_Z5[NN * 2];

// ---------------- graph preprocessing ----------------
__global__ void init_kernel() {
    int i = blockIdx.x * blockDim.x + threadIdx.x;
    if (i < NN) {
        g_deg[i]  = 1.0f;   // self-loop weight
        g_cnt[i]  = 1;      // self-loop edge
        g_fill[i] = 0;
    }
}

__global__ void deg_cnt_kernel(const int* __restrict__ ei,
                               const float* __restrict__ w) {
    int e = blockIdx.x * blockDim.x + threadIdx.x;
    if (e >= EE) return;
    int d = ei[EE + e];
    atomicAdd(&g_deg[d], w[e]);
    atomicAdd(&g_cnt[d], 1);
}

__global__ void dinv_kernel() {
    int i = blockIdx.x * blockDim.x + threadIdx.x;
    if (i < NN) g_deg[i] = rsqrtf(g_deg[i]);   // deg >= 1 always (self-loop)
}

// ---- 3-phase exclusive scan of g_cnt -> g_rowptr ----
__global__ __launch_bounds__(SCAN_CH) void scanA_kernel() {
    __shared__ int s[SCAN_CH];
    int t = threadIdx.x;
    int idx = blockIdx.x * SCAN_CH + t;
    s[t] = (idx < NN) ? g_cnt[idx] : 0;
    __syncthreads();
    for (int off = SCAN_CH >> 1; off > 0; off >>= 1) {
        if (t < off) s[t] += s[t + off];
        __syncthreads();
    }
    if (t == 0) g_bsum[blockIdx.x] = s[0];
}

__global__ void scanB_kernel() {
    __shared__ int s[SCAN_NB];
    int t = threadIdx.x;
    if (t < SCAN_NB) s[t] = g_bsum[t];
    __syncthreads();
    if (t == 0) {
        int run = 0;
        for (int i = 0; i < SCAN_NB; i++) { int v = s[i]; s[i] = run; run += v; }
    }
    __syncthreads();
    if (t < SCAN_NB) g_boff[t] = s[t];
}

__global__ __launch_bounds__(SCAN_CH) void scanC_kernel() {
    __shared__ int s[SCAN_CH];
    int t = threadIdx.x;
    int idx = blockIdx.x * SCAN_CH + t;
    int my = (idx < NN) ? g_cnt[idx] : 0;
    s[t] = my;
    __syncthreads();
    for (int off = 1; off < SCAN_CH; off <<= 1) {
        int u = 0;
        if (t >= off) u = s[t - off];
        __syncthreads();
        s[t] += u;
        __syncthreads();
    }
    if (idx < NN) g_rowptr[idx] = g_boff[blockIdx.x] + s[t] - my;  // exclusive
    if (idx == NN - 1) g_rowptr[NN] = EE + NN;                      // known total
}

__global__ void csr_fill_kernel(const int* __restrict__ ei,
                                const float* __restrict__ w) {
    int e = blockIdx.x * blockDim.x + threadIdx.x;
    if (e < EE) {
        int s = ei[e];
        int d = ei[EE + e];
        int pos = g_rowptr[d] + atomicAdd(&g_fill[d], 1);
        float v = g_deg[s] * w[e] * g_deg[d];       // g_deg holds dinv now
        g_pair[pos] = make_int2(s, __float_as_int(v));
    } else if (e < EE + NN) {
        int i = e - EE;
        int pos = g_rowptr[i] + atomicAdd(&g_fill[i], 1);
        float di = g_deg[i];
        g_pair[pos] = make_int2(i, __float_as_int(di * di));
    }
}

// ---------------- tf32 tensor-core GEMM: Zh[M,128] = A[M,128] @ B[128,128] ----
// A may be fp32 (layer 1 input x) or fp16 (inter-layer H) — templated loader.
#define GBM 128
#define GBK 32
#define AS_STRIDE 36
#define BS_STRIDE 136

__device__ __forceinline__ uint32_t f2tf32(float f) {
    uint32_t u;
    asm("cvt.rna.tf32.f32 %0, %1;" : "=r"(u) : "f"(f));
    return u;
}

__device__ __forceinline__ float4 load4(const float* p) {
    return *reinterpret_cast<const float4*>(p);
}
__device__ __forceinline__ float4 load4(const __half* p) {
    uint2 u = *reinterpret_cast<const uint2*>(p);
    __half2 lo = *reinterpret_cast<const __half2*>(&u.x);
    __half2 hi = *reinterpret_cast<const __half2*>(&u.y);
    float2 a = __half22float2(lo), b = __half22float2(hi);
    return make_float4(a.x, a.y, b.x, b.y);
}

template <typename TA>
__global__ __launch_bounds__(256) void gemm_tf32_kernel(const TA* __restrict__ A,
                                                        const float* __restrict__ B,
                                                        __half* __restrict__ C, int M) {
    __shared__ uint32_t As[GBM * AS_STRIDE];   // [m][k]
    __shared__ uint32_t Bs[GBK * BS_STRIDE];   // [k][n]
    const int tid  = threadIdx.x;
    const int wid  = tid >> 5;
    const int lane = tid & 31;
    const int g    = lane >> 2;
    const int tig  = lane & 3;
    const int warp_m = wid & 3;
    const int warp_n = wid >> 2;
    const int m0 = blockIdx.x * GBM;

    float acc[2][8][4];
#pragma unroll
    for (int mi = 0; mi < 2; mi++)
#pragma unroll
        for (int ni = 0; ni < 8; ni++)
#pragma unroll
            for (int q = 0; q < 4; q++) acc[mi][ni][q] = 0.0f;

    for (int k0 = 0; k0 < 128; k0 += GBK) {
#pragma unroll
        for (int it = 0; it < 4; it++) {
            int idx = tid + it * 256;
            int row = idx >> 3;
            int c4  = (idx & 7) * 4;
            float4 a = make_float4(0.f, 0.f, 0.f, 0.f);
            if (m0 + row < M)
                a = load4(A + (size_t)(m0 + row) * DD + k0 + c4);
            uint4 u = make_uint4(f2tf32(a.x), f2tf32(a.y), f2tf32(a.z), f2tf32(a.w));
            *reinterpret_cast<uint4*>(&As[row * AS_STRIDE + c4]) = u;
        }
#pragma unroll
        for (int it = 0; it < 4; it++) {
            int idx = tid + it * 256;
            int row = idx >> 5;
            int c4  = (idx & 31) * 4;
            float4 b = *reinterpret_cast<const float4*>(B + (size_t)(k0 + row) * 128 + c4);
            uint4 u = make_uint4(f2tf32(b.x), f2tf32(b.y), f2tf32(b.z), f2tf32(b.w));
            *reinterpret_cast<uint4*>(&Bs[row * BS_STRIDE + c4]) = u;
        }
        __syncthreads();
#pragma unroll
        for (int ks = 0; ks < 4; ks++) {
            const int kk = ks * 8;
            uint32_t af[2][4], bf[8][2];
#pragma unroll
            for (int mi = 0; mi < 2; mi++) {
                int rm = warp_m * 32 + mi * 16;
                af[mi][0] = As[(rm + g    ) * AS_STRIDE + kk + tig    ];
                af[mi][1] = As[(rm + g + 8) * AS_STRIDE + kk + tig    ];
                af[mi][2] = As[(rm + g    ) * AS_STRIDE + kk + tig + 4];
                af[mi][3] = As[(rm + g + 8) * AS_STRIDE + kk + tig + 4];
            }
#pragma unroll
            for (int ni = 0; ni < 8; ni++) {
                int nb = warp_n * 64 + ni * 8;
                bf[ni][0] = Bs[(kk + tig    ) * BS_STRIDE + nb + g];
                bf[ni][1] = Bs[(kk + tig + 4) * BS_STRIDE + nb + g];
            }
#pragma unroll
            for (int mi = 0; mi < 2; mi++)
#pragma unroll
                for (int ni = 0; ni < 8; ni++) {
                    asm volatile(
                        "mma.sync.aligned.m16n8k8.row.col.f32.tf32.tf32.f32 "
                        "{%0,%1,%2,%3}, {%4,%5,%6,%7}, {%8,%9}, {%0,%1,%2,%3};\n"
                        : "+f"(acc[mi][ni][0]), "+f"(acc[mi][ni][1]),
                          "+f"(acc[mi][ni][2]), "+f"(acc[mi][ni][3])
                        : "r"(af[mi][0]), "r"(af[mi][1]), "r"(af[mi][2]), "r"(af[mi][3]),
                          "r"(bf[ni][0]), "r"(bf[ni][1]));
                }
        }
        __syncthreads();
    }
#pragma unroll
    for (int mi = 0; mi < 2; mi++) {
        int row0 = m0 + warp_m * 32 + mi * 16 + g;
#pragma unroll
        for (int ni = 0; ni < 8; ni++) {
            int col = warp_n * 64 + ni * 8 + tig * 2;
            if (row0 < M)
                *reinterpret_cast<__half2*>(C + (size_t)row0 * DD + col) =
                    __floats2half2_rn(acc[mi][ni][0], acc[mi][ni][1]);
            if (row0 + 8 < M)
                *reinterpret_cast<__half2*>(C + (size_t)(row0 + 8) * DD + col) =
                    __floats2half2_rn(acc[mi][ni][2], acc[mi][ni][3]);
        }
    }
}

// ---------------- sparse aggregation: H[n] = relu(sum val * Zh[col] + b) ------
// warp-per-node; lane owns 4 channels; fp32 accumulate; fp16 output.
template <bool RELU>
__global__ __launch_bounds__(256) void agg_kernel(const __half* __restrict__ Z,
                                                  const float* __restrict__ b,
                                                  __half* __restrict__ out) {
    int warp = (blockIdx.x * blockDim.x + threadIdx.x) >> 5;
    if (warp >= NN) return;
    int lane = threadIdx.x & 31;
    const __half* Zl = Z + lane * 4;
    int i   = g_rowptr[warp];
    int end = g_rowptr[warp + 1];
    float4 acc = make_float4(0.f, 0.f, 0.f, 0.f);

    if ((i & 1) && i < end) {
        int2 p = g_pair[i];
        float v = __int_as_float(p.y);
        const __half2* q = reinterpret_cast<const __half2*>(Zl + (size_t)p.x * DD);
        __half2 a = q[0], d = q[1];
        float2 f;
        f = __half22float2(a); acc.x = fmaf(v, f.x, acc.x); acc.y = fmaf(v, f.y, acc.y);
        f = __half22float2(d); acc.z = fmaf(v, f.x, acc.z); acc.w = fmaf(v, f.y, acc.w);
        i++;
    }
    for (; i + 4 <= end; i += 4) {
        int4 pA = *reinterpret_cast<const int4*>(&g_pair[i]);
        int4 pB = *reinterpret_cast<const int4*>(&g_pair[i + 2]);
        float v0 = __int_as_float(pA.y), v1 = __int_as_float(pA.w);
        float v2 = __int_as_float(pB.y), v3 = __int_as_float(pB.w);
        const __half2* p0 = reinterpret_cast<const __half2*>(Zl + (size_t)pA.x * DD);
        const __half2* p1 = reinterpret_cast<const __half2*>(Zl + (size_t)pA.z * DD);
        const __half2* p2 = reinterpret_cast<const __half2*>(Zl + (size_t)pB.x * DD);
        const __half2* p3 = reinterpret_cast<const __half2*>(Zl + (size_t)pB.z * DD);
        __half2 a0 = p0[0], b0 = p0[1];
        __half2 a1 = p1[0], b1 = p1[1];
        __half2 a2 = p2[0], b2 = p2[1];
        __half2 a3 = p3[0], b3 = p3[1];
        float2 f;
        f = __half22float2(a0); acc.x = fmaf(v0, f.x, acc.x); acc.y = fmaf(v0, f.y, acc.y);
        f = __half22float2(b0); acc.z = fmaf(v0, f.x, acc.z); acc.w = fmaf(v0, f.y, acc.w);
        f = __half22float2(a1); acc.x = fmaf(v1, f.x, acc.x); acc.y = fmaf(v1, f.y, acc.y);
        f = __half22float2(b1); acc.z = fmaf(v1, f.x, acc.z); acc.w = fmaf(v1, f.y, acc.w);
        f = __half22float2(a2); acc.x = fmaf(v2, f.x, acc.x); acc.y = fmaf(v2, f.y, acc.y);
        f = __half22float2(b2); acc.z = fmaf(v2, f.x, acc.z); acc.w = fmaf(v2, f.y, acc.w);
        f = __half22float2(a3); acc.x = fmaf(v3, f.x, acc.x); acc.y = fmaf(v3, f.y, acc.y);
        f = __half22float2(b3); acc.z = fmaf(v3, f.x, acc.z); acc.w = fmaf(v3, f.y, acc.w);
    }
    for (; i < end; i++) {
        int2 p = g_pair[i];
        float v = __int_as_float(p.y);
        const __half2* q = reinterpret_cast<const __half2*>(Zl + (size_t)p.x * DD);
        __half2 a = q[0], d = q[1];
        float2 f;
        f = __half22float2(a); acc.x = fmaf(v, f.x, acc.x); acc.y = fmaf(v, f.y, acc.y);
        f = __half22float2(d); acc.z = fmaf(v, f.x, acc.z); acc.w = fmaf(v, f.y, acc.w);
    }
    const float4 bb = *reinterpret_cast<const float4*>(b + lane * 4);
    acc.x += bb.x; acc.y += bb.y; acc.z += bb.z; acc.w += bb.w;
    if (RELU) {
        acc.x = fmaxf(acc.x, 0.f); acc.y = fmaxf(acc.y, 0.f);
        acc.z = fmaxf(acc.z, 0.f); acc.w = fmaxf(acc.w, 0.f);
    }
    __half2 lo = __floats2half2_rn(acc.x, acc.y);
    __half2 hi = __floats2half2_rn(acc.z, acc.w);
    uint2 pk;
    pk.x = *reinterpret_cast<uint32_t*>(&lo);
    pk.y = *reinterpret_cast<uint32_t*>(&hi);
    *reinterpret_cast<uint2*>(out + (size_t)warp * DD + lane * 4) = pk;
}

// ---------------- layer 5: GEMM [N,128]@[128,2] then 2-wide aggregation -------
__global__ __launch_bounds__(256) void gemm5_kernel(const __half* __restrict__ H,
                                                    const float* __restrict__ W5,
                                                    float* __restrict__ Z5) {
    int warp = (blockIdx.x * blockDim.x + threadIdx.x) >> 5;
    if (warp >= NN) return;
    int lane = threadIdx.x & 31;
    const float4 h  = load4(H + (size_t)warp * DD + lane * 4);
    const float4 w0 = *reinterpret_cast<const float4*>(W5 + lane * 8);
    const float4 w1 = *reinterpret_cast<const float4*>(W5 + lane * 8 + 4);
    float p0 = h.x * w0.x + h.y * w0.z + h.z * w1.x + h.w * w1.z;
    float p1 = h.x * w0.y + h.y * w0.w + h.z * w1.y + h.w * w1.w;
#pragma unroll
    for (int off = 16; off > 0; off >>= 1) {
        p0 += __shfl_down_sync(0xffffffffu, p0, off);
        p1 += __shfl_down_sync(0xffffffffu, p1, off);
    }
    if (lane == 0) {
        Z5[(size_t)warp * 2]     = p0;
        Z5[(size_t)warp * 2 + 1] = p1;
    }
}

__global__ __launch_bounds__(256) void agg5_kernel(const float* __restrict__ Z5,
                                                   const float* __restrict__ b5,
                                                   float* __restrict__ out) {
    int n = blockIdx.x * blockDim.x + threadIdx.x;
    if (n >= NN) return;
    float a0 = 0.f, a1 = 0.f;
    int i = g_rowptr[n];
    int end = g_rowptr[n + 1];
    for (; i < end; i++) {
        int2 p = g_pair[i];
        float v = __int_as_float(p.y);
        const float2 z = *reinterpret_cast<const float2*>(Z5 + (size_t)p.x * 2);
        a0 = fmaf(v, z.x, a0);
        a1 = fmaf(v, z.y, a1);
    }
    out[(size_t)n * 2]     = a0 + b5[0];
    out[(size_t)n * 2 + 1] = a1 + b5[1];
}

// ---------------- driver ----------------
extern "C" void kernel_launch(void* const* d_in, const int* in_sizes, int n_in,
                              void* d_out, int out_size) {
    const float* x  = (const float*)d_in[0];
    const int*   ei = (const int*)d_in[1];       // int32 (JAX default, x64 disabled)
    const float* ew = (const float*)d_in[2];
    const float* W1 = (const float*)d_in[3];  const float* b1 = (const float*)d_in[4];
    const float* W2 = (const float*)d_in[5];  const float* b2 = (const float*)d_in[6];
    const float* W3 = (const float*)d_in[7];  const float* b3 = (const float*)d_in[8];
    const float* W4 = (const float*)d_in[9];  const float* b4 = (const float*)d_in[10];
    const float* W5 = (const float*)d_in[11]; const float* b5 = (const float*)d_in[12];
    float* out = (float*)d_out;

    __half *Zh, *HA, *HB; float *Z5;
    cudaGetSymbolAddress((void**)&Zh, g_Zh);
    cudaGetSymbolAddress((void**)&HA, g_HA);
    cudaGetSymbolAddress((void**)&HB, g_HB);
    cudaGetSymbolAddress((void**)&Z5, g_Z5);

    const int TB = 256;
    // graph preprocessing
    init_kernel<<<(NN + TB - 1) / TB, TB>>>();
    deg_cnt_kernel<<<(EE + TB - 1) / TB, TB>>>(ei, ew);
    dinv_kernel<<<(NN + TB - 1) / TB, TB>>>();
    scanA_kernel<<<SCAN_NB, SCAN_CH>>>();
    scanB_kernel<<<1, 128>>>();
    scanC_kernel<<<SCAN_NB, SCAN_CH>>>();
    csr_fill_kernel<<<(EE + NN + TB - 1) / TB, TB>>>(ei, ew);

    const int gemm_blocks = (NN + GBM - 1) / GBM;
    const int agg_blocks  = (int)(((size_t)NN * 32 + TB - 1) / TB);

    // layer 1 (A = x fp32)
    gemm_tf32_kernel<float><<<gemm_blocks, 256>>>(x, W1, Zh, NN);
    agg_kernel<true><<<agg_blocks, TB>>>(Zh, b1, HA);
    // layer 2
    gemm_tf32_kernel<__half><<<gemm_blocks, 256>>>(HA, W2, Zh, NN);
    agg_kernel<true><<<agg_blocks, TB>>>(Zh, b2, HB);
    // layer 3
    gemm_tf32_kernel<__half><<<gemm_blocks, 256>>>(HB, W3, Zh, NN);
    agg_kernel<true><<<agg_blocks, TB>>>(Zh, b3, HA);
    // layer 4 (no relu)
    gemm_tf32_kernel<__half><<<gemm_blocks, 256>>>(HA, W4, Zh, NN);
    agg_kernel<false><<<agg_blocks, TB>>>(Zh, b4, HB);
    // layer 5 (128 -> 2)
    gemm5_kernel<<<agg_blocks, TB>>>(HB, W5, Z5);
    agg5_kernel<<<(NN + TB - 1) / TB, TB>>>(Z5, b5, out);
}

// round 10
// speedup vs baseline: 1.6912x; 1.1275x over previous
#include <cuda_runtime.h>
#include <cuda_fp16.h>
#include <stdint.h>

#define NN 100000
#define EE 1600000
#define DD 128

#define SCAN_CH  1024
#define SCAN_NB  ((NN + SCAN_CH - 1) / SCAN_CH)   // 98

// ---------------- scratch (static __device__, no allocation) ----------------
__device__ float  g_deg[NN];            // deg, then dinv in place
__device__ int    g_cnt[NN];
__device__ int    g_rowptr[NN + 1];
__device__ int    g_fill[NN];
__device__ int    g_bsum[SCAN_NB];
__device__ int    g_boff[SCAN_NB];
__device__ __align__(16) int2 g_pair[EE + NN];   // packed {col, val_bits}
__device__ __half g_Zh[NN * DD];        // post-GEMM features (gather source)
__device__ __half g_HA[NN * DD];        // post-agg features, fp16
__device__ __half g_HB[NN * DD];
__device__ float  g_Z5[NN * 2];

// ---------------- graph preprocessing ----------------
__global__ void init_kernel() {
    int i = blockIdx.x * blockDim.x + threadIdx.x;
    if (i < NN) {
        g_deg[i]  = 1.0f;   // self-loop weight
        g_cnt[i]  = 1;      // self-loop edge
        g_fill[i] = 0;
    }
}

__global__ void deg_cnt_kernel(const int* __restrict__ ei,
                               const float* __restrict__ w) {
    int e = blockIdx.x * blockDim.x + threadIdx.x;
    if (e >= EE) return;
    int d = ei[EE + e];
    atomicAdd(&g_deg[d], w[e]);
    atomicAdd(&g_cnt[d], 1);
}

__global__ void dinv_kernel() {
    int i = blockIdx.x * blockDim.x + threadIdx.x;
    if (i < NN) g_deg[i] = rsqrtf(g_deg[i]);   // deg >= 1 always (self-loop)
}

// ---- 3-phase exclusive scan of g_cnt -> g_rowptr ----
__global__ __launch_bounds__(SCAN_CH) void scanA_kernel() {
    __shared__ int s[SCAN_CH];
    int t = threadIdx.x;
    int idx = blockIdx.x * SCAN_CH + t;
    s[t] = (idx < NN) ? g_cnt[idx] : 0;
    __syncthreads();
    for (int off = SCAN_CH >> 1; off > 0; off >>= 1) {
        if (t < off) s[t] += s[t + off];
        __syncthreads();
    }
    if (t == 0) g_bsum[blockIdx.x] = s[0];
}

__global__ void scanB_kernel() {
    __shared__ int s[SCAN_NB];
    int t = threadIdx.x;
    if (t < SCAN_NB) s[t] = g_bsum[t];
    __syncthreads();
    if (t == 0) {
        int run = 0;
        for (int i = 0; i < SCAN_NB; i++) { int v = s[i]; s[i] = run; run += v; }
    }
    __syncthreads();
    if (t < SCAN_NB) g_boff[t] = s[t];
}

__global__ __launch_bounds__(SCAN_CH) void scanC_kernel() {
    __shared__ int s[SCAN_CH];
    int t = threadIdx.x;
    int idx = blockIdx.x * SCAN_CH + t;
    int my = (idx < NN) ? g_cnt[idx] : 0;
    s[t] = my;
    __syncthreads();
    for (int off = 1; off < SCAN_CH; off <<= 1) {
        int u = 0;
        if (t >= off) u = s[t - off];
        __syncthreads();
        s[t] += u;
        __syncthreads();
    }
    if (idx < NN) g_rowptr[idx] = g_boff[blockIdx.x] + s[t] - my;  // exclusive
    if (idx == NN - 1) g_rowptr[NN] = EE + NN;                      // known total
}

__global__ void csr_fill_kernel(const int* __restrict__ ei,
                                const float* __restrict__ w) {
    int e = blockIdx.x * blockDim.x + threadIdx.x;
    if (e < EE) {
        int s = ei[e];
        int d = ei[EE + e];
        int pos = g_rowptr[d] + atomicAdd(&g_fill[d], 1);
        float v = g_deg[s] * w[e] * g_deg[d];       // g_deg holds dinv now
        g_pair[pos] = make_int2(s, __float_as_int(v));
    } else if (e < EE + NN) {
        int i = e - EE;
        int pos = g_rowptr[i] + atomicAdd(&g_fill[i], 1);
        float di = g_deg[i];
        g_pair[pos] = make_int2(i, __float_as_int(di * di));
    }
}

// ---------------- fp16 tensor-core GEMM: Zh[M,128] = A[M,128] @ W[128,128] ----
// CTA tile 128x128, full K=128 resident in DYNAMIC smem (68KB, opt-in); 8 warps
// (4m x 2n), warp tile 32x64 via m16n8k16; fragments via ldmatrix (stride 136).
#define GBM 128
#define LDH 136   // halves per smem row (272 B; 68 words ≡ 4 mod 32 → ldmatrix conflict-free)
#define GEMM_SMEM (2 * GBM * LDH * (int)sizeof(__half))   // 69632

__device__ __forceinline__ uint32_t smem_u32(const void* p) {
    return (uint32_t)__cvta_generic_to_shared(p);
}

template <typename TA>
__global__ __launch_bounds__(256) void gemm_h16_kernel(const TA* __restrict__ A,
                                                       const float* __restrict__ W,
                                                       __half* __restrict__ C, int M) {
    extern __shared__ __half smh[];
    __half* As = smh;                 // [128][LDH]
    __half* Bs = smh + GBM * LDH;     // [128][LDH]
    const int tid  = threadIdx.x;
    const int wid  = tid >> 5;
    const int lane = tid & 31;
    const int warp_m = wid & 3;     // 32 rows each
    const int warp_n = wid >> 2;    // 64 cols each
    const int m0 = blockIdx.x * GBM;

    // ---- load A tile (convert to fp16 if fp32) ----
#pragma unroll
    for (int it = 0; it < 8; it++) {
        int idx = tid + it * 256;       // 0..2047
        int row = idx >> 4;             // 0..127
        int hg  = (idx & 15) * 8;       // half-group of 8
        uint4 pk = make_uint4(0u, 0u, 0u, 0u);
        if (m0 + row < M) {
            const TA* src = A + (size_t)(m0 + row) * DD + hg;
            if (sizeof(TA) == 2) {
                pk = *reinterpret_cast<const uint4*>(src);
            } else {
                const float4 f0 = *reinterpret_cast<const float4*>((const float*)src);
                const float4 f1 = *reinterpret_cast<const float4*>((const float*)src + 4);
                __half2 h0 = __floats2half2_rn(f0.x, f0.y);
                __half2 h1 = __floats2half2_rn(f0.z, f0.w);
                __half2 h2 = __floats2half2_rn(f1.x, f1.y);
                __half2 h3 = __floats2half2_rn(f1.z, f1.w);
                pk.x = *reinterpret_cast<uint32_t*>(&h0);
                pk.y = *reinterpret_cast<uint32_t*>(&h1);
                pk.z = *reinterpret_cast<uint32_t*>(&h2);
                pk.w = *reinterpret_cast<uint32_t*>(&h3);
            }
        }
        *reinterpret_cast<uint4*>(&As[row * LDH + hg]) = pk;
    }
    // ---- load W tile (fp32 -> fp16) ----
#pragma unroll
    for (int it = 0; it < 16; it++) {
        int idx = tid + it * 256;       // 0..4095
        int row = idx >> 5;             // 0..127
        int cg  = (idx & 31) * 4;       // float4 at col cg
        float4 w = *reinterpret_cast<const float4*>(W + (size_t)row * 128 + cg);
        __half2 h0 = __floats2half2_rn(w.x, w.y);
        __half2 h1 = __floats2half2_rn(w.z, w.w);
        uint2 pk;
        pk.x = *reinterpret_cast<uint32_t*>(&h0);
        pk.y = *reinterpret_cast<uint32_t*>(&h1);
        *reinterpret_cast<uint2*>(&Bs[row * LDH + cg]) = pk;
    }
    __syncthreads();

    float acc[2][8][4];
#pragma unroll
    for (int mi = 0; mi < 2; mi++)
#pragma unroll
        for (int ni = 0; ni < 8; ni++)
#pragma unroll
            for (int q = 0; q < 4; q++) acc[mi][ni][q] = 0.0f;

#pragma unroll
    for (int ks = 0; ks < 8; ks++) {
        const int kk = ks * 16;
        uint32_t a[2][4], b[8][2];
        // A fragments: rows warp_m*32 + mi*16 + lane%16, col kk + (lane/16)*8
#pragma unroll
        for (int mi = 0; mi < 2; mi++) {
            uint32_t addr = smem_u32(&As[(warp_m * 32 + mi * 16 + (lane & 15)) * LDH
                                         + kk + (lane >> 4) * 8]);
            asm volatile("ldmatrix.sync.aligned.m8n8.x4.shared.b16 {%0,%1,%2,%3}, [%4];"
                         : "=r"(a[mi][0]), "=r"(a[mi][1]), "=r"(a[mi][2]), "=r"(a[mi][3])
                         : "r"(addr));
        }
        // B fragments: x4.trans covers 16 n-cols (2 mma n-tiles) per issue
#pragma unroll
        for (int nb = 0; nb < 4; nb++) {
            uint32_t addr = smem_u32(&Bs[(kk + (lane & 15)) * LDH
                                         + warp_n * 64 + nb * 16 + (lane >> 4) * 8]);
            asm volatile("ldmatrix.sync.aligned.m8n8.x4.trans.shared.b16 {%0,%1,%2,%3}, [%4];"
                         : "=r"(b[nb * 2][0]), "=r"(b[nb * 2][1]),
                           "=r"(b[nb * 2 + 1][0]), "=r"(b[nb * 2 + 1][1])
                         : "r"(addr));
        }
#pragma unroll
        for (int mi = 0; mi < 2; mi++)
#pragma unroll
            for (int ni = 0; ni < 8; ni++) {
                asm volatile(
                    "mma.sync.aligned.m16n8k16.row.col.f32.f16.f16.f32 "
                    "{%0,%1,%2,%3}, {%4,%5,%6,%7}, {%8,%9}, {%0,%1,%2,%3};\n"
                    : "+f"(acc[mi][ni][0]), "+f"(acc[mi][ni][1]),
                      "+f"(acc[mi][ni][2]), "+f"(acc[mi][ni][3])
                    : "r"(a[mi][0]), "r"(a[mi][1]), "r"(a[mi][2]), "r"(a[mi][3]),
                      "r"(b[ni][0]), "r"(b[ni][1]));
            }
    }
    // epilogue: c0,c1 -> (row g, cols tig*2, tig*2+1); c2,c3 -> row g+8
    const int g   = lane >> 2;
    const int tig = lane & 3;
#pragma unroll
    for (int mi = 0; mi < 2; mi++) {
        int row0 = m0 + warp_m * 32 + mi * 16 + g;
#pragma unroll
        for (int ni = 0; ni < 8; ni++) {
            int col = warp_n * 64 + ni * 8 + tig * 2;
            if (row0 < M)
                *reinterpret_cast<__half2*>(C + (size_t)row0 * DD + col) =
                    __floats2half2_rn(acc[mi][ni][0], acc[mi][ni][1]);
            if (row0 + 8 < M)
                *reinterpret_cast<__half2*>(C + (size_t)(row0 + 8) * DD + col) =
                    __floats2half2_rn(acc[mi][ni][2], acc[mi][ni][3]);
        }
    }
}

// ---------------- sparse aggregation: H[n] = relu(sum val * Zh[col] + b) ------
template <bool RELU>
__global__ __launch_bounds__(256) void agg_kernel(const __half* __restrict__ Z,
                                                  const float* __restrict__ b,
                                                  __half* __restrict__ out) {
    int warp = (blockIdx.x * blockDim.x + threadIdx.x) >> 5;
    if (warp >= NN) return;
    int lane = threadIdx.x & 31;
    const __half* Zl = Z + lane * 4;
    int i   = g_rowptr[warp];
    int end = g_rowptr[warp + 1];
    float4 acc = make_float4(0.f, 0.f, 0.f, 0.f);

    if ((i & 1) && i < end) {
        int2 p = g_pair[i];
        float v = __int_as_float(p.y);
        const __half2* q = reinterpret_cast<const __half2*>(Zl + (size_t)p.x * DD);
        __half2 a = q[0], d = q[1];
        float2 f;
        f = __half22float2(a); acc.x = fmaf(v, f.x, acc.x); acc.y = fmaf(v, f.y, acc.y);
        f = __half22float2(d); acc.z = fmaf(v, f.x, acc.z); acc.w = fmaf(v, f.y, acc.w);
        i++;
    }
    for (; i + 4 <= end; i += 4) {
        int4 pA = *reinterpret_cast<const int4*>(&g_pair[i]);
        int4 pB = *reinterpret_cast<const int4*>(&g_pair[i + 2]);
        float v0 = __int_as_float(pA.y), v1 = __int_as_float(pA.w);
        float v2 = __int_as_float(pB.y), v3 = __int_as_float(pB.w);
        const __half2* p0 = reinterpret_cast<const __half2*>(Zl + (size_t)pA.x * DD);
        const __half2* p1 = reinterpret_cast<const __half2*>(Zl + (size_t)pA.z * DD);
        const __half2* p2 = reinterpret_cast<const __half2*>(Zl + (size_t)pB.x * DD);
        const __half2* p3 = reinterpret_cast<const __half2*>(Zl + (size_t)pB.z * DD);
        __half2 a0 = p0[0], b0 = p0[1];
        __half2 a1 = p1[0], b1 = p1[1];
        __half2 a2 = p2[0], b2 = p2[1];
        __half2 a3 = p3[0], b3 = p3[1];
        float2 f;
        f = __half22float2(a0); acc.x = fmaf(v0, f.x, acc.x); acc.y = fmaf(v0, f.y, acc.y);
        f = __half22float2(b0); acc.z = fmaf(v0, f.x, acc.z); acc.w = fmaf(v0, f.y, acc.w);
        f = __half22float2(a1); acc.x = fmaf(v1, f.x, acc.x); acc.y = fmaf(v1, f.y, acc.y);
        f = __half22float2(b1); acc.z = fmaf(v1, f.x, acc.z); acc.w = fmaf(v1, f.y, acc.w);
        f = __half22float2(a2); acc.x = fmaf(v2, f.x, acc.x); acc.y = fmaf(v2, f.y, acc.y);
        f = __half22float2(b2); acc.z = fmaf(v2, f.x, acc.z); acc.w = fmaf(v2, f.y, acc.w);
        f = __half22float2(a3); acc.x = fmaf(v3, f.x, acc.x); acc.y = fmaf(v3, f.y, acc.y);
        f = __half22float2(b3); acc.z = fmaf(v3, f.x, acc.z); acc.w = fmaf(v3, f.y, acc.w);
    }
    for (; i < end; i++) {
        int2 p = g_pair[i];
        float v = __int_as_float(p.y);
        const __half2* q = reinterpret_cast<const __half2*>(Zl + (size_t)p.x * DD);
        __half2 a = q[0], d = q[1];
        float2 f;
        f = __half22float2(a); acc.x = fmaf(v, f.x, acc.x); acc.y = fmaf(v, f.y, acc.y);
        f = __half22float2(d); acc.z = fmaf(v, f.x, acc.z); acc.w = fmaf(v, f.y, acc.w);
    }
    const float4 bb = *reinterpret_cast<const float4*>(b + lane * 4);
    acc.x += bb.x; acc.y += bb.y; acc.z += bb.z; acc.w += bb.w;
    if (RELU) {
        acc.x = fmaxf(acc.x, 0.f); acc.y = fmaxf(acc.y, 0.f);
        acc.z = fmaxf(acc.z, 0.f); acc.w = fmaxf(acc.w, 0.f);
    }
    __half2 lo = __floats2half2_rn(acc.x, acc.y);
    __half2 hi = __floats2half2_rn(acc.z, acc.w);
    uint2 pk;
    pk.x = *reinterpret_cast<uint32_t*>(&lo);
    pk.y = *reinterpret_cast<uint32_t*>(&hi);
    *reinterpret_cast<uint2*>(out + (size_t)warp * DD + lane * 4) = pk;
}

// ---------------- layer 5: GEMM [N,128]@[128,2] then 2-wide aggregation -------
__device__ __forceinline__ float4 load4h(const __half* p) {
    uint2 u = *reinterpret_cast<const uint2*>(p);
    __half2 lo = *reinterpret_cast<const __half2*>(&u.x);
    __half2 hi = *reinterpret_cast<const __half2*>(&u.y);
    float2 a = __half22float2(lo), b = __half22float2(hi);
    return make_float4(a.x, a.y, b.x, b.y);
}

__global__ __launch_bounds__(256) void gemm5_kernel(const __half* __restrict__ H,
                                                    const float* __restrict__ W5,
                                                    float* __restrict__ Z5) {
    int warp = (blockIdx.x * blockDim.x + threadIdx.x) >> 5;
    if (warp >= NN) return;
    int lane = threadIdx.x & 31;
    const float4 h  = load4h(H + (size_t)warp * DD + lane * 4);
    const float4 w0 = *reinterpret_cast<const float4*>(W5 + lane * 8);
    const float4 w1 = *reinterpret_cast<const float4*>(W5 + lane * 8 + 4);
    float p0 = h.x * w0.x + h.y * w0.z + h.z * w1.x + h.w * w1.z;
    float p1 = h.x * w0.y + h.y * w0.w + h.z * w1.y + h.w * w1.w;
#pragma unroll
    for (int off = 16; off > 0; off >>= 1) {
        p0 += __shfl_down_sync(0xffffffffu, p0, off);
        p1 += __shfl_down_sync(0xffffffffu, p1, off);
    }
    if (lane == 0) {
        Z5[(size_t)warp * 2]     = p0;
        Z5[(size_t)warp * 2 + 1] = p1;
    }
}

__global__ __launch_bounds__(256) void agg5_kernel(const float* __restrict__ Z5,
                                                   const float* __restrict__ b5,
                                                   float* __restrict__ out) {
    int n = blockIdx.x * blockDim.x + threadIdx.x;
    if (n >= NN) return;
    float a0 = 0.f, a1 = 0.f;
    int i = g_rowptr[n];
    int end = g_rowptr[n + 1];
    for (; i < end; i++) {
        int2 p = g_pair[i];
        float v = __int_as_float(p.y);
        const float2 z = *reinterpret_cast<const float2*>(Z5 + (size_t)p.x * 2);
        a0 = fmaf(v, z.x, a0);
        a1 = fmaf(v, z.y, a1);
    }
    out[(size_t)n * 2]     = a0 + b5[0];
    out[(size_t)n * 2 + 1] = a1 + b5[1];
}

// ---------------- driver ----------------
extern "C" void kernel_launch(void* const* d_in, const int* in_sizes, int n_in,
                              void* d_out, int out_size) {
    const float* x  = (const float*)d_in[0];
    const int*   ei = (const int*)d_in[1];       // int32 (JAX default, x64 disabled)
    const float* ew = (const float*)d_in[2];
    const float* W1 = (const float*)d_in[3];  const float* b1 = (const float*)d_in[4];
    const float* W2 = (const float*)d_in[5];  const float* b2 = (const float*)d_in[6];
    const float* W3 = (const float*)d_in[7];  const float* b3 = (const float*)d_in[8];
    const float* W4 = (const float*)d_in[9];  const float* b4 = (const float*)d_in[10];
    const float* W5 = (const float*)d_in[11]; const float* b5 = (const float*)d_in[12];
    float* out = (float*)d_out;

    __half *Zh, *HA, *HB; float *Z5;
    cudaGetSymbolAddress((void**)&Zh, g_Zh);
    cudaGetSymbolAddress((void**)&HA, g_HA);
    cudaGetSymbolAddress((void**)&HB, g_HB);
    cudaGetSymbolAddress((void**)&Z5, g_Z5);

    cudaFuncSetAttribute(gemm_h16_kernel<float>,
                         cudaFuncAttributeMaxDynamicSharedMemorySize, GEMM_SMEM);
    cudaFuncSetAttribute(gemm_h16_kernel<__half>,
                         cudaFuncAttributeMaxDynamicSharedMemorySize, GEMM_SMEM);

    const int TB = 256;
    // graph preprocessing
    init_kernel<<<(NN + TB - 1) / TB, TB>>>();
    deg_cnt_kernel<<<(EE + TB - 1) / TB, TB>>>(ei, ew);
    dinv_kernel<<<(NN + TB - 1) / TB, TB>>>();
    scanA_kernel<<<SCAN_NB, SCAN_CH>>>();
    scanB_kernel<<<1, 128>>>();
    scanC_kernel<<<SCAN_NB, SCAN_CH>>>();
    csr_fill_kernel<<<(EE + NN + TB - 1) / TB, TB>>>(ei, ew);

    const int gemm_blocks = (NN + GBM - 1) / GBM;
    const int agg_blocks  = (int)(((size_t)NN * 32 + TB - 1) / TB);

    // layer 1 (A = x fp32, converted in-kernel)
    gemm_h16_kernel<float><<<gemm_blocks, 256, GEMM_SMEM>>>(x, W1, Zh, NN);
    agg_kernel<true><<<agg_blocks, TB>>>(Zh, b1, HA);
    // layer 2
    gemm_h16_kernel<__half><<<gemm_blocks, 256, GEMM_SMEM>>>(HA, W2, Zh, NN);
    agg_kernel<true><<<agg_blocks, TB>>>(Zh, b2, HB);
    // layer 3
    gemm_h16_kernel<__half><<<gemm_blocks, 256, GEMM_SMEM>>>(HB, W3, Zh, NN);
    agg_kernel<true><<<agg_blocks, TB>>>(Zh, b3, HA);
    // layer 4 (no relu)
    gemm_h16_kernel<__half><<<gemm_blocks, 256, GEMM_SMEM>>>(HA, W4, Zh, NN);
    agg_kernel<false><<<agg_blocks, TB>>>(Zh, b4, HB);
    // layer 5 (128 -> 2)
    gemm5_kernel<<<agg_blocks, TB>>>(HB, W5, Z5);
    agg5_kernel<<<(NN + TB - 1) / TB, TB>>>(Z5, b5, out);
}

// round 11
// speedup vs baseline: 1.7344x; 1.0255x over previous
#include <cuda_runtime.h>
#include <cuda_fp16.h>
#include <stdint.h>

#define NN 100000
#define EE 1600000
#define DD 128

#define SCAN_CH  1024
#define SCAN_NB  ((NN + SCAN_CH - 1) / SCAN_CH)   // 98

// ---------------- scratch (static __device__, no allocation) ----------------
__device__ float  g_deg[NN];            // deg, then dinv in place
__device__ int    g_cnt[NN];
__device__ int    g_rowptr[NN + 1];
__device__ int    g_fill[NN];
__device__ int    g_bsum[SCAN_NB];
__device__ __align__(16) int2 g_pair[EE + NN];   // packed {col, val_bits}
__device__ __half g_Zh[NN * DD];        // post-GEMM features (gather source)
__device__ __half g_HA[NN * DD];        // post-agg features, fp16
__device__ __half g_HB[NN * DD];
__device__ float  g_Z5[NN * 2];

// ---------------- graph preprocessing ----------------
__global__ void init_kernel() {
    int i = blockIdx.x * blockDim.x + threadIdx.x;
    if (i < NN) {
        g_deg[i]  = 1.0f;   // self-loop weight
        g_cnt[i]  = 1;      // self-loop edge
        g_fill[i] = 0;
    }
}

__global__ void deg_cnt_kernel(const int* __restrict__ ei,
                               const float* __restrict__ w) {
    int e = blockIdx.x * blockDim.x + threadIdx.x;
    if (e >= EE) return;
    int d = ei[EE + e];
    atomicAdd(&g_deg[d], w[e]);
    atomicAdd(&g_cnt[d], 1);
}

// ---- scan phase A + dinv fused: per-block sums of cnt, and deg -> rsqrt ----
__global__ __launch_bounds__(SCAN_CH) void scanA_dinv_kernel() {
    __shared__ int s[SCAN_CH];
    int t = threadIdx.x;
    int idx = blockIdx.x * SCAN_CH + t;
    int c = 0;
    if (idx < NN) {
        c = g_cnt[idx];
        g_deg[idx] = rsqrtf(g_deg[idx]);   // deg >= 1 always (self-loop)
    }
    s[t] = c;
    __syncthreads();
    for (int off = SCAN_CH >> 1; off > 0; off >>= 1) {
        if (t < off) s[t] += s[t + off];
        __syncthreads();
    }
    if (t == 0) g_bsum[blockIdx.x] = s[0];
}

// ---- scan phase C: per-block Hillis-Steele + locally computed block offset ----
__global__ __launch_bounds__(SCAN_CH) void scanC_kernel() {
    __shared__ int s[SCAN_CH];
    __shared__ int boff;
    int t = threadIdx.x;
    int idx = blockIdx.x * SCAN_CH + t;
    int my = (idx < NN) ? g_cnt[idx] : 0;
    s[t] = my;
    if (t == 0) {
        int run = 0;
        for (int i = 0; i < blockIdx.x; i++) run += g_bsum[i];
        boff = run;
    }
    __syncthreads();
    for (int off = 1; off < SCAN_CH; off <<= 1) {
        int u = 0;
        if (t >= off) u = s[t - off];
        __syncthreads();
        s[t] += u;
        __syncthreads();
    }
    if (idx < NN) g_rowptr[idx] = boff + s[t] - my;   // exclusive
    if (idx == NN - 1) g_rowptr[NN] = EE + NN;        // known total
}

__global__ void csr_fill_kernel(const int* __restrict__ ei,
                                const float* __restrict__ w) {
    int e = blockIdx.x * blockDim.x + threadIdx.x;
    if (e < EE) {
        int s = ei[e];
        int d = ei[EE + e];
        int pos = g_rowptr[d] + atomicAdd(&g_fill[d], 1);
        float v = g_deg[s] * w[e] * g_deg[d];       // g_deg holds dinv now
        g_pair[pos] = make_int2(s, __float_as_int(v));
    } else if (e < EE + NN) {
        int i = e - EE;
        int pos = g_rowptr[i] + atomicAdd(&g_fill[i], 1);
        float di = g_deg[i];
        g_pair[pos] = make_int2(i, __float_as_int(di * di));
    }
}

// ---------------- fp16 tensor-core GEMM: Zh[M,128] = A[M,128] @ W[128,128] ----
#define GBM 128
#define LDH 136   // halves per smem row (272 B; conflict-free ldmatrix phases)
#define GEMM_SMEM (2 * GBM * LDH * (int)sizeof(__half))   // 69632

__device__ __forceinline__ uint32_t smem_u32(const void* p) {
    return (uint32_t)__cvta_generic_to_shared(p);
}

template <typename TA>
__global__ __launch_bounds__(256) void gemm_h16_kernel(const TA* __restrict__ A,
                                                       const float* __restrict__ W,
                                                       __half* __restrict__ C, int M) {
    extern __shared__ __half smh[];
    __half* As = smh;                 // [128][LDH]
    __half* Bs = smh + GBM * LDH;     // [128][LDH]
    const int tid  = threadIdx.x;
    const int wid  = tid >> 5;
    const int lane = tid & 31;
    const int warp_m = wid & 3;
    const int warp_n = wid >> 2;
    const int m0 = blockIdx.x * GBM;

#pragma unroll
    for (int it = 0; it < 8; it++) {
        int idx = tid + it * 256;
        int row = idx >> 4;
        int hg  = (idx & 15) * 8;
        uint4 pk = make_uint4(0u, 0u, 0u, 0u);
        if (m0 + row < M) {
            const TA* src = A + (size_t)(m0 + row) * DD + hg;
            if (sizeof(TA) == 2) {
                pk = *reinterpret_cast<const uint4*>(src);
            } else {
                const float4 f0 = *reinterpret_cast<const float4*>((const float*)src);
                const float4 f1 = *reinterpret_cast<const float4*>((const float*)src + 4);
                __half2 h0 = __floats2half2_rn(f0.x, f0.y);
                __half2 h1 = __floats2half2_rn(f0.z, f0.w);
                __half2 h2 = __floats2half2_rn(f1.x, f1.y);
                __half2 h3 = __floats2half2_rn(f1.z, f1.w);
                pk.x = *reinterpret_cast<uint32_t*>(&h0);
                pk.y = *reinterpret_cast<uint32_t*>(&h1);
                pk.z = *reinterpret_cast<uint32_t*>(&h2);
                pk.w = *reinterpret_cast<uint32_t*>(&h3);
            }
        }
        *reinterpret_cast<uint4*>(&As[row * LDH + hg]) = pk;
    }
#pragma unroll
    for (int it = 0; it < 16; it++) {
        int idx = tid + it * 256;
        int row = idx >> 5;
        int cg  = (idx & 31) * 4;
        float4 w = *reinterpret_cast<const float4*>(W + (size_t)row * 128 + cg);
        __half2 h0 = __floats2half2_rn(w.x, w.y);
        __half2 h1 = __floats2half2_rn(w.z, w.w);
        uint2 pk;
        pk.x = *reinterpret_cast<uint32_t*>(&h0);
        pk.y = *reinterpret_cast<uint32_t*>(&h1);
        *reinterpret_cast<uint2*>(&Bs[row * LDH + cg]) = pk;
    }
    __syncthreads();

    float acc[2][8][4];
#pragma unroll
    for (int mi = 0; mi < 2; mi++)
#pragma unroll
        for (int ni = 0; ni < 8; ni++)
#pragma unroll
            for (int q = 0; q < 4; q++) acc[mi][ni][q] = 0.0f;

#pragma unroll
    for (int ks = 0; ks < 8; ks++) {
        const int kk = ks * 16;
        uint32_t a[2][4], b[8][2];
#pragma unroll
        for (int mi = 0; mi < 2; mi++) {
            uint32_t addr = smem_u32(&As[(warp_m * 32 + mi * 16 + (lane & 15)) * LDH
                                         + kk + (lane >> 4) * 8]);
            asm volatile("ldmatrix.sync.aligned.m8n8.x4.shared.b16 {%0,%1,%2,%3}, [%4];"
                         : "=r"(a[mi][0]), "=r"(a[mi][1]), "=r"(a[mi][2]), "=r"(a[mi][3])
                         : "r"(addr));
        }
#pragma unroll
        for (int nb = 0; nb < 4; nb++) {
            uint32_t addr = smem_u32(&Bs[(kk + (lane & 15)) * LDH
                                         + warp_n * 64 + nb * 16 + (lane >> 4) * 8]);
            asm volatile("ldmatrix.sync.aligned.m8n8.x4.trans.shared.b16 {%0,%1,%2,%3}, [%4];"
                         : "=r"(b[nb * 2][0]), "=r"(b[nb * 2][1]),
                           "=r"(b[nb * 2 + 1][0]), "=r"(b[nb * 2 + 1][1])
                         : "r"(addr));
        }
#pragma unroll
        for (int mi = 0; mi < 2; mi++)
#pragma unroll
            for (int ni = 0; ni < 8; ni++) {
                asm volatile(
                    "mma.sync.aligned.m16n8k16.row.col.f32.f16.f16.f32 "
                    "{%0,%1,%2,%3}, {%4,%5,%6,%7}, {%8,%9}, {%0,%1,%2,%3};\n"
                    : "+f"(acc[mi][ni][0]), "+f"(acc[mi][ni][1]),
                      "+f"(acc[mi][ni][2]), "+f"(acc[mi][ni][3])
                    : "r"(a[mi][0]), "r"(a[mi][1]), "r"(a[mi][2]), "r"(a[mi][3]),
                      "r"(b[ni][0]), "r"(b[ni][1]));
            }
    }
    const int g   = lane >> 2;
    const int tig = lane & 3;
#pragma unroll
    for (int mi = 0; mi < 2; mi++) {
        int row0 = m0 + warp_m * 32 + mi * 16 + g;
#pragma unroll
        for (int ni = 0; ni < 8; ni++) {
            int col = warp_n * 64 + ni * 8 + tig * 2;
            if (row0 < M)
                *reinterpret_cast<__half2*>(C + (size_t)row0 * DD + col) =
                    __floats2half2_rn(acc[mi][ni][0], acc[mi][ni][1]);
            if (row0 + 8 < M)
                *reinterpret_cast<__half2*>(C + (size_t)(row0 + 8) * DD + col) =
                    __floats2half2_rn(acc[mi][ni][2], acc[mi][ni][3]);
        }
    }
}

// ---- warp-aggregate one node into a float4 (lane's 4-channel slice) ----------
__device__ __forceinline__ float4 warp_agg_node(const __half* __restrict__ Zl,
                                                int i, int end) {
    float4 acc = make_float4(0.f, 0.f, 0.f, 0.f);
    if ((i & 1) && i < end) {     // peel to even pair index for int4 loads
        int2 p = g_pair[i];
        float v = __int_as_float(p.y);
        const __half2* q = reinterpret_cast<const __half2*>(Zl + (size_t)p.x * DD);
        __half2 a = q[0], d = q[1];
        float2 f;
        f = __half22float2(a); acc.x = fmaf(v, f.x, acc.x); acc.y = fmaf(v, f.y, acc.y);
        f = __half22float2(d); acc.z = fmaf(v, f.x, acc.z); acc.w = fmaf(v, f.y, acc.w);
        i++;
    }
    for (; i + 8 <= end; i += 8) {
        int4 pA = *reinterpret_cast<const int4*>(&g_pair[i]);
        int4 pB = *reinterpret_cast<const int4*>(&g_pair[i + 2]);
        int4 pC = *reinterpret_cast<const int4*>(&g_pair[i + 4]);
        int4 pD = *reinterpret_cast<const int4*>(&g_pair[i + 6]);
        const __half2* q0 = reinterpret_cast<const __half2*>(Zl + (size_t)pA.x * DD);
        const __half2* q1 = reinterpret_cast<const __half2*>(Zl + (size_t)pA.z * DD);
        const __half2* q2 = reinterpret_cast<const __half2*>(Zl + (size_t)pB.x * DD);
        const __half2* q3 = reinterpret_cast<const __half2*>(Zl + (size_t)pB.z * DD);
        const __half2* q4 = reinterpret_cast<const __half2*>(Zl + (size_t)pC.x * DD);
        const __half2* q5 = reinterpret_cast<const __half2*>(Zl + (size_t)pC.z * DD);
        const __half2* q6 = reinterpret_cast<const __half2*>(Zl + (size_t)pD.x * DD);
        const __half2* q7 = reinterpret_cast<const __half2*>(Zl + (size_t)pD.z * DD);
        __half2 a0 = q0[0], b0 = q0[1];
        __half2 a1 = q1[0], b1 = q1[1];
        __half2 a2 = q2[0], b2 = q2[1];
        __half2 a3 = q3[0], b3 = q3[1];
        __half2 a4 = q4[0], b4 = q4[1];
        __half2 a5 = q5[0], b5 = q5[1];
        __half2 a6 = q6[0], b6 = q6[1];
        __half2 a7 = q7[0], b7 = q7[1];
        float v0 = __int_as_float(pA.y), v1 = __int_as_float(pA.w);
        float v2 = __int_as_float(pB.y), v3 = __int_as_float(pB.w);
        float v4 = __int_as_float(pC.y), v5 = __int_as_float(pC.w);
        float v6 = __int_as_float(pD.y), v7 = __int_as_float(pD.w);
        float2 f;
        f = __half22float2(a0); acc.x = fmaf(v0, f.x, acc.x); acc.y = fmaf(v0, f.y, acc.y);
        f = __half22float2(b0); acc.z = fmaf(v0, f.x, acc.z); acc.w = fmaf(v0, f.y, acc.w);
        f = __half22float2(a1); acc.x = fmaf(v1, f.x, acc.x); acc.y = fmaf(v1, f.y, acc.y);
        f = __half22float2(b1); acc.z = fmaf(v1, f.x, acc.z); acc.w = fmaf(v1, f.y, acc.w);
        f = __half22float2(a2); acc.x = fmaf(v2, f.x, acc.x); acc.y = fmaf(v2, f.y, acc.y);
        f = __half22float2(b2); acc.z = fmaf(v2, f.x, acc.z); acc.w = fmaf(v2, f.y, acc.w);
        f = __half22float2(a3); acc.x = fmaf(v3, f.x, acc.x); acc.y = fmaf(v3, f.y, acc.y);
        f = __half22float2(b3); acc.z = fmaf(v3, f.x, acc.z); acc.w = fmaf(v3, f.y, acc.w);
        f = __half22float2(a4); acc.x = fmaf(v4, f.x, acc.x); acc.y = fmaf(v4, f.y, acc.y);
        f = __half22float2(b4); acc.z = fmaf(v4, f.x, acc.z); acc.w = fmaf(v4, f.y, acc.w);
        f = __half22float2(a5); acc.x = fmaf(v5, f.x, acc.x); acc.y = fmaf(v5, f.y, acc.y);
        f = __half22float2(b5); acc.z = fmaf(v5, f.x, acc.z); acc.w = fmaf(v5, f.y, acc.w);
        f = __half22float2(a6); acc.x = fmaf(v6, f.x, acc.x); acc.y = fmaf(v6, f.y, acc.y);
        f = __half22float2(b6); acc.z = fmaf(v6, f.x, acc.z); acc.w = fmaf(v6, f.y, acc.w);
        f = __half22float2(a7); acc.x = fmaf(v7, f.x, acc.x); acc.y = fmaf(v7, f.y, acc.y);
        f = __half22float2(b7); acc.z = fmaf(v7, f.x, acc.z); acc.w = fmaf(v7, f.y, acc.w);
    }
    for (; i + 2 <= end; i += 2) {
        int4 pA = *reinterpret_cast<const int4*>(&g_pair[i]);
        float v0 = __int_as_float(pA.y), v1 = __int_as_float(pA.w);
        const __half2* q0 = reinterpret_cast<const __half2*>(Zl + (size_t)pA.x * DD);
        const __half2* q1 = reinterpret_cast<const __half2*>(Zl + (size_t)pA.z * DD);
        __half2 a0 = q0[0], b0 = q0[1];
        __half2 a1 = q1[0], b1 = q1[1];
        float2 f;
        f = __half22float2(a0); acc.x = fmaf(v0, f.x, acc.x); acc.y = fmaf(v0, f.y, acc.y);
        f = __half22float2(b0); acc.z = fmaf(v0, f.x, acc.z); acc.w = fmaf(v0, f.y, acc.w);
        f = __half22float2(a1); acc.x = fmaf(v1, f.x, acc.x); acc.y = fmaf(v1, f.y, acc.y);
        f = __half22float2(b1); acc.z = fmaf(v1, f.x, acc.z); acc.w = fmaf(v1, f.y, acc.w);
    }
    if (i < end) {
        int2 p = g_pair[i];
        float v = __int_as_float(p.y);
        const __half2* q = reinterpret_cast<const __half2*>(Zl + (size_t)p.x * DD);
        __half2 a = q[0], d = q[1];
        float2 f;
        f = __half22float2(a); acc.x = fmaf(v, f.x, acc.x); acc.y = fmaf(v, f.y, acc.y);
        f = __half22float2(d); acc.z = fmaf(v, f.x, acc.z); acc.w = fmaf(v, f.y, acc.w);
    }
    return acc;
}

// ---------------- sparse aggregation: H[n] = relu(sum val * Zh[col] + b) ------
__global__ __launch_bounds__(256) void agg_kernel(const __half* __restrict__ Z,
                                                  const float* __restrict__ b,
                                                  __half* __restrict__ out) {
    int warp = (blockIdx.x * blockDim.x + threadIdx.x) >> 5;
    if (warp >= NN) return;
    int lane = threadIdx.x & 31;
    float4 acc = warp_agg_node(Z + lane * 4, g_rowptr[warp], g_rowptr[warp + 1]);
    const float4 bb = *reinterpret_cast<const float4*>(b + lane * 4);
    acc.x = fmaxf(acc.x + bb.x, 0.f);
    acc.y = fmaxf(acc.y + bb.y, 0.f);
    acc.z = fmaxf(acc.z + bb.z, 0.f);
    acc.w = fmaxf(acc.w + bb.w, 0.f);
    __half2 lo = __floats2half2_rn(acc.x, acc.y);
    __half2 hi = __floats2half2_rn(acc.z, acc.w);
    uint2 pk;
    pk.x = *reinterpret_cast<uint32_t*>(&lo);
    pk.y = *reinterpret_cast<uint32_t*>(&hi);
    *reinterpret_cast<uint2*>(out + (size_t)warp * DD + lane * 4) = pk;
}

// ------- fused agg4 (no relu) + gemm5 (128->2): Z5[n] = (agg(Zh)[n]+b4) @ W5 --
__global__ __launch_bounds__(256) void agg_gemm5_kernel(const __half* __restrict__ Z,
                                                        const float* __restrict__ b4,
                                                        const float* __restrict__ W5,
                                                        float* __restrict__ Z5) {
    int warp = (blockIdx.x * blockDim.x + threadIdx.x) >> 5;
    if (warp >= NN) return;
    int lane = threadIdx.x & 31;
    float4 acc = warp_agg_node(Z + lane * 4, g_rowptr[warp], g_rowptr[warp + 1]);
    const float4 bb = *reinterpret_cast<const float4*>(b4 + lane * 4);
    acc.x += bb.x; acc.y += bb.y; acc.z += bb.z; acc.w += bb.w;
    // W5 row-major [128][2]: lane covers k = 4*lane .. 4*lane+3
    const float4 w0 = *reinterpret_cast<const float4*>(W5 + lane * 8);
    const float4 w1 = *reinterpret_cast<const float4*>(W5 + lane * 8 + 4);
    float p0 = acc.x * w0.x + acc.y * w0.z + acc.z * w1.x + acc.w * w1.z;
    float p1 = acc.x * w0.y + acc.y * w0.w + acc.z * w1.y + acc.w * w1.w;
#pragma unroll
    for (int off = 16; off > 0; off >>= 1) {
        p0 += __shfl_down_sync(0xffffffffu, p0, off);
        p1 += __shfl_down_sync(0xffffffffu, p1, off);
    }
    if (lane == 0) {
        Z5[(size_t)warp * 2]     = p0;
        Z5[(size_t)warp * 2 + 1] = p1;
    }
}

// ---------------- final aggregation on 2-wide Z5 ------------------------------
__global__ __launch_bounds__(256) void agg5_kernel(const float* __restrict__ Z5,
                                                   const float* __restrict__ b5,
                                                   float* __restrict__ out) {
    int n = blockIdx.x * blockDim.x + threadIdx.x;
    if (n >= NN) return;
    float a0 = 0.f, a1 = 0.f;
    int i = g_rowptr[n];
    int end = g_rowptr[n + 1];
    for (; i < end; i++) {
        int2 p = g_pair[i];
        float v = __int_as_float(p.y);
        const float2 z = *reinterpret_cast<const float2*>(Z5 + (size_t)p.x * 2);
        a0 = fmaf(v, z.x, a0);
        a1 = fmaf(v, z.y, a1);
    }
    out[(size_t)n * 2]     = a0 + b5[0];
    out[(size_t)n * 2 + 1] = a1 + b5[1];
}

// ---------------- driver ----------------
extern "C" void kernel_launch(void* const* d_in, const int* in_sizes, int n_in,
                              void* d_out, int out_size) {
    const float* x  = (const float*)d_in[0];
    const int*   ei = (const int*)d_in[1];       // int32 (JAX default, x64 disabled)
    const float* ew = (const float*)d_in[2];
    const float* W1 = (const float*)d_in[3];  const float* b1 = (const float*)d_in[4];
    const float* W2 = (const float*)d_in[5];  const float* b2 = (const float*)d_in[6];
    const float* W3 = (const float*)d_in[7];  const float* b3 = (const float*)d_in[8];
    const float* W4 = (const float*)d_in[9];  const float* b4 = (const float*)d_in[10];
    const float* W5 = (const float*)d_in[11]; const float* b5 = (const float*)d_in[12];
    float* out = (float*)d_out;

    __half *Zh, *HA, *HB; float *Z5;
    cudaGetSymbolAddress((void**)&Zh, g_Zh);
    cudaGetSymbolAddress((void**)&HA, g_HA);
    cudaGetSymbolAddress((void**)&HB, g_HB);
    cudaGetSymbolAddress((void**)&Z5, g_Z5);

    cudaFuncSetAttribute(gemm_h16_kernel<float>,
                         cudaFuncAttributeMaxDynamicSharedMemorySize, GEMM_SMEM);
    cudaFuncSetAttribute(gemm_h16_kernel<__half>,
                         cudaFuncAttributeMaxDynamicSharedMemorySize, GEMM_SMEM);

    const int TB = 256;
    // graph preprocessing (5 launches)
    init_kernel<<<(NN + TB - 1) / TB, TB>>>();
    deg_cnt_kernel<<<(EE + TB - 1) / TB, TB>>>(ei, ew);
    scanA_dinv_kernel<<<SCAN_NB, SCAN_CH>>>();
    scanC_kernel<<<SCAN_NB, SCAN_CH>>>();
    csr_fill_kernel<<<(EE + NN + TB - 1) / TB, TB>>>(ei, ew);

    const int gemm_blocks = (NN + GBM - 1) / GBM;
    const int agg_blocks  = (int)(((size_t)NN * 32 + TB - 1) / TB);

    // layer 1 (A = x fp32, converted in-kernel)
    gemm_h16_kernel<float><<<gemm_blocks, 256, GEMM_SMEM>>>(x, W1, Zh, NN);
    agg_kernel<<<agg_blocks, TB>>>(Zh, b1, HA);
    // layer 2
    gemm_h16_kernel<__half><<<gemm_blocks, 256, GEMM_SMEM>>>(HA, W2, Zh, NN);
    agg_kernel<<<agg_blocks, TB>>>(Zh, b2, HB);
    // layer 3
    gemm_h16_kernel<__half><<<gemm_blocks, 256, GEMM_SMEM>>>(HB, W3, Zh, NN);
    agg_kernel<<<agg_blocks, TB>>>(Zh, b3, HA);
    // layer 4 gemm, then fused agg4+gemm5
    gemm_h16_kernel<__half><<<gemm_blocks, 256, GEMM_SMEM>>>(HA, W4, Zh, NN);
    agg_gemm5_kernel<<<agg_blocks, TB>>>(Zh, b4, W5, Z5);
    // final 2-wide aggregation
    agg5_kernel<<<(NN + TB - 1) / TB, TB>>>(Z5, b5, out);
}

// round 12
// speedup vs baseline: 1.7738x; 1.0227x over previous
#include <cuda_runtime.h>
#include <cuda_fp16.h>
#include <stdint.h>

#define NN 100000
#define EE 1600000
#define DD 128

#define SCAN_CH  1024
#define SCAN_NB  ((NN + SCAN_CH - 1) / SCAN_CH)   // 98

// ---------------- scratch (static __device__, no allocation) ----------------
__device__ float  g_deg[NN];            // edge-weight sums; then dinv in place; zeroed by agg1
__device__ int    g_cnt[NN];            // edge counts (atomic); zeroed by scanC
__device__ int    g_rowptr[NN + 1];
__device__ int    g_fill[NN];           // fill cursor = rowptr+1 (self-loop at rowptr)
__device__ int    g_bsum[SCAN_NB];
__device__ __align__(16) int2 g_pair[EE + NN];   // packed {col, val_bits}
__device__ __half g_Wh[4 * DD * DD];    // fp16-converted W1..W4
__device__ __half g_Zh[NN * DD];        // post-GEMM features (gather source)
__device__ __half g_HA[NN * DD];        // post-agg features, fp16
__device__ __half g_HB[NN * DD];
__device__ float  g_Z5[NN * 2];

// ---------------- graph preprocessing ----------------
// NOTE: g_deg and g_cnt are guaranteed zero at entry: first call via module
// load, subsequent calls because scanC zeroes g_cnt and agg1 zeroes g_deg.
__global__ void deg_cnt_kernel(const int* __restrict__ ei,
                               const float* __restrict__ w) {
    int e = blockIdx.x * blockDim.x + threadIdx.x;
    if (e >= EE) return;
    int d = ei[EE + e];
    atomicAdd(&g_deg[d], w[e]);
    atomicAdd(&g_cnt[d], 1);
}

// ---- scan phase A + dinv: per-block sums of cnt; deg -> rsqrt(deg_edges + 1) --
__global__ __launch_bounds__(SCAN_CH) void scanA_dinv_kernel() {
    __shared__ int s[SCAN_CH];
    int t = threadIdx.x;
    int idx = blockIdx.x * SCAN_CH + t;
    int c = 0;
    if (idx < NN) {
        c = g_cnt[idx];
        g_deg[idx] = rsqrtf(g_deg[idx] + 1.0f);   // +1 = self-loop weight
    }
    s[t] = c;
    __syncthreads();
    for (int off = SCAN_CH >> 1; off > 0; off >>= 1) {
        if (t < off) s[t] += s[t + off];
        __syncthreads();
    }
    if (t == 0) g_bsum[blockIdx.x] = s[0];
}

// ---- scan phase C: rowptr (incl. self-loops), fill cursor, self-loop pair ----
__global__ __launch_bounds__(SCAN_CH) void scanC_kernel() {
    __shared__ int s[SCAN_CH];
    __shared__ int boff;
    int t = threadIdx.x;
    int idx = blockIdx.x * SCAN_CH + t;
    int my = (idx < NN) ? g_cnt[idx] : 0;
    s[t] = my;
    if (t == 0) {
        int run = 0;
        for (int i = 0; i < blockIdx.x; i++) run += g_bsum[i];
        boff = run;
    }
    __syncthreads();
    for (int off = 1; off < SCAN_CH; off <<= 1) {
        int u = 0;
        if (t >= off) u = s[t - off];
        __syncthreads();
        s[t] += u;
        __syncthreads();
    }
    if (idx < NN) {
        int rp = boff + (s[t] - my) + idx;       // +idx = self-loop slots
        g_rowptr[idx] = rp;
        g_fill[idx]   = rp + 1;                  // cursor; edge entries after self-loop
        float di = g_deg[idx];
        g_pair[rp] = make_int2(idx, __float_as_int(di * di));   // self-loop entry
        g_cnt[idx] = 0;                          // re-zero for next call
    }
    if (idx == NN - 1) g_rowptr[NN] = EE + NN;   // known total
}

__global__ void csr_fill_kernel(const int* __restrict__ ei,
                                const float* __restrict__ w) {
    int e = blockIdx.x * blockDim.x + threadIdx.x;
    if (e >= EE) return;
    int s = ei[e];
    int d = ei[EE + e];
    int pos = atomicAdd(&g_fill[d], 1);
    float v = g_deg[s] * w[e] * g_deg[d];        // g_deg holds dinv now
    g_pair[pos] = make_int2(s, __float_as_int(v));
}

// ---- pre-convert W1..W4 (fp32 [128][128]) to fp16 ----
__global__ __launch_bounds__(256) void convW_kernel(const float* __restrict__ W1,
                                                    const float* __restrict__ W2,
                                                    const float* __restrict__ W3,
                                                    const float* __restrict__ W4) {
    int idx = blockIdx.x * blockDim.x + threadIdx.x;   // 0..16383 (x4 floats)
    int which = idx >> 12;                             // 4096 float4 per W
    int off   = (idx & 4095) * 4;
    const float* W = (which == 0) ? W1 : (which == 1) ? W2 : (which == 2) ? W3 : W4;
    float4 f = *reinterpret_cast<const float4*>(W + off);
    __half2 h0 = __floats2half2_rn(f.x, f.y);
    __half2 h1 = __floats2half2_rn(f.z, f.w);
    uint2 pk;
    pk.x = *reinterpret_cast<uint32_t*>(&h0);
    pk.y = *reinterpret_cast<uint32_t*>(&h1);
    *reinterpret_cast<uint2*>(&g_Wh[which * DD * DD + off]) = pk;
}

// ---------------- fp16 tensor-core GEMM: Zh[M,128] = A[M,128] @ W[128,128] ----
#define GBM 128
#define LDH 136   // halves per smem row (272 B; conflict-free ldmatrix phases)
#define GEMM_SMEM (2 * GBM * LDH * (int)sizeof(__half))   // 69632

__device__ __forceinline__ uint32_t smem_u32(const void* p) {
    return (uint32_t)__cvta_generic_to_shared(p);
}

template <typename TA>
__global__ __launch_bounds__(256) void gemm_h16_kernel(const TA* __restrict__ A,
                                                       const __half* __restrict__ W,
                                                       __half* __restrict__ C, int M) {
    extern __shared__ __half smh[];
    __half* As = smh;                 // [128][LDH]
    __half* Bs = smh + GBM * LDH;     // [128][LDH]
    const int tid  = threadIdx.x;
    const int wid  = tid >> 5;
    const int lane = tid & 31;
    const int warp_m = wid & 3;
    const int warp_n = wid >> 2;
    const int m0 = blockIdx.x * GBM;

    // ---- load A tile (convert to fp16 if fp32) ----
#pragma unroll
    for (int it = 0; it < 8; it++) {
        int idx = tid + it * 256;
        int row = idx >> 4;
        int hg  = (idx & 15) * 8;
        uint4 pk = make_uint4(0u, 0u, 0u, 0u);
        if (m0 + row < M) {
            const TA* src = A + (size_t)(m0 + row) * DD + hg;
            if (sizeof(TA) == 2) {
                pk = *reinterpret_cast<const uint4*>(src);
            } else {
                const float4 f0 = *reinterpret_cast<const float4*>((const float*)src);
                const float4 f1 = *reinterpret_cast<const float4*>((const float*)src + 4);
                __half2 h0 = __floats2half2_rn(f0.x, f0.y);
                __half2 h1 = __floats2half2_rn(f0.z, f0.w);
                __half2 h2 = __floats2half2_rn(f1.x, f1.y);
                __half2 h3 = __floats2half2_rn(f1.z, f1.w);
                pk.x = *reinterpret_cast<uint32_t*>(&h0);
                pk.y = *reinterpret_cast<uint32_t*>(&h1);
                pk.z = *reinterpret_cast<uint32_t*>(&h2);
                pk.w = *reinterpret_cast<uint32_t*>(&h3);
            }
        }
        *reinterpret_cast<uint4*>(&As[row * LDH + hg]) = pk;
    }
    // ---- load W tile (already fp16) ----
#pragma unroll
    for (int it = 0; it < 8; it++) {
        int idx = tid + it * 256;
        int row = idx >> 4;
        int hg  = (idx & 15) * 8;
        uint4 pk = *reinterpret_cast<const uint4*>(W + (size_t)row * DD + hg);
        *reinterpret_cast<uint4*>(&Bs[row * LDH + hg]) = pk;
    }
    __syncthreads();

    float acc[2][8][4];
#pragma unroll
    for (int mi = 0; mi < 2; mi++)
#pragma unroll
        for (int ni = 0; ni < 8; ni++)
#pragma unroll
            for (int q = 0; q < 4; q++) acc[mi][ni][q] = 0.0f;

#pragma unroll
    for (int ks = 0; ks < 8; ks++) {
        const int kk = ks * 16;
        uint32_t a[2][4], b[8][2];
#pragma unroll
        for (int mi = 0; mi < 2; mi++) {
            uint32_t addr = smem_u32(&As[(warp_m * 32 + mi * 16 + (lane & 15)) * LDH
                                         + kk + (lane >> 4) * 8]);
            asm volatile("ldmatrix.sync.aligned.m8n8.x4.shared.b16 {%0,%1,%2,%3}, [%4];"
                         : "=r"(a[mi][0]), "=r"(a[mi][1]), "=r"(a[mi][2]), "=r"(a[mi][3])
                         : "r"(addr));
        }
#pragma unroll
        for (int nb = 0; nb < 4; nb++) {
            uint32_t addr = smem_u32(&Bs[(kk + (lane & 15)) * LDH
                                         + warp_n * 64 + nb * 16 + (lane >> 4) * 8]);
            asm volatile("ldmatrix.sync.aligned.m8n8.x4.trans.shared.b16 {%0,%1,%2,%3}, [%4];"
                         : "=r"(b[nb * 2][0]), "=r"(b[nb * 2][1]),
                           "=r"(b[nb * 2 + 1][0]), "=r"(b[nb * 2 + 1][1])
                         : "r"(addr));
        }
#pragma unroll
        for (int mi = 0; mi < 2; mi++)
#pragma unroll
            for (int ni = 0; ni < 8; ni++) {
                asm volatile(
                    "mma.sync.aligned.m16n8k16.row.col.f32.f16.f16.f32 "
                    "{%0,%1,%2,%3}, {%4,%5,%6,%7}, {%8,%9}, {%0,%1,%2,%3};\n"
                    : "+f"(acc[mi][ni][0]), "+f"(acc[mi][ni][1]),
                      "+f"(acc[mi][ni][2]), "+f"(acc[mi][ni][3])
                    : "r"(a[mi][0]), "r"(a[mi][1]), "r"(a[mi][2]), "r"(a[mi][3]),
                      "r"(b[ni][0]), "r"(b[ni][1]));
            }
    }
    const int g   = lane >> 2;
    const int tig = lane & 3;
#pragma unroll
    for (int mi = 0; mi < 2; mi++) {
        int row0 = m0 + warp_m * 32 + mi * 16 + g;
#pragma unroll
        for (int ni = 0; ni < 8; ni++) {
            int col = warp_n * 64 + ni * 8 + tig * 2;
            if (row0 < M)
                *reinterpret_cast<__half2*>(C + (size_t)row0 * DD + col) =
                    __floats2half2_rn(acc[mi][ni][0], acc[mi][ni][1]);
            if (row0 + 8 < M)
                *reinterpret_cast<__half2*>(C + (size_t)(row0 + 8) * DD + col) =
                    __floats2half2_rn(acc[mi][ni][2], acc[mi][ni][3]);
        }
    }
}

// ---- warp-aggregate one node into a float4 (lane's 4-channel slice) ----------
__device__ __forceinline__ float4 warp_agg_node(const __half* __restrict__ Zl,
                                                int i, int end) {
    float4 acc = make_float4(0.f, 0.f, 0.f, 0.f);
    if ((i & 1) && i < end) {     // peel to even pair index for int4 loads
        int2 p = g_pair[i];
        float v = __int_as_float(p.y);
        const __half2* q = reinterpret_cast<const __half2*>(Zl + (size_t)p.x * DD);
        __half2 a = q[0], d = q[1];
        float2 f;
        f = __half22float2(a); acc.x = fmaf(v, f.x, acc.x); acc.y = fmaf(v, f.y, acc.y);
        f = __half22float2(d); acc.z = fmaf(v, f.x, acc.z); acc.w = fmaf(v, f.y, acc.w);
        i++;
    }
    for (; i + 8 <= end; i += 8) {
        int4 pA = *reinterpret_cast<const int4*>(&g_pair[i]);
        int4 pB = *reinterpret_cast<const int4*>(&g_pair[i + 2]);
        int4 pC = *reinterpret_cast<const int4*>(&g_pair[i + 4]);
        int4 pD = *reinterpret_cast<const int4*>(&g_pair[i + 6]);
        const __half2* q0 = reinterpret_cast<const __half2*>(Zl + (size_t)pA.x * DD);
        const __half2* q1 = reinterpret_cast<const __half2*>(Zl + (size_t)pA.z * DD);
        const __half2* q2 = reinterpret_cast<const __half2*>(Zl + (size_t)pB.x * DD);
        const __half2* q3 = reinterpret_cast<const __half2*>(Zl + (size_t)pB.z * DD);
        const __half2* q4 = reinterpret_cast<const __half2*>(Zl + (size_t)pC.x * DD);
        const __half2* q5 = reinterpret_cast<const __half2*>(Zl + (size_t)pC.z * DD);
        const __half2* q6 = reinterpret_cast<const __half2*>(Zl + (size_t)pD.x * DD);
        const __half2* q7 = reinterpret_cast<const __half2*>(Zl + (size_t)pD.z * DD);
        __half2 a0 = q0[0], b0 = q0[1];
        __half2 a1 = q1[0], b1 = q1[1];
        __half2 a2 = q2[0], b2 = q2[1];
        __half2 a3 = q3[0], b3 = q3[1];
        __half2 a4 = q4[0], b4 = q4[1];
        __half2 a5 = q5[0], b5 = q5[1];
        __half2 a6 = q6[0], b6 = q6[1];
        __half2 a7 = q7[0], b7 = q7[1];
        float v0 = __int_as_float(pA.y), v1 = __int_as_float(pA.w);
        float v2 = __int_as_float(pB.y), v3 = __int_as_float(pB.w);
        float v4 = __int_as_float(pC.y), v5 = __int_as_float(pC.w);
        float v6 = __int_as_float(pD.y), v7 = __int_as_float(pD.w);
        float2 f;
        f = __half22float2(a0); acc.x = fmaf(v0, f.x, acc.x); acc.y = fmaf(v0, f.y, acc.y);
        f = __half22float2(b0); acc.z = fmaf(v0, f.x, acc.z); acc.w = fmaf(v0, f.y, acc.w);
        f = __half22float2(a1); acc.x = fmaf(v1, f.x, acc.x); acc.y = fmaf(v1, f.y, acc.y);
        f = __half22float2(b1); acc.z = fmaf(v1, f.x, acc.z); acc.w = fmaf(v1, f.y, acc.w);
        f = __half22float2(a2); acc.x = fmaf(v2, f.x, acc.x); acc.y = fmaf(v2, f.y, acc.y);
        f = __half22float2(b2); acc.z = fmaf(v2, f.x, acc.z); acc.w = fmaf(v2, f.y, acc.w);
        f = __half22float2(a3); acc.x = fmaf(v3, f.x, acc.x); acc.y = fmaf(v3, f.y, acc.y);
        f = __half22float2(b3); acc.z = fmaf(v3, f.x, acc.z); acc.w = fmaf(v3, f.y, acc.w);
        f = __half22float2(a4); acc.x = fmaf(v4, f.x, acc.x); acc.y = fmaf(v4, f.y, acc.y);
        f = __half22float2(b4); acc.z = fmaf(v4, f.x, acc.z); acc.w = fmaf(v4, f.y, acc.w);
        f = __half22float2(a5); acc.x = fmaf(v5, f.x, acc.x); acc.y = fmaf(v5, f.y, acc.y);
        f = __half22float2(b5); acc.z = fmaf(v5, f.x, acc.z); acc.w = fmaf(v5, f.y, acc.w);
        f = __half22float2(a6); acc.x = fmaf(v6, f.x, acc.x); acc.y = fmaf(v6, f.y, acc.y);
        f = __half22float2(b6); acc.z = fmaf(v6, f.x, acc.z); acc.w = fmaf(v6, f.y, acc.w);
        f = __half22float2(a7); acc.x = fmaf(v7, f.x, acc.x); acc.y = fmaf(v7, f.y, acc.y);
        f = __half22float2(b7); acc.z = fmaf(v7, f.x, acc.z); acc.w = fmaf(v7, f.y, acc.w);
    }
    for (; i + 2 <= end; i += 2) {
        int4 pA = *reinterpret_cast<const int4*>(&g_pair[i]);
        float v0 = __int_as_float(pA.y), v1 = __int_as_float(pA.w);
        const __half2* q0 = reinterpret_cast<const __half2*>(Zl + (size_t)pA.x * DD);
        const __half2* q1 = reinterpret_cast<const __half2*>(Zl + (size_t)pA.z * DD);
        __half2 a0 = q0[0], b0 = q0[1];
        __half2 a1 = q1[0], b1 = q1[1];
        float2 f;
        f = __half22float2(a0); acc.x = fmaf(v0, f.x, acc.x); acc.y = fmaf(v0, f.y, acc.y);
        f = __half22float2(b0); acc.z = fmaf(v0, f.x, acc.z); acc.w = fmaf(v0, f.y, acc.w);
        f = __half22float2(a1); acc.x = fmaf(v1, f.x, acc.x); acc.y = fmaf(v1, f.y, acc.y);
        f = __half22float2(b1); acc.z = fmaf(v1, f.x, acc.z); acc.w = fmaf(v1, f.y, acc.w);
    }
    if (i < end) {
        int2 p = g_pair[i];
        float v = __int_as_float(p.y);
        const __half2* q = reinterpret_cast<const __half2*>(Zl + (size_t)p.x * DD);
        __half2 a = q[0], d = q[1];
        float2 f;
        f = __half22float2(a); acc.x = fmaf(v, f.x, acc.x); acc.y = fmaf(v, f.y, acc.y);
        f = __half22float2(d); acc.z = fmaf(v, f.x, acc.z); acc.w = fmaf(v, f.y, acc.w);
    }
    return acc;
}

// ---------------- sparse aggregation: H[n] = relu(sum val * Zh[col] + b) ------
template <bool ZERO_DEG>
__global__ __launch_bounds__(256) void agg_kernel(const __half* __restrict__ Z,
                                                  const float* __restrict__ b,
                                                  __half* __restrict__ out) {
    int warp = (blockIdx.x * blockDim.x + threadIdx.x) >> 5;
    if (warp >= NN) return;
    int lane = threadIdx.x & 31;
    if (ZERO_DEG && lane == 0) g_deg[warp] = 0.0f;   // re-zero for next call
    float4 acc = warp_agg_node(Z + lane * 4, g_rowptr[warp], g_rowptr[warp + 1]);
    const float4 bb = *reinterpret_cast<const float4*>(b + lane * 4);
    acc.x = fmaxf(acc.x + bb.x, 0.f);
    acc.y = fmaxf(acc.y + bb.y, 0.f);
    acc.z = fmaxf(acc.z + bb.z, 0.f);
    acc.w = fmaxf(acc.w + bb.w, 0.f);
    __half2 lo = __floats2half2_rn(acc.x, acc.y);
    __half2 hi = __floats2half2_rn(acc.z, acc.w);
    uint2 pk;
    pk.x = *reinterpret_cast<uint32_t*>(&lo);
    pk.y = *reinterpret_cast<uint32_t*>(&hi);
    *reinterpret_cast<uint2*>(out + (size_t)warp * DD + lane * 4) = pk;
}

// ------- fused agg4 (no relu) + gemm5 (128->2): Z5[n] = (agg(Zh)[n]+b4) @ W5 --
__global__ __launch_bounds__(256) void agg_gemm5_kernel(const __half* __restrict__ Z,
                                                        const float* __restrict__ b4,
                                                        const float* __restrict__ W5,
                                                        float* __restrict__ Z5) {
    int warp = (blockIdx.x * blockDim.x + threadIdx.x) >> 5;
    if (warp >= NN) return;
    int lane = threadIdx.x & 31;
    float4 acc = warp_agg_node(Z + lane * 4, g_rowptr[warp], g_rowptr[warp + 1]);
    const float4 bb = *reinterpret_cast<const float4*>(b4 + lane * 4);
    acc.x += bb.x; acc.y += bb.y; acc.z += bb.z; acc.w += bb.w;
    const float4 w0 = *reinterpret_cast<const float4*>(W5 + lane * 8);
    const float4 w1 = *reinterpret_cast<const float4*>(W5 + lane * 8 + 4);
    float p0 = acc.x * w0.x + acc.y * w0.z + acc.z * w1.x + acc.w * w1.z;
    float p1 = acc.x * w0.y + acc.y * w0.w + acc.z * w1.y + acc.w * w1.w;
#pragma unroll
    for (int off = 16; off > 0; off >>= 1) {
        p0 += __shfl_down_sync(0xffffffffu, p0, off);
        p1 += __shfl_down_sync(0xffffffffu, p1, off);
    }
    if (lane == 0) {
        Z5[(size_t)warp * 2]     = p0;
        Z5[(size_t)warp * 2 + 1] = p1;
    }
}

// ---------------- final aggregation on 2-wide Z5 ------------------------------
__global__ __launch_bounds__(256) void agg5_kernel(const float* __restrict__ Z5,
                                                   const float* __restrict__ b5,
                                                   float* __restrict__ out) {
    int n = blockIdx.x * blockDim.x + threadIdx.x;
    if (n >= NN) return;
    float a0 = 0.f, a1 = 0.f;
    int i = g_rowptr[n];
    int end = g_rowptr[n + 1];
    for (; i < end; i++) {
        int2 p = g_pair[i];
        float v = __int_as_float(p.y);
        const float2 z = *reinterpret_cast<const float2*>(Z5 + (size_t)p.x * 2);
        a0 = fmaf(v, z.x, a0);
        a1 = fmaf(v, z.y, a1);
    }
    out[(size_t)n * 2]     = a0 + b5[0];
    out[(size_t)n * 2 + 1] = a1 + b5[1];
}

// ---------------- driver ----------------
extern "C" void kernel_launch(void* const* d_in, const int* in_sizes, int n_in,
                              void* d_out, int out_size) {
    const float* x  = (const float*)d_in[0];
    const int*   ei = (const int*)d_in[1];       // int32 (JAX default, x64 disabled)
    const float* ew = (const float*)d_in[2];
    const float* W1 = (const float*)d_in[3];  const float* b1 = (const float*)d_in[4];
    const float* W2 = (const float*)d_in[5];  const float* b2 = (const float*)d_in[6];
    const float* W3 = (const float*)d_in[7];  const float* b3 = (const float*)d_in[8];
    const float* W4 = (const float*)d_in[9];  const float* b4 = (const float*)d_in[10];
    const float* W5 = (const float*)d_in[11]; const float* b5 = (const float*)d_in[12];
    float* out = (float*)d_out;

    __half *Zh, *HA, *HB, *Wh; float *Z5;
    cudaGetSymbolAddress((void**)&Zh, g_Zh);
    cudaGetSymbolAddress((void**)&HA, g_HA);
    cudaGetSymbolAddress((void**)&HB, g_HB);
    cudaGetSymbolAddress((void**)&Wh, g_Wh);
    cudaGetSymbolAddress((void**)&Z5, g_Z5);

    cudaFuncSetAttribute(gemm_h16_kernel<float>,
                         cudaFuncAttributeMaxDynamicSharedMemorySize, GEMM_SMEM);
    cudaFuncSetAttribute(gemm_h16_kernel<__half>,
                         cudaFuncAttributeMaxDynamicSharedMemorySize, GEMM_SMEM);

    const int TB = 256;
    // graph preprocessing (4 launches; csr_fill is the 4th -> ncu target)
    deg_cnt_kernel<<<(EE + TB - 1) / TB, TB>>>(ei, ew);
    scanA_dinv_kernel<<<SCAN_NB, SCAN_CH>>>();
    scanC_kernel<<<SCAN_NB, SCAN_CH>>>();
    csr_fill_kernel<<<(EE + TB - 1) / TB, TB>>>(ei, ew);
    // W pre-conversion
    convW_kernel<<<64, TB>>>(W1, W2, W3, W4);

    const int gemm_blocks = (NN + GBM - 1) / GBM;
    const int agg_blocks  = (int)(((size_t)NN * 32 + TB - 1) / TB);

    // layer 1 (A = x fp32, converted in-kernel); agg1 also re-zeroes g_deg
    gemm_h16_kernel<float><<<gemm_blocks, 256, GEMM_SMEM>>>(x, Wh, Zh, NN);
    agg_kernel<true><<<agg_blocks, TB>>>(Zh, b1, HA);
    // layer 2
    gemm_h16_kernel<__half><<<gemm_blocks, 256, GEMM_SMEM>>>(HA, Wh + DD * DD, Zh, NN);
    agg_kernel<false><<<agg_blocks, TB>>>(Zh, b2, HB);
    // layer 3
    gemm_h16_kernel<__half><<<gemm_blocks, 256, GEMM_SMEM>>>(HB, Wh + 2 * DD * DD, Zh, NN);
    agg_kernel<false><<<agg_blocks, TB>>>(Zh, b3, HA);
    // layer 4 gemm, then fused agg4+gemm5
    gemm_h16_kernel<__half><<<gemm_blocks, 256, GEMM_SMEM>>>(HA, Wh + 3 * DD * DD, Zh, NN);
    agg_gemm5_kernel<<<agg_blocks, TB>>>(Zh, b4, W5, Z5);
    // final 2-wide aggregation
    agg5_kernel<<<(NN + TB - 1) / TB, TB>>>(Z5, b5, out);
}

// round 13
// speedup vs baseline: 1.8144x; 1.0229x over previous
#include <cuda_runtime.h>
#include <cuda_fp16.h>
#include <stdint.h>

#define NN 100000
#define EE 1600000
#define DD 128

#define SCAN_CH  1024
#define SCAN_NB  ((NN + SCAN_CH - 1) / SCAN_CH)   // 98
#define CONVW_NB 16                                // extra scanA blocks for W conversion

// ---------------- scratch (static __device__, no allocation) ----------------
__device__ unsigned long long g_degcnt[NN];  // packed {cnt[52:64), wsum_q32[0:52)}; zeroed by scanC
__device__ float  g_deg[NN];                 // dinv (pure scanA output)
__device__ int    g_cnt[NN];                 // decoded counts (scanA -> scanC)
__device__ int    g_seq[EE];                 // per-edge slot within dst row
__device__ int    g_rowptr[NN + 1];
__device__ int    g_bsum[SCAN_NB];
__device__ __align__(16) int2 g_pair[EE + NN];   // packed {col, val_bits}
__device__ __half g_Wh[4 * DD * DD];    // fp16-converted W1..W4
__device__ __half g_Zh[NN * DD];        // post-GEMM features (gather source)
__device__ __half g_HA[NN * DD];        // post-agg features, fp16
__device__ __half g_HB[NN * DD];
__device__ float  g_Z5[NN * 2];

// ---------------- graph preprocessing ----------------
// g_degcnt is zero at entry (module load first call; scanC re-zeroes after).
__global__ void deg_cnt_kernel(const int* __restrict__ ei,
                               const float* __restrict__ w) {
    int e = blockIdx.x * blockDim.x + threadIdx.x;
    if (e >= EE) return;
    int d = ei[EE + e];
    unsigned long long wq = (unsigned long long)((double)w[e] * 4294967296.0);
    unsigned long long old = atomicAdd(&g_degcnt[d], (1ull << 52) | wq);
    g_seq[e] = (int)(old >> 52);
}

// ---- scanA: decode degcnt -> per-block sums + dinv; extra blocks convert W ----
__global__ __launch_bounds__(SCAN_CH) void scanA_dinv_convW_kernel(
    const float* __restrict__ W1, const float* __restrict__ W2,
    const float* __restrict__ W3, const float* __restrict__ W4) {
    int t = threadIdx.x;
    if (blockIdx.x >= SCAN_NB) {
        // W conversion: 16 blocks x 1024 threads = 16384 float4 (4 x 128 x 128)
        int idx = (blockIdx.x - SCAN_NB) * SCAN_CH + t;
        int which = idx >> 12;
        int off   = (idx & 4095) * 4;
        const float* W = (which == 0) ? W1 : (which == 1) ? W2 : (which == 2) ? W3 : W4;
        float4 f = *reinterpret_cast<const float4*>(W + off);
        __half2 h0 = __floats2half2_rn(f.x, f.y);
        __half2 h1 = __floats2half2_rn(f.z, f.w);
        uint2 pk;
        pk.x = *reinterpret_cast<uint32_t*>(&h0);
        pk.y = *reinterpret_cast<uint32_t*>(&h1);
        *reinterpret_cast<uint2*>(&g_Wh[which * DD * DD + off]) = pk;
        return;
    }
    __shared__ int s[SCAN_CH];
    int idx = blockIdx.x * SCAN_CH + t;
    int c = 0;
    if (idx < NN) {
        unsigned long long dc = g_degcnt[idx];
        c = (int)(dc >> 52);
        float wsum = (float)((double)(dc & ((1ull << 52) - 1ull)) * (1.0 / 4294967296.0));
        g_deg[idx] = rsqrtf(wsum + 1.0f);   // +1 = self-loop weight
        g_cnt[idx] = c;
    }
    s[t] = c;
    __syncthreads();
    for (int off = SCAN_CH >> 1; off > 0; off >>= 1) {
        if (t < off) s[t] += s[t + off];
        __syncthreads();
    }
    if (t == 0) g_bsum[blockIdx.x] = s[0];
}

// ---- scanC: rowptr (incl. self-loops), self-loop pair, re-zero degcnt ----
__global__ __launch_bounds__(SCAN_CH) void scanC_kernel() {
    __shared__ int s[SCAN_CH];
    __shared__ int boff;
    int t = threadIdx.x;
    int idx = blockIdx.x * SCAN_CH + t;
    int my = (idx < NN) ? g_cnt[idx] : 0;
    s[t] = my;
    if (t == 0) {
        int run = 0;
        for (int i = 0; i < blockIdx.x; i++) run += g_bsum[i];
        boff = run;
    }
    __syncthreads();
    for (int off = 1; off < SCAN_CH; off <<= 1) {
        int u = 0;
        if (t >= off) u = s[t - off];
        __syncthreads();
        s[t] += u;
        __syncthreads();
    }
    if (idx < NN) {
        int rp = boff + (s[t] - my) + idx;       // +idx = self-loop slots
        g_rowptr[idx] = rp;
        float di = g_deg[idx];
        g_pair[rp] = make_int2(idx, __float_as_int(di * di));   // self-loop entry
        g_degcnt[idx] = 0ull;                    // re-zero for next call
    }
    if (idx == NN - 1) g_rowptr[NN] = EE + NN;   // known total
}

// ---- csr_fill: atomic-free (position = rowptr[d] + 1 + seq[e]) ----
__global__ void csr_fill_kernel(const int* __restrict__ ei,
                                const float* __restrict__ w) {
    int e = blockIdx.x * blockDim.x + threadIdx.x;
    if (e >= EE) return;
    int s = ei[e];
    int d = ei[EE + e];
    int pos = g_rowptr[d] + 1 + g_seq[e];
    float v = g_deg[s] * w[e] * g_deg[d];        // g_deg holds dinv
    g_pair[pos] = make_int2(s, __float_as_int(v));
}

// ---------------- fp16 tensor-core GEMM: Zh[M,128] = A[M,128] @ W[128,128] ----
#define GBM 128
#define LDH 136   // halves per smem row (272 B; conflict-free ldmatrix phases)
#define GEMM_SMEM (2 * GBM * LDH * (int)sizeof(__half))   // 69632

__device__ __forceinline__ uint32_t smem_u32(const void* p) {
    return (uint32_t)__cvta_generic_to_shared(p);
}

template <typename TA>
__global__ __launch_bounds__(256) void gemm_h16_kernel(const TA* __restrict__ A,
                                                       const __half* __restrict__ W,
                                                       __half* __restrict__ C, int M) {
    extern __shared__ __half smh[];
    __half* As = smh;                 // [128][LDH]
    __half* Bs = smh + GBM * LDH;     // [128][LDH]
    const int tid  = threadIdx.x;
    const int wid  = tid >> 5;
    const int lane = tid & 31;
    const int warp_m = wid & 3;
    const int warp_n = wid >> 2;
    const int m0 = blockIdx.x * GBM;

#pragma unroll
    for (int it = 0; it < 8; it++) {
        int idx = tid + it * 256;
        int row = idx >> 4;
        int hg  = (idx & 15) * 8;
        uint4 pk = make_uint4(0u, 0u, 0u, 0u);
        if (m0 + row < M) {
            const TA* src = A + (size_t)(m0 + row) * DD + hg;
            if (sizeof(TA) == 2) {
                pk = *reinterpret_cast<const uint4*>(src);
            } else {
                const float4 f0 = *reinterpret_cast<const float4*>((const float*)src);
                const float4 f1 = *reinterpret_cast<const float4*>((const float*)src + 4);
                __half2 h0 = __floats2half2_rn(f0.x, f0.y);
                __half2 h1 = __floats2half2_rn(f0.z, f0.w);
                __half2 h2 = __floats2half2_rn(f1.x, f1.y);
                __half2 h3 = __floats2half2_rn(f1.z, f1.w);
                pk.x = *reinterpret_cast<uint32_t*>(&h0);
                pk.y = *reinterpret_cast<uint32_t*>(&h1);
                pk.z = *reinterpret_cast<uint32_t*>(&h2);
                pk.w = *reinterpret_cast<uint32_t*>(&h3);
            }
        }
        *reinterpret_cast<uint4*>(&As[row * LDH + hg]) = pk;
    }
#pragma unroll
    for (int it = 0; it < 8; it++) {
        int idx = tid + it * 256;
        int row = idx >> 4;
        int hg  = (idx & 15) * 8;
        uint4 pk = *reinterpret_cast<const uint4*>(W + (size_t)row * DD + hg);
        *reinterpret_cast<uint4*>(&Bs[row * LDH + hg]) = pk;
    }
    __syncthreads();

    float acc[2][8][4];
#pragma unroll
    for (int mi = 0; mi < 2; mi++)
#pragma unroll
        for (int ni = 0; ni < 8; ni++)
#pragma unroll
            for (int q = 0; q < 4; q++) acc[mi][ni][q] = 0.0f;

#pragma unroll
    for (int ks = 0; ks < 8; ks++) {
        const int kk = ks * 16;
        uint32_t a[2][4], b[8][2];
#pragma unroll
        for (int mi = 0; mi < 2; mi++) {
            uint32_t addr = smem_u32(&As[(warp_m * 32 + mi * 16 + (lane & 15)) * LDH
                                         + kk + (lane >> 4) * 8]);
            asm volatile("ldmatrix.sync.aligned.m8n8.x4.shared.b16 {%0,%1,%2,%3}, [%4];"
                         : "=r"(a[mi][0]), "=r"(a[mi][1]), "=r"(a[mi][2]), "=r"(a[mi][3])
                         : "r"(addr));
        }
#pragma unroll
        for (int nb = 0; nb < 4; nb++) {
            uint32_t addr = smem_u32(&Bs[(kk + (lane & 15)) * LDH
                                         + warp_n * 64 + nb * 16 + (lane >> 4) * 8]);
            asm volatile("ldmatrix.sync.aligned.m8n8.x4.trans.shared.b16 {%0,%1,%2,%3}, [%4];"
                         : "=r"(b[nb * 2][0]), "=r"(b[nb * 2][1]),
                           "=r"(b[nb * 2 + 1][0]), "=r"(b[nb * 2 + 1][1])
                         : "r"(addr));
        }
#pragma unroll
        for (int mi = 0; mi < 2; mi++)
#pragma unroll
            for (int ni = 0; ni < 8; ni++) {
                asm volatile(
                    "mma.sync.aligned.m16n8k16.row.col.f32.f16.f16.f32 "
                    "{%0,%1,%2,%3}, {%4,%5,%6,%7}, {%8,%9}, {%0,%1,%2,%3};\n"
                    : "+f"(acc[mi][ni][0]), "+f"(acc[mi][ni][1]),
                      "+f"(acc[mi][ni][2]), "+f"(acc[mi][ni][3])
                    : "r"(a[mi][0]), "r"(a[mi][1]), "r"(a[mi][2]), "r"(a[mi][3]),
                      "r"(b[ni][0]), "r"(b[ni][1]));
            }
    }
    const int g   = lane >> 2;
    const int tig = lane & 3;
#pragma unroll
    for (int mi = 0; mi < 2; mi++) {
        int row0 = m0 + warp_m * 32 + mi * 16 + g;
#pragma unroll
        for (int ni = 0; ni < 8; ni++) {
            int col = warp_n * 64 + ni * 8 + tig * 2;
            if (row0 < M)
                *reinterpret_cast<__half2*>(C + (size_t)row0 * DD + col) =
                    __floats2half2_rn(acc[mi][ni][0], acc[mi][ni][1]);
            if (row0 + 8 < M)
                *reinterpret_cast<__half2*>(C + (size_t)(row0 + 8) * DD + col) =
                    __floats2half2_rn(acc[mi][ni][2], acc[mi][ni][3]);
        }
    }
}

// ---- warp-aggregate one node into a float4 (lane's 4-channel slice) ----------
__device__ __forceinline__ float4 warp_agg_node(const __half* __restrict__ Zl,
                                                int i, int end) {
    float4 acc = make_float4(0.f, 0.f, 0.f, 0.f);
    if ((i & 1) && i < end) {     // peel to even pair index for int4 loads
        int2 p = g_pair[i];
        float v = __int_as_float(p.y);
        const __half2* q = reinterpret_cast<const __half2*>(Zl + (size_t)p.x * DD);
        __half2 a = q[0], d = q[1];
        float2 f;
        f = __half22float2(a); acc.x = fmaf(v, f.x, acc.x); acc.y = fmaf(v, f.y, acc.y);
        f = __half22float2(d); acc.z = fmaf(v, f.x, acc.z); acc.w = fmaf(v, f.y, acc.w);
        i++;
    }
    for (; i + 8 <= end; i += 8) {
        int4 pA = *reinterpret_cast<const int4*>(&g_pair[i]);
        int4 pB = *reinterpret_cast<const int4*>(&g_pair[i + 2]);
        int4 pC = *reinterpret_cast<const int4*>(&g_pair[i + 4]);
        int4 pD = *reinterpret_cast<const int4*>(&g_pair[i + 6]);
        const __half2* q0 = reinterpret_cast<const __half2*>(Zl + (size_t)pA.x * DD);
        const __half2* q1 = reinterpret_cast<const __half2*>(Zl + (size_t)pA.z * DD);
        const __half2* q2 = reinterpret_cast<const __half2*>(Zl + (size_t)pB.x * DD);
        const __half2* q3 = reinterpret_cast<const __half2*>(Zl + (size_t)pB.z * DD);
        const __half2* q4 = reinterpret_cast<const __half2*>(Zl + (size_t)pC.x * DD);
        const __half2* q5 = reinterpret_cast<const __half2*>(Zl + (size_t)pC.z * DD);
        const __half2* q6 = reinterpret_cast<const __half2*>(Zl + (size_t)pD.x * DD);
        const __half2* q7 = reinterpret_cast<const __half2*>(Zl + (size_t)pD.z * DD);
        __half2 a0 = q0[0], b0 = q0[1];
        __half2 a1 = q1[0], b1 = q1[1];
        __half2 a2 = q2[0], b2 = q2[1];
        __half2 a3 = q3[0], b3 = q3[1];
        __half2 a4 = q4[0], b4 = q4[1];
        __half2 a5 = q5[0], b5 = q5[1];
        __half2 a6 = q6[0], b6 = q6[1];
        __half2 a7 = q7[0], b7 = q7[1];
        float v0 = __int_as_float(pA.y), v1 = __int_as_float(pA.w);
        float v2 = __int_as_float(pB.y), v3 = __int_as_float(pB.w);
        float v4 = __int_as_float(pC.y), v5 = __int_as_float(pC.w);
        float v6 = __int_as_float(pD.y), v7 = __int_as_float(pD.w);
        float2 f;
        f = __half22float2(a0); acc.x = fmaf(v0, f.x, acc.x); acc.y = fmaf(v0, f.y, acc.y);
        f = __half22float2(b0); acc.z = fmaf(v0, f.x, acc.z); acc.w = fmaf(v0, f.y, acc.w);
        f = __half22float2(a1); acc.x = fmaf(v1, f.x, acc.x); acc.y = fmaf(v1, f.y, acc.y);
        f = __half22float2(b1); acc.z = fmaf(v1, f.x, acc.z); acc.w = fmaf(v1, f.y, acc.w);
        f = __half22float2(a2); acc.x = fmaf(v2, f.x, acc.x); acc.y = fmaf(v2, f.y, acc.y);
        f = __half22float2(b2); acc.z = fmaf(v2, f.x, acc.z); acc.w = fmaf(v2, f.y, acc.w);
        f = __half22float2(a3); acc.x = fmaf(v3, f.x, acc.x); acc.y = fmaf(v3, f.y, acc.y);
        f = __half22float2(b3); acc.z = fmaf(v3, f.x, acc.z); acc.w = fmaf(v3, f.y, acc.w);
        f = __half22float2(a4); acc.x = fmaf(v4, f.x, acc.x); acc.y = fmaf(v4, f.y, acc.y);
        f = __half22float2(b4); acc.z = fmaf(v4, f.x, acc.z); acc.w = fmaf(v4, f.y, acc.w);
        f = __half22float2(a5); acc.x = fmaf(v5, f.x, acc.x); acc.y = fmaf(v5, f.y, acc.y);
        f = __half22float2(b5); acc.z = fmaf(v5, f.x, acc.z); acc.w = fmaf(v5, f.y, acc.w);
        f = __half22float2(a6); acc.x = fmaf(v6, f.x, acc.x); acc.y = fmaf(v6, f.y, acc.y);
        f = __half22float2(b6); acc.z = fmaf(v6, f.x, acc.z); acc.w = fmaf(v6, f.y, acc.w);
        f = __half22float2(a7); acc.x = fmaf(v7, f.x, acc.x); acc.y = fmaf(v7, f.y, acc.y);
        f = __half22float2(b7); acc.z = fmaf(v7, f.x, acc.z); acc.w = fmaf(v7, f.y, acc.w);
    }
    for (; i + 2 <= end; i += 2) {
        int4 pA = *reinterpret_cast<const int4*>(&g_pair[i]);
        float v0 = __int_as_float(pA.y), v1 = __int_as_float(pA.w);
        const __half2* q0 = reinterpret_cast<const __half2*>(Zl + (size_t)pA.x * DD);
        const __half2* q1 = reinterpret_cast<const __half2*>(Zl + (size_t)pA.z * DD);
        __half2 a0 = q0[0], b0 = q0[1];
        __half2 a1 = q1[0], b1 = q1[1];
        float2 f;
        f = __half22float2(a0); acc.x = fmaf(v0, f.x, acc.x); acc.y = fmaf(v0, f.y, acc.y);
        f = __half22float2(b0); acc.z = fmaf(v0, f.x, acc.z); acc.w = fmaf(v0, f.y, acc.w);
        f = __half22float2(a1); acc.x = fmaf(v1, f.x, acc.x); acc.y = fmaf(v1, f.y, acc.y);
        f = __half22float2(b1); acc.z = fmaf(v1, f.x, acc.z); acc.w = fmaf(v1, f.y, acc.w);
    }
    if (i < end) {
        int2 p = g_pair[i];
        float v = __int_as_float(p.y);
        const __half2* q = reinterpret_cast<const __half2*>(Zl + (size_t)p.x * DD);
        __half2 a = q[0], d = q[1];
        float2 f;
        f = __half22float2(a); acc.x = fmaf(v, f.x, acc.x); acc.y = fmaf(v, f.y, acc.y);
        f = __half22float2(d); acc.z = fmaf(v, f.x, acc.z); acc.w = fmaf(v, f.y, acc.w);
    }
    return acc;
}

// ---------------- sparse aggregation: H[n] = relu(sum val * Zh[col] + b) ------
__global__ __launch_bounds__(256) void agg_kernel(const __half* __restrict__ Z,
                                                  const float* __restrict__ b,
                                                  __half* __restrict__ out) {
    int warp = (blockIdx.x * blockDim.x + threadIdx.x) >> 5;
    if (warp >= NN) return;
    int lane = threadIdx.x & 31;
    float4 acc = warp_agg_node(Z + lane * 4, g_rowptr[warp], g_rowptr[warp + 1]);
    const float4 bb = *reinterpret_cast<const float4*>(b + lane * 4);
    acc.x = fmaxf(acc.x + bb.x, 0.f);
    acc.y = fmaxf(acc.y + bb.y, 0.f);
    acc.z = fmaxf(acc.z + bb.z, 0.f);
    acc.w = fmaxf(acc.w + bb.w, 0.f);
    __half2 lo = __floats2half2_rn(acc.x, acc.y);
    __half2 hi = __floats2half2_rn(acc.z, acc.w);
    uint2 pk;
    pk.x = *reinterpret_cast<uint32_t*>(&lo);
    pk.y = *reinterpret_cast<uint32_t*>(&hi);
    *reinterpret_cast<uint2*>(out + (size_t)warp * DD + lane * 4) = pk;
}

// ------- fused agg4 (no relu) + gemm5 (128->2): Z5[n] = (agg(Zh)[n]+b4) @ W5 --
__global__ __launch_bounds__(256) void agg_gemm5_kernel(const __half* __restrict__ Z,
                                                        const float* __restrict__ b4,
                                                        const float* __restrict__ W5,
                                                        float* __restrict__ Z5) {
    int warp = (blockIdx.x * blockDim.x + threadIdx.x) >> 5;
    if (warp >= NN) return;
    int lane = threadIdx.x & 31;
    float4 acc = warp_agg_node(Z + lane * 4, g_rowptr[warp], g_rowptr[warp + 1]);
    const float4 bb = *reinterpret_cast<const float4*>(b4 + lane * 4);
    acc.x += bb.x; acc.y += bb.y; acc.z += bb.z; acc.w += bb.w;
    const float4 w0 = *reinterpret_cast<const float4*>(W5 + lane * 8);
    const float4 w1 = *reinterpret_cast<const float4*>(W5 + lane * 8 + 4);
    float p0 = acc.x * w0.x + acc.y * w0.z + acc.z * w1.x + acc.w * w1.z;
    float p1 = acc.x * w0.y + acc.y * w0.w + acc.z * w1.y + acc.w * w1.w;
#pragma unroll
    for (int off = 16; off > 0; off >>= 1) {
        p0 += __shfl_down_sync(0xffffffffu, p0, off);
        p1 += __shfl_down_sync(0xffffffffu, p1, off);
    }
    if (lane == 0) {
        Z5[(size_t)warp * 2]     = p0;
        Z5[(size_t)warp * 2 + 1] = p1;
    }
}

// ---------------- final aggregation on 2-wide Z5 ------------------------------
__global__ __launch_bounds__(256) void agg5_kernel(const float* __restrict__ Z5,
                                                   const float* __restrict__ b5,
                                                   float* __restrict__ out) {
    int n = blockIdx.x * blockDim.x + threadIdx.x;
    if (n >= NN) return;
    float a0 = 0.f, a1 = 0.f;
    int i = g_rowptr[n];
    int end = g_rowptr[n + 1];
    for (; i < end; i++) {
        int2 p = g_pair[i];
        float v = __int_as_float(p.y);
        const float2 z = *reinterpret_cast<const float2*>(Z5 + (size_t)p.x * 2);
        a0 = fmaf(v, z.x, a0);
        a1 = fmaf(v, z.y, a1);
    }
    out[(size_t)n * 2]     = a0 + b5[0];
    out[(size_t)n * 2 + 1] = a1 + b5[1];
}

// ---------------- driver ----------------
extern "C" void kernel_launch(void* const* d_in, const int* in_sizes, int n_in,
                              void* d_out, int out_size) {
    const float* x  = (const float*)d_in[0];
    const int*   ei = (const int*)d_in[1];       // int32 (JAX default, x64 disabled)
    const float* ew = (const float*)d_in[2];
    const float* W1 = (const float*)d_in[3];  const float* b1 = (const float*)d_in[4];
    const float* W2 = (const float*)d_in[5];  const float* b2 = (const float*)d_in[6];
    const float* W3 = (const float*)d_in[7];  const float* b3 = (const float*)d_in[8];
    const float* W4 = (const float*)d_in[9];  const float* b4 = (const float*)d_in[10];
    const float* W5 = (const float*)d_in[11]; const float* b5 = (const float*)d_in[12];
    float* out = (float*)d_out;

    __half *Zh, *HA, *HB, *Wh; float *Z5;
    cudaGetSymbolAddress((void**)&Zh, g_Zh);
    cudaGetSymbolAddress((void**)&HA, g_HA);
    cudaGetSymbolAddress((void**)&HB, g_HB);
    cudaGetSymbolAddress((void**)&Wh, g_Wh);
    cudaGetSymbolAddress((void**)&Z5, g_Z5);

    cudaFuncSetAttribute(gemm_h16_kernel<float>,
                         cudaFuncAttributeMaxDynamicSharedMemorySize, GEMM_SMEM);
    cudaFuncSetAttribute(gemm_h16_kernel<__half>,
                         cudaFuncAttributeMaxDynamicSharedMemorySize, GEMM_SMEM);

    const int TB = 256;
    // graph preprocessing (4 launches; csr_fill is the 4th -> ncu target)
    deg_cnt_kernel<<<(EE + TB - 1) / TB, TB>>>(ei, ew);
    scanA_dinv_convW_kernel<<<SCAN_NB + CONVW_NB, SCAN_CH>>>(W1, W2, W3, W4);
    scanC_kernel<<<SCAN_NB, SCAN_CH>>>();
    csr_fill_kernel<<<(EE + TB - 1) / TB, TB>>>(ei, ew);

    const int gemm_blocks = (NN + GBM - 1) / GBM;
    const int agg_blocks  = (int)(((size_t)NN * 32 + TB - 1) / TB);

    // layer 1 (A = x fp32, converted in-kernel)
    gemm_h16_kernel<float><<<gemm_blocks, 256, GEMM_SMEM>>>(x, Wh, Zh, NN);
    agg_kernel<<<agg_blocks, TB>>>(Zh, b1, HA);
    // layer 2
    gemm_h16_kernel<__half><<<gemm_blocks, 256, GEMM_SMEM>>>(HA, Wh + DD * DD, Zh, NN);
    agg_kernel<<<agg_blocks, TB>>>(Zh, b2, HB);
    // layer 3
    gemm_h16_kernel<__half><<<gemm_blocks, 256, GEMM_SMEM>>>(HB, Wh + 2 * DD * DD, Zh, NN);
    agg_kernel<<<agg_blocks, TB>>>(Zh, b3, HA);
    // layer 4 gemm, then fused agg4+gemm5
    gemm_h16_kernel<__half><<<gemm_blocks, 256, GEMM_SMEM>>>(HA, Wh + 3 * DD * DD, Zh, NN);
    agg_gemm5_kernel<<<agg_blocks, TB>>>(Zh, b4, W5, Z5);
    // final 2-wide aggregation
    agg5_kernel<<<(NN + TB - 1) / TB, TB>>>(Z5, b5, out);
}

// round 14
// speedup vs baseline: 1.9458x; 1.0724x over previous
#include <cuda_runtime.h>
#include <cuda_fp16.h>
#include <stdint.h>

#define NN 100000
#define EE 1600000
#define DD 128

#define SCAN_CH  1024
#define SCAN_NB  ((NN + SCAN_CH - 1) / SCAN_CH)   // 98
#define CONVW_NB 16                                // extra scanA blocks for W conversion

// ---------------- scratch (static __device__, no allocation) ----------------
__device__ unsigned long long g_degcnt[NN];  // packed {cnt[52:64), wsum_q32[0:52)}; zeroed by scanC
__device__ float  g_deg[NN];                 // dinv (pure scanA output)
__device__ int    g_cnt[NN];                 // decoded counts (scanA -> scanC)
__device__ int    g_seq[EE];                 // per-edge slot within dst row
__device__ int    g_rowptr[NN + 1];
__device__ int    g_bsum[SCAN_NB];
__device__ __align__(16) int2 g_pair[EE + NN];   // packed {col, w_bits}  (no dinv!)
__device__ __half g_Wh[4 * DD * DD];    // fp16-converted W1..W4
__device__ __half g_Zh[NN * DD];        // post-GEMM features, PRE-SCALED by dinv[row]
__device__ __half g_HA[NN * DD];        // post-agg features, fp16
__device__ __half g_HB[NN * DD];
__device__ float  g_Z5[NN * 2];         // layer-5 logits, PRE-SCALED by dinv[row]

// ---------------- graph preprocessing ----------------
// g_degcnt is zero at entry (module load first call; scanC re-zeroes after).
__global__ void deg_cnt_kernel(const int* __restrict__ ei,
                               const float* __restrict__ w) {
    int e = blockIdx.x * blockDim.x + threadIdx.x;
    if (e >= EE) return;
    int d = ei[EE + e];
    unsigned long long wq = (unsigned long long)((double)w[e] * 4294967296.0);
    unsigned long long old = atomicAdd(&g_degcnt[d], (1ull << 52) | wq);
    g_seq[e] = (int)(old >> 52);
}

// ---- scanA: decode degcnt -> per-block sums + dinv; extra blocks convert W ----
__global__ __launch_bounds__(SCAN_CH) void scanA_dinv_convW_kernel(
    const float* __restrict__ W1, const float* __restrict__ W2,
    const float* __restrict__ W3, const float* __restrict__ W4) {
    int t = threadIdx.x;
    if (blockIdx.x >= SCAN_NB) {
        int idx = (blockIdx.x - SCAN_NB) * SCAN_CH + t;
        int which = idx >> 12;
        int off   = (idx & 4095) * 4;
        const float* W = (which == 0) ? W1 : (which == 1) ? W2 : (which == 2) ? W3 : W4;
        float4 f = *reinterpret_cast<const float4*>(W + off);
        __half2 h0 = __floats2half2_rn(f.x, f.y);
        __half2 h1 = __floats2half2_rn(f.z, f.w);
        uint2 pk;
        pk.x = *reinterpret_cast<uint32_t*>(&h0);
        pk.y = *reinterpret_cast<uint32_t*>(&h1);
        *reinterpret_cast<uint2*>(&g_Wh[which * DD * DD + off]) = pk;
        return;
    }
    __shared__ int s[SCAN_CH];
    int idx = blockIdx.x * SCAN_CH + t;
    int c = 0;
    if (idx < NN) {
        unsigned long long dc = g_degcnt[idx];
        c = (int)(dc >> 52);
        float wsum = (float)((double)(dc & ((1ull << 52) - 1ull)) * (1.0 / 4294967296.0));
        g_deg[idx] = rsqrtf(wsum + 1.0f);   // +1 = self-loop weight
        g_cnt[idx] = c;
    }
    s[t] = c;
    __syncthreads();
    for (int off = SCAN_CH >> 1; off > 0; off >>= 1) {
        if (t < off) s[t] += s[t + off];
        __syncthreads();
    }
    if (t == 0) g_bsum[blockIdx.x] = s[0];
}

// ---- scanC: rowptr (incl. self-loops), self-loop pair (w=1), re-zero degcnt --
__global__ __launch_bounds__(SCAN_CH) void scanC_kernel() {
    __shared__ int s[SCAN_CH];
    __shared__ int boff;
    int t = threadIdx.x;
    int idx = blockIdx.x * SCAN_CH + t;
    int my = (idx < NN) ? g_cnt[idx] : 0;
    s[t] = my;
    if (t == 0) {
        int run = 0;
        for (int i = 0; i < blockIdx.x; i++) run += g_bsum[i];
        boff = run;
    }
    __syncthreads();
    for (int off = 1; off < SCAN_CH; off <<= 1) {
        int u = 0;
        if (t >= off) u = s[t - off];
        __syncthreads();
        s[t] += u;
        __syncthreads();
    }
    if (idx < NN) {
        int rp = boff + (s[t] - my) + idx;       // +idx = self-loop slots
        g_rowptr[idx] = rp;
        g_pair[rp] = make_int2(idx, __float_as_int(1.0f));   // self-loop weight 1
        g_degcnt[idx] = 0ull;                    // re-zero for next call
    }
    if (idx == NN - 1) g_rowptr[NN] = EE + NN;   // known total
}

// ---- csr_fill: atomic-free AND dinv-free (pure streams + 8B scatter) ----
__global__ void csr_fill_kernel(const int* __restrict__ ei,
                                const float* __restrict__ w) {
    int e = blockIdx.x * blockDim.x + threadIdx.x;
    if (e >= EE) return;
    int s = ei[e];
    int d = ei[EE + e];
    int pos = g_rowptr[d] + 1 + g_seq[e];
    g_pair[pos] = make_int2(s, __float_as_int(w[e]));
}

// ---------------- fp16 tensor-core GEMM: Zh[M,128] = dinv[m]*(A[M,128]@W) ----
#define GBM 128
#define LDH 136   // halves per smem row (272 B; conflict-free ldmatrix phases)
#define GEMM_SMEM (2 * GBM * LDH * (int)sizeof(__half))   // 69632

__device__ __forceinline__ uint32_t smem_u32(const void* p) {
    return (uint32_t)__cvta_generic_to_shared(p);
}

template <typename TA>
__global__ __launch_bounds__(256) void gemm_h16_kernel(const TA* __restrict__ A,
                                                       const __half* __restrict__ W,
                                                       __half* __restrict__ C, int M) {
    extern __shared__ __half smh[];
    __half* As = smh;                 // [128][LDH]
    __half* Bs = smh + GBM * LDH;     // [128][LDH]
    const int tid  = threadIdx.x;
    const int wid  = tid >> 5;
    const int lane = tid & 31;
    const int warp_m = wid & 3;
    const int warp_n = wid >> 2;
    const int m0 = blockIdx.x * GBM;

#pragma unroll
    for (int it = 0; it < 8; it++) {
        int idx = tid + it * 256;
        int row = idx >> 4;
        int hg  = (idx & 15) * 8;
        uint4 pk = make_uint4(0u, 0u, 0u, 0u);
        if (m0 + row < M) {
            const TA* src = A + (size_t)(m0 + row) * DD + hg;
            if (sizeof(TA) == 2) {
                pk = *reinterpret_cast<const uint4*>(src);
            } else {
                const float4 f0 = *reinterpret_cast<const float4*>((const float*)src);
                const float4 f1 = *reinterpret_cast<const float4*>((const float*)src + 4);
                __half2 h0 = __floats2half2_rn(f0.x, f0.y);
                __half2 h1 = __floats2half2_rn(f0.z, f0.w);
                __half2 h2 = __floats2half2_rn(f1.x, f1.y);
                __half2 h3 = __floats2half2_rn(f1.z, f1.w);
                pk.x = *reinterpret_cast<uint32_t*>(&h0);
                pk.y = *reinterpret_cast<uint32_t*>(&h1);
                pk.z = *reinterpret_cast<uint32_t*>(&h2);
                pk.w = *reinterpret_cast<uint32_t*>(&h3);
            }
        }
        *reinterpret_cast<uint4*>(&As[row * LDH + hg]) = pk;
    }
#pragma unroll
    for (int it = 0; it < 8; it++) {
        int idx = tid + it * 256;
        int row = idx >> 4;
        int hg  = (idx & 15) * 8;
        uint4 pk = *reinterpret_cast<const uint4*>(W + (size_t)row * DD + hg);
        *reinterpret_cast<uint4*>(&Bs[row * LDH + hg]) = pk;
    }
    __syncthreads();

    float acc[2][8][4];
#pragma unroll
    for (int mi = 0; mi < 2; mi++)
#pragma unroll
        for (int ni = 0; ni < 8; ni++)
#pragma unroll
            for (int q = 0; q < 4; q++) acc[mi][ni][q] = 0.0f;

#pragma unroll
    for (int ks = 0; ks < 8; ks++) {
        const int kk = ks * 16;
        uint32_t a[2][4], b[8][2];
#pragma unroll
        for (int mi = 0; mi < 2; mi++) {
            uint32_t addr = smem_u32(&As[(warp_m * 32 + mi * 16 + (lane & 15)) * LDH
                                         + kk + (lane >> 4) * 8]);
            asm volatile("ldmatrix.sync.aligned.m8n8.x4.shared.b16 {%0,%1,%2,%3}, [%4];"
                         : "=r"(a[mi][0]), "=r"(a[mi][1]), "=r"(a[mi][2]), "=r"(a[mi][3])
                         : "r"(addr));
        }
#pragma unroll
        for (int nb = 0; nb < 4; nb++) {
            uint32_t addr = smem_u32(&Bs[(kk + (lane & 15)) * LDH
                                         + warp_n * 64 + nb * 16 + (lane >> 4) * 8]);
            asm volatile("ldmatrix.sync.aligned.m8n8.x4.trans.shared.b16 {%0,%1,%2,%3}, [%4];"
                         : "=r"(b[nb * 2][0]), "=r"(b[nb * 2][1]),
                           "=r"(b[nb * 2 + 1][0]), "=r"(b[nb * 2 + 1][1])
                         : "r"(addr));
        }
#pragma unroll
        for (int mi = 0; mi < 2; mi++)
#pragma unroll
            for (int ni = 0; ni < 8; ni++) {
                asm volatile(
                    "mma.sync.aligned.m16n8k16.row.col.f32.f16.f16.f32 "
                    "{%0,%1,%2,%3}, {%4,%5,%6,%7}, {%8,%9}, {%0,%1,%2,%3};\n"
                    : "+f"(acc[mi][ni][0]), "+f"(acc[mi][ni][1]),
                      "+f"(acc[mi][ni][2]), "+f"(acc[mi][ni][3])
                    : "r"(a[mi][0]), "r"(a[mi][1]), "r"(a[mi][2]), "r"(a[mi][3]),
                      "r"(b[ni][0]), "r"(b[ni][1]));
            }
    }
    // epilogue: scale by dinv[row], convert to fp16
    const int g   = lane >> 2;
    const int tig = lane & 3;
#pragma unroll
    for (int mi = 0; mi < 2; mi++) {
        int row0 = m0 + warp_m * 32 + mi * 16 + g;
        float dv0 = (row0 < M)     ? g_deg[row0]     : 0.0f;
        float dv1 = (row0 + 8 < M) ? g_deg[row0 + 8] : 0.0f;
#pragma unroll
        for (int ni = 0; ni < 8; ni++) {
            int col = warp_n * 64 + ni * 8 + tig * 2;
            if (row0 < M)
                *reinterpret_cast<__half2*>(C + (size_t)row0 * DD + col) =
                    __floats2half2_rn(acc[mi][ni][0] * dv0, acc[mi][ni][1] * dv0);
            if (row0 + 8 < M)
                *reinterpret_cast<__half2*>(C + (size_t)(row0 + 8) * DD + col) =
                    __floats2half2_rn(acc[mi][ni][2] * dv1, acc[mi][ni][3] * dv1);
        }
    }
}

// ---- warp-aggregate one node into a float4 (lane's 4-channel slice) ----------
__device__ __forceinline__ float4 warp_agg_node(const __half* __restrict__ Zl,
                                                int i, int end) {
    float4 acc = make_float4(0.f, 0.f, 0.f, 0.f);
    if ((i & 1) && i < end) {     // peel to even pair index for int4 loads
        int2 p = g_pair[i];
        float v = __int_as_float(p.y);
        const __half2* q = reinterpret_cast<const __half2*>(Zl + (size_t)p.x * DD);
        __half2 a = q[0], d = q[1];
        float2 f;
        f = __half22float2(a); acc.x = fmaf(v, f.x, acc.x); acc.y = fmaf(v, f.y, acc.y);
        f = __half22float2(d); acc.z = fmaf(v, f.x, acc.z); acc.w = fmaf(v, f.y, acc.w);
        i++;
    }
    for (; i + 8 <= end; i += 8) {
        int4 pA = *reinterpret_cast<const int4*>(&g_pair[i]);
        int4 pB = *reinterpret_cast<const int4*>(&g_pair[i + 2]);
        int4 pC = *reinterpret_cast<const int4*>(&g_pair[i + 4]);
        int4 pD = *reinterpret_cast<const int4*>(&g_pair[i + 6]);
        const __half2* q0 = reinterpret_cast<const __half2*>(Zl + (size_t)pA.x * DD);
        const __half2* q1 = reinterpret_cast<const __half2*>(Zl + (size_t)pA.z * DD);
        const __half2* q2 = reinterpret_cast<const __half2*>(Zl + (size_t)pB.x * DD);
        const __half2* q3 = reinterpret_cast<const __half2*>(Zl + (size_t)pB.z * DD);
        const __half2* q4 = reinterpret_cast<const __half2*>(Zl + (size_t)pC.x * DD);
        const __half2* q5 = reinterpret_cast<const __half2*>(Zl + (size_t)pC.z * DD);
        const __half2* q6 = reinterpret_cast<const __half2*>(Zl + (size_t)pD.x * DD);
        const __half2* q7 = reinterpret_cast<const __half2*>(Zl + (size_t)pD.z * DD);
        __half2 a0 = q0[0], b0 = q0[1];
        __half2 a1 = q1[0], b1 = q1[1];
        __half2 a2 = q2[0], b2 = q2[1];
        __half2 a3 = q3[0], b3 = q3[1];
        __half2 a4 = q4[0], b4 = q4[1];
        __half2 a5 = q5[0], b5 = q5[1];
        __half2 a6 = q6[0], b6 = q6[1];
        __half2 a7 = q7[0], b7 = q7[1];
        float v0 = __int_as_float(pA.y), v1 = __int_as_float(pA.w);
        float v2 = __int_as_float(pB.y), v3 = __int_as_float(pB.w);
        float v4 = __int_as_float(pC.y), v5 = __int_as_float(pC.w);
        float v6 = __int_as_float(pD.y), v7 = __int_as_float(pD.w);
        float2 f;
        f = __half22float2(a0); acc.x = fmaf(v0, f.x, acc.x); acc.y = fmaf(v0, f.y, acc.y);
        f = __half22float2(b0); acc.z = fmaf(v0, f.x, acc.z); acc.w = fmaf(v0, f.y, acc.w);
        f = __half22float2(a1); acc.x = fmaf(v1, f.x, acc.x); acc.y = fmaf(v1, f.y, acc.y);
        f = __half22float2(b1); acc.z = fmaf(v1, f.x, acc.z); acc.w = fmaf(v1, f.y, acc.w);
        f = __half22float2(a2); acc.x = fmaf(v2, f.x, acc.x); acc.y = fmaf(v2, f.y, acc.y);
        f = __half22float2(b2); acc.z = fmaf(v2, f.x, acc.z); acc.w = fmaf(v2, f.y, acc.w);
        f = __half22float2(a3); acc.x = fmaf(v3, f.x, acc.x); acc.y = fmaf(v3, f.y, acc.y);
        f = __half22float2(b3); acc.z = fmaf(v3, f.x, acc.z); acc.w = fmaf(v3, f.y, acc.w);
        f = __half22float2(a4); acc.x = fmaf(v4, f.x, acc.x); acc.y = fmaf(v4, f.y, acc.y);
        f = __half22float2(b4); acc.z = fmaf(v4, f.x, acc.z); acc.w = fmaf(v4, f.y, acc.w);
        f = __half22float2(a5); acc.x = fmaf(v5, f.x, acc.x); acc.y = fmaf(v5, f.y, acc.y);
        f = __half22float2(b5); acc.z = fmaf(v5, f.x, acc.z); acc.w = fmaf(v5, f.y, acc.w);
        f = __half22float2(a6); acc.x = fmaf(v6, f.x, acc.x); acc.y = fmaf(v6, f.y, acc.y);
        f = __half22float2(b6); acc.z = fmaf(v6, f.x, acc.z); acc.w = fmaf(v6, f.y, acc.w);
        f = __half22float2(a7); acc.x = fmaf(v7, f.x, acc.x); acc.y = fmaf(v7, f.y, acc.y);
        f = __half22float2(b7); acc.z = fmaf(v7, f.x, acc.z); acc.w = fmaf(v7, f.y, acc.w);
    }
    for (; i + 2 <= end; i += 2) {
        int4 pA = *reinterpret_cast<const int4*>(&g_pair[i]);
        float v0 = __int_as_float(pA.y), v1 = __int_as_float(pA.w);
        const __half2* q0 = reinterpret_cast<const __half2*>(Zl + (size_t)pA.x * DD);
        const __half2* q1 = reinterpret_cast<const __half2*>(Zl + (size_t)pA.z * DD);
        __half2 a0 = q0[0], b0 = q0[1];
        __half2 a1 = q1[0], b1 = q1[1];
        float2 f;
        f = __half22float2(a0); acc.x = fmaf(v0, f.x, acc.x); acc.y = fmaf(v0, f.y, acc.y);
        f = __half22float2(b0); acc.z = fmaf(v0, f.x, acc.z); acc.w = fmaf(v0, f.y, acc.w);
        f = __half22float2(a1); acc.x = fmaf(v1, f.x, acc.x); acc.y = fmaf(v1, f.y, acc.y);
        f = __half22float2(b1); acc.z = fmaf(v1, f.x, acc.z); acc.w = fmaf(v1, f.y, acc.w);
    }
    if (i < end) {
        int2 p = g_pair[i];
        float v = __int_as_float(p.y);
        const __half2* q = reinterpret_cast<const __half2*>(Zl + (size_t)p.x * DD);
        __half2 a = q[0], d = q[1];
        float2 f;
        f = __half22float2(a); acc.x = fmaf(v, f.x, acc.x); acc.y = fmaf(v, f.y, acc.y);
        f = __half22float2(d); acc.z = fmaf(v, f.x, acc.z); acc.w = fmaf(v, f.y, acc.w);
    }
    return acc;
}

// ------------- sparse aggregation: H[n] = relu(dinv[n]*sum + b) --------------
__global__ __launch_bounds__(256) void agg_kernel(const __half* __restrict__ Z,
                                                  const float* __restrict__ b,
                                                  __half* __restrict__ out) {
    int warp = (blockIdx.x * blockDim.x + threadIdx.x) >> 5;
    if (warp >= NN) return;
    int lane = threadIdx.x & 31;
    float dv = g_deg[warp];
    float4 acc = warp_agg_node(Z + lane * 4, g_rowptr[warp], g_rowptr[warp + 1]);
    const float4 bb = *reinterpret_cast<const float4*>(b + lane * 4);
    acc.x = fmaxf(fmaf(dv, acc.x, bb.x), 0.f);
    acc.y = fmaxf(fmaf(dv, acc.y, bb.y), 0.f);
    acc.z = fmaxf(fmaf(dv, acc.z, bb.z), 0.f);
    acc.w = fmaxf(fmaf(dv, acc.w, bb.w), 0.f);
    __half2 lo = __floats2half2_rn(acc.x, acc.y);
    __half2 hi = __floats2half2_rn(acc.z, acc.w);
    uint2 pk;
    pk.x = *reinterpret_cast<uint32_t*>(&lo);
    pk.y = *reinterpret_cast<uint32_t*>(&hi);
    *reinterpret_cast<uint2*>(out + (size_t)warp * DD + lane * 4) = pk;
}

// -- fused agg4 + gemm5: Z5s[n] = dinv[n] * ((dinv[n]*sum + b4) @ W5) ---------
__global__ __launch_bounds__(256) void agg_gemm5_kernel(const __half* __restrict__ Z,
                                                        const float* __restrict__ b4,
                                                        const float* __restrict__ W5,
                                                        float* __restrict__ Z5) {
    int warp = (blockIdx.x * blockDim.x + threadIdx.x) >> 5;
    if (warp >= NN) return;
    int lane = threadIdx.x & 31;
    float dv = g_deg[warp];
    float4 acc = warp_agg_node(Z + lane * 4, g_rowptr[warp], g_rowptr[warp + 1]);
    const float4 bb = *reinterpret_cast<const float4*>(b4 + lane * 4);
    acc.x = fmaf(dv, acc.x, bb.x);
    acc.y = fmaf(dv, acc.y, bb.y);
    acc.z = fmaf(dv, acc.z, bb.z);
    acc.w = fmaf(dv, acc.w, bb.w);
    const float4 w0 = *reinterpret_cast<const float4*>(W5 + lane * 8);
    const float4 w1 = *reinterpret_cast<const float4*>(W5 + lane * 8 + 4);
    float p0 = acc.x * w0.x + acc.y * w0.z + acc.z * w1.x + acc.w * w1.z;
    float p1 = acc.x * w0.y + acc.y * w0.w + acc.z * w1.y + acc.w * w1.w;
#pragma unroll
    for (int off = 16; off > 0; off >>= 1) {
        p0 += __shfl_down_sync(0xffffffffu, p0, off);
        p1 += __shfl_down_sync(0xffffffffu, p1, off);
    }
    if (lane == 0) {
        Z5[(size_t)warp * 2]     = p0 * dv;   // pre-scale for final aggregation
        Z5[(size_t)warp * 2 + 1] = p1 * dv;
    }
}

// -------- final aggregation: out[n] = dinv[n] * sum w*Z5s[src] + b5 ----------
__global__ __launch_bounds__(256) void agg5_kernel(const float* __restrict__ Z5,
                                                   const float* __restrict__ b5,
                                                   float* __restrict__ out) {
    int n = blockIdx.x * blockDim.x + threadIdx.x;
    if (n >= NN) return;
    float a0 = 0.f, a1 = 0.f;
    int i = g_rowptr[n];
    int end = g_rowptr[n + 1];
    for (; i < end; i++) {
        int2 p = g_pair[i];
        float v = __int_as_float(p.y);
        const float2 z = *reinterpret_cast<const float2*>(Z5 + (size_t)p.x * 2);
        a0 = fmaf(v, z.x, a0);
        a1 = fmaf(v, z.y, a1);
    }
    float dv = g_deg[n];
    out[(size_t)n * 2]     = fmaf(dv, a0, b5[0]);
    out[(size_t)n * 2 + 1] = fmaf(dv, a1, b5[1]);
}

// ---------------- driver ----------------
extern "C" void kernel_launch(void* const* d_in, const int* in_sizes, int n_in,
                              void* d_out, int out_size) {
    const float* x  = (const float*)d_in[0];
    const int*   ei = (const int*)d_in[1];       // int32 (JAX default, x64 disabled)
    const float* ew = (const float*)d_in[2];
    const float* W1 = (const float*)d_in[3];  const float* b1 = (const float*)d_in[4];
    const float* W2 = (const float*)d_in[5];  const float* b2 = (const float*)d_in[6];
    const float* W3 = (const float*)d_in[7];  const float* b3 = (const float*)d_in[8];
    const float* W4 = (const float*)d_in[9];  const float* b4 = (const float*)d_in[10];
    const float* W5 = (const float*)d_in[11]; const float* b5 = (const float*)d_in[12];
    float* out = (float*)d_out;

    __half *Zh, *HA, *HB, *Wh; float *Z5;
    cudaGetSymbolAddress((void**)&Zh, g_Zh);
    cudaGetSymbolAddress((void**)&HA, g_HA);
    cudaGetSymbolAddress((void**)&HB, g_HB);
    cudaGetSymbolAddress((void**)&Wh, g_Wh);
    cudaGetSymbolAddress((void**)&Z5, g_Z5);

    cudaFuncSetAttribute(gemm_h16_kernel<float>,
                         cudaFuncAttributeMaxDynamicSharedMemorySize, GEMM_SMEM);
    cudaFuncSetAttribute(gemm_h16_kernel<__half>,
                         cudaFuncAttributeMaxDynamicSharedMemorySize, GEMM_SMEM);

    const int TB = 256;
    // graph preprocessing (4 launches; csr_fill is the 4th -> ncu target)
    deg_cnt_kernel<<<(EE + TB - 1) / TB, TB>>>(ei, ew);
    scanA_dinv_convW_kernel<<<SCAN_NB + CONVW_NB, SCAN_CH>>>(W1, W2, W3, W4);
    scanC_kernel<<<SCAN_NB, SCAN_CH>>>();
    csr_fill_kernel<<<(EE + TB - 1) / TB, TB>>>(ei, ew);

    const int gemm_blocks = (NN + GBM - 1) / GBM;
    const int agg_blocks  = (int)(((size_t)NN * 32 + TB - 1) / TB);

    // layer 1 (A = x fp32, converted in-kernel)
    gemm_h16_kernel<float><<<gemm_blocks, 256, GEMM_SMEM>>>(x, Wh, Zh, NN);
    agg_kernel<<<agg_blocks, TB>>>(Zh, b1, HA);
    // layer 2
    gemm_h16_kernel<__half><<<gemm_blocks, 256, GEMM_SMEM>>>(HA, Wh + DD * DD, Zh, NN);
    agg_kernel<<<agg_blocks, TB>>>(Zh, b2, HB);
    // layer 3
    gemm_h16_kernel<__half><<<gemm_blocks, 256, GEMM_SMEM>>>(HB, Wh + 2 * DD * DD, Zh, NN);
    agg_kernel<<<agg_blocks, TB>>>(Zh, b3, HA);
    // layer 4 gemm, then fused agg4+gemm5
    gemm_h16_kernel<__half><<<gemm_blocks, 256, GEMM_SMEM>>>(HA, Wh + 3 * DD * DD, Zh, NN);
    agg_gemm5_kernel<<<agg_blocks, TB>>>(Zh, b4, W5, Z5);
    // final 2-wide aggregation
    agg5_kernel<<<(NN + TB - 1) / TB, TB>>>(Z5, b5, out);
}

// round 16
// speedup vs baseline: 1.9480x; 1.0011x over previous
#include <cuda_runtime.h>
#include <cuda_fp16.h>
#include <stdint.h>

#define NN 100000
#define EE 1600000
#define DD 128

#define SCAN_CH  1024
#define SCAN_NB  ((NN + SCAN_CH - 1) / SCAN_CH)   // 98

// ---------------- scratch (static __device__, no allocation) ----------------
__device__ unsigned long long g_degcnt[NN];  // packed {cnt[52:64), wsum_q32[0:52)}; zeroed by scanC
__device__ float  g_deg[NN];                 // dinv (pure scanA output)
__device__ int    g_cnt[NN];                 // decoded counts (scanA -> scanC)
__device__ int    g_seq[EE];                 // per-edge slot within dst row
__device__ int    g_rowptr[NN + 1];
__device__ int    g_bsum[SCAN_NB];
__device__ __align__(16) int2 g_pair[EE + NN];   // packed {col, w_bits}  (no dinv)
__device__ __half g_Wh[4 * DD * DD];    // fp16-converted W1..W4
__device__ __half g_Zh[NN * DD];        // post-GEMM features, PRE-SCALED by dinv[row]
__device__ __half g_HA[NN * DD];        // post-agg features, fp16
__device__ __half g_HB[NN * DD];
__device__ float  g_Z5[NN * 2];         // layer-5 logits, PRE-SCALED by dinv[row]

// ---------------- graph preprocessing ----------------
// g_degcnt is zero at entry (module load first call; scanC re-zeroes after).
__global__ void deg_cnt_kernel(const int* __restrict__ ei,
                               const float* __restrict__ w) {
    int e = blockIdx.x * blockDim.x + threadIdx.x;
    if (e >= EE) return;
    int d = ei[EE + e];
    unsigned long long wq = (unsigned long long)((double)w[e] * 4294967296.0);
    unsigned long long old = atomicAdd(&g_degcnt[d], (1ull << 52) | wq);
    g_seq[e] = (int)(old >> 52);
}

// ---- scanA: decode degcnt -> per-block sums + dinv ----
__global__ __launch_bounds__(SCAN_CH) void scanA_dinv_kernel() {
    __shared__ int s[SCAN_CH];
    int t = threadIdx.x;
    int idx = blockIdx.x * SCAN_CH + t;
    int c = 0;
    if (idx < NN) {
        unsigned long long dc = g_degcnt[idx];
        c = (int)(dc >> 52);
        float wsum = (float)((double)(dc & ((1ull << 52) - 1ull)) * (1.0 / 4294967296.0));
        g_deg[idx] = rsqrtf(wsum + 1.0f);   // +1 = self-loop weight
        g_cnt[idx] = c;
    }
    s[t] = c;
    __syncthreads();
    for (int off = SCAN_CH >> 1; off > 0; off >>= 1) {
        if (t < off) s[t] += s[t + off];
        __syncthreads();
    }
    if (t == 0) g_bsum[blockIdx.x] = s[0];
}

// ---- scanC: rowptr (incl. self-loops), self-loop pair (w=1), re-zero degcnt --
// Block offset computed by a parallel smem scan of the 98 block sums.
__global__ __launch_bounds__(SCAN_CH) void scanC_kernel() {
    __shared__ int s[SCAN_CH];
    __shared__ int bpre[SCAN_NB];
    int t = threadIdx.x;
    int idx = blockIdx.x * SCAN_CH + t;
    int my = (idx < NN) ? g_cnt[idx] : 0;
    s[t] = my;
    if (t < SCAN_NB) bpre[t] = g_bsum[t];
    __syncthreads();
    // inclusive scan of bpre (98 elements, Hillis-Steele)
    for (int off = 1; off < SCAN_NB; off <<= 1) {
        int u = 0;
        if (t >= off && t < SCAN_NB) u = bpre[t - off];
        __syncthreads();
        if (t < SCAN_NB) bpre[t] += u;
        __syncthreads();
    }
    // node scan
    for (int off = 1; off < SCAN_CH; off <<= 1) {
        int u = 0;
        if (t >= off) u = s[t - off];
        __syncthreads();
        s[t] += u;
        __syncthreads();
    }
    int boff = (blockIdx.x == 0) ? 0 : bpre[blockIdx.x - 1];
    if (idx < NN) {
        int rp = boff + (s[t] - my) + idx;       // +idx = self-loop slots
        g_rowptr[idx] = rp;
        g_pair[rp] = make_int2(idx, __float_as_int(1.0f));   // self-loop weight 1
        g_degcnt[idx] = 0ull;                    // re-zero for next call
    }
    if (idx == NN - 1) g_rowptr[NN] = EE + NN;   // known total
}

// ---- csr_fill: atomic-free AND dinv-free (pure streams + 8B scatter) ----
__global__ void csr_fill_kernel(const int* __restrict__ ei,
                                const float* __restrict__ w) {
    int e = blockIdx.x * blockDim.x + threadIdx.x;
    if (e >= EE) return;
    int s = ei[e];
    int d = ei[EE + e];
    int pos = g_rowptr[d] + 1 + g_seq[e];
    g_pair[pos] = make_int2(s, __float_as_int(w[e]));
}

// ---- pre-convert W1..W4 (fp32 [128][128]) to fp16 ----
__global__ __launch_bounds__(256) void convW_kernel(const float* __restrict__ W1,
                                                    const float* __restrict__ W2,
                                                    const float* __restrict__ W3,
                                                    const float* __restrict__ W4) {
    int idx = blockIdx.x * blockDim.x + threadIdx.x;   // 0..16383 (x4 floats)
    int which = idx >> 12;
    int off   = (idx & 4095) * 4;
    const float* W = (which == 0) ? W1 : (which == 1) ? W2 : (which == 2) ? W3 : W4;
    float4 f = *reinterpret_cast<const float4*>(W + off);
    __half2 h0 = __floats2half2_rn(f.x, f.y);
    __half2 h1 = __floats2half2_rn(f.z, f.w);
    uint2 pk;
    pk.x = *reinterpret_cast<uint32_t*>(&h0);
    pk.y = *reinterpret_cast<uint32_t*>(&h1);
    *reinterpret_cast<uint2*>(&g_Wh[which * DD * DD + off]) = pk;
}

// ---------------- fp16 tensor-core GEMM: Zh[M,128] = dinv[m]*(A[M,128]@W) ----
#define GBM 128
#define LDH 136   // halves per smem row (272 B; conflict-free ldmatrix phases)
#define GEMM_SMEM (2 * GBM * LDH * (int)sizeof(__half))   // 69632

__device__ __forceinline__ uint32_t smem_u32(const void* p) {
    return (uint32_t)__cvta_generic_to_shared(p);
}

template <typename TA>
__global__ __launch_bounds__(256) void gemm_h16_kernel(const TA* __restrict__ A,
                                                       const __half* __restrict__ W,
                                                       __half* __restrict__ C, int M) {
    extern __shared__ __half smh[];
    __half* As = smh;                 // [128][LDH]
    __half* Bs = smh + GBM * LDH;     // [128][LDH]
    const int tid  = threadIdx.x;
    const int wid  = tid >> 5;
    const int lane = tid & 31;
    const int warp_m = wid & 3;
    const int warp_n = wid >> 2;
    const int m0 = blockIdx.x * GBM;

#pragma unroll
    for (int it = 0; it < 8; it++) {
        int idx = tid + it * 256;
        int row = idx >> 4;
        int hg  = (idx & 15) * 8;
        uint4 pk = make_uint4(0u, 0u, 0u, 0u);
        if (m0 + row < M) {
            const TA* src = A + (size_t)(m0 + row) * DD + hg;
            if (sizeof(TA) == 2) {
                pk = *reinterpret_cast<const uint4*>(src);
            } else {
                const float4 f0 = *reinterpret_cast<const float4*>((const float*)src);
                const float4 f1 = *reinterpret_cast<const float4*>((const float*)src + 4);
                __half2 h0 = __floats2half2_rn(f0.x, f0.y);
                __half2 h1 = __floats2half2_rn(f0.z, f0.w);
                __half2 h2 = __floats2half2_rn(f1.x, f1.y);
                __half2 h3 = __floats2half2_rn(f1.z, f1.w);
                pk.x = *reinterpret_cast<uint32_t*>(&h0);
                pk.y = *reinterpret_cast<uint32_t*>(&h1);
                pk.z = *reinterpret_cast<uint32_t*>(&h2);
                pk.w = *reinterpret_cast<uint32_t*>(&h3);
            }
        }
        *reinterpret_cast<uint4*>(&As[row * LDH + hg]) = pk;
    }
#pragma unroll
    for (int it = 0; it < 8; it++) {
        int idx = tid + it * 256;
        int row = idx >> 4;
        int hg  = (idx & 15) * 8;
        uint4 pk = *reinterpret_cast<const uint4*>(W + (size_t)row * DD + hg);
        *reinterpret_cast<uint4*>(&Bs[row * LDH + hg]) = pk;
    }
    __syncthreads();

    float acc[2][8][4];
#pragma unroll
    for (int mi = 0; mi < 2; mi++)
#pragma unroll
        for (int ni = 0; ni < 8; ni++)
#pragma unroll
            for (int q = 0; q < 4; q++) acc[mi][ni][q] = 0.0f;

#pragma unroll
    for (int ks = 0; ks < 8; ks++) {
        const int kk = ks * 16;
        uint32_t a[2][4], b[8][2];
#pragma unroll
        for (int mi = 0; mi < 2; mi++) {
            uint32_t addr = smem_u32(&As[(warp_m * 32 + mi * 16 + (lane & 15)) * LDH
                                         + kk + (lane >> 4) * 8]);
            asm volatile("ldmatrix.sync.aligned.m8n8.x4.shared.b16 {%0,%1,%2,%3}, [%4];"
                         : "=r"(a[mi][0]), "=r"(a[mi][1]), "=r"(a[mi][2]), "=r"(a[mi][3])
                         : "r"(addr));
        }
#pragma unroll
        for (int nb = 0; nb < 4; nb++) {
            uint32_t addr = smem_u32(&Bs[(kk + (lane & 15)) * LDH
                                         + warp_n * 64 + nb * 16 + (lane >> 4) * 8]);
            asm volatile("ldmatrix.sync.aligned.m8n8.x4.trans.shared.b16 {%0,%1,%2,%3}, [%4];"
                         : "=r"(b[nb * 2][0]), "=r"(b[nb * 2][1]),
                           "=r"(b[nb * 2 + 1][0]), "=r"(b[nb * 2 + 1][1])
                         : "r"(addr));
        }
#pragma unroll
        for (int mi = 0; mi < 2; mi++)
#pragma unroll
            for (int ni = 0; ni < 8; ni++) {
                asm volatile(
                    "mma.sync.aligned.m16n8k16.row.col.f32.f16.f16.f32 "
                    "{%0,%1,%2,%3}, {%4,%5,%6,%7}, {%8,%9}, {%0,%1,%2,%3};\n"
                    : "+f"(acc[mi][ni][0]), "+f"(acc[mi][ni][1]),
                      "+f"(acc[mi][ni][2]), "+f"(acc[mi][ni][3])
                    : "r"(a[mi][0]), "r"(a[mi][1]), "r"(a[mi][2]), "r"(a[mi][3]),
                      "r"(b[ni][0]), "r"(b[ni][1]));
            }
    }
    // epilogue: scale by dinv[row], convert to fp16
    const int g   = lane >> 2;
    const int tig = lane & 3;
#pragma unroll
    for (int mi = 0; mi < 2; mi++) {
        int row0 = m0 + warp_m * 32 + mi * 16 + g;
        float dv0 = (row0 < M)     ? g_deg[row0]     : 0.0f;
        float dv1 = (row0 + 8 < M) ? g_deg[row0 + 8] : 0.0f;
#pragma unroll
        for (int ni = 0; ni < 8; ni++) {
            int col = warp_n * 64 + ni * 8 + tig * 2;
            if (row0 < M)
                *reinterpret_cast<__half2*>(C + (size_t)row0 * DD + col) =
                    __floats2half2_rn(acc[mi][ni][0] * dv0, acc[mi][ni][1] * dv0);
            if (row0 + 8 < M)
                *reinterpret_cast<__half2*>(C + (size_t)(row0 + 8) * DD + col) =
                    __floats2half2_rn(acc[mi][ni][2] * dv1, acc[mi][ni][3] * dv1);
        }
    }
}

// ---- warp-aggregate one node into a float4 (lane's 4-channel slice) ----------
__device__ __forceinline__ float4 warp_agg_node(const __half* __restrict__ Zl,
                                                int i, int end) {
    float4 acc = make_float4(0.f, 0.f, 0.f, 0.f);
    if ((i & 1) && i < end) {     // peel to even pair index for int4 loads
        int2 p = g_pair[i];
        float v = __int_as_float(p.y);
        const __half2* q = reinterpret_cast<const __half2*>(Zl + (size_t)p.x * DD);
        __half2 a = q[0], d = q[1];
        float2 f;
        f = __half22float2(a); acc.x = fmaf(v, f.x, acc.x); acc.y = fmaf(v, f.y, acc.y);
        f = __half22float2(d); acc.z = fmaf(v, f.x, acc.z); acc.w = fmaf(v, f.y, acc.w);
        i++;
    }
    for (; i + 8 <= end; i += 8) {
        int4 pA = *reinterpret_cast<const int4*>(&g_pair[i]);
        int4 pB = *reinterpret_cast<const int4*>(&g_pair[i + 2]);
        int4 pC = *reinterpret_cast<const int4*>(&g_pair[i + 4]);
        int4 pD = *reinterpret_cast<const int4*>(&g_pair[i + 6]);
        const __half2* q0 = reinterpret_cast<const __half2*>(Zl + (size_t)pA.x * DD);
        const __half2* q1 = reinterpret_cast<const __half2*>(Zl + (size_t)pA.z * DD);
        const __half2* q2 = reinterpret_cast<const __half2*>(Zl + (size_t)pB.x * DD);
        const __half2* q3 = reinterpret_cast<const __half2*>(Zl + (size_t)pB.z * DD);
        const __half2* q4 = reinterpret_cast<const __half2*>(Zl + (size_t)pC.x * DD);
        const __half2* q5 = reinterpret_cast<const __half2*>(Zl + (size_t)pC.z * DD);
        const __half2* q6 = reinterpret_cast<const __half2*>(Zl + (size_t)pD.x * DD);
        const __half2* q7 = reinterpret_cast<const __half2*>(Zl + (size_t)pD.z * DD);
        __half2 a0 = q0[0], b0 = q0[1];
        __half2 a1 = q1[0], b1 = q1[1];
        __half2 a2 = q2[0], b2 = q2[1];
        __half2 a3 = q3[0], b3 = q3[1];
        __half2 a4 = q4[0], b4 = q4[1];
        __half2 a5 = q5[0], b5 = q5[1];
        __half2 a6 = q6[0], b6 = q6[1];
        __half2 a7 = q7[0], b7 = q7[1];
        float v0 = __int_as_float(pA.y), v1 = __int_as_float(pA.w);
        float v2 = __int_as_float(pB.y), v3 = __int_as_float(pB.w);
        float v4 = __int_as_float(pC.y), v5 = __int_as_float(pC.w);
        float v6 = __int_as_float(pD.y), v7 = __int_as_float(pD.w);
        float2 f;
        f = __half22float2(a0); acc.x = fmaf(v0, f.x, acc.x); acc.y = fmaf(v0, f.y, acc.y);
        f = __half22float2(b0); acc.z = fmaf(v0, f.x, acc.z); acc.w = fmaf(v0, f.y, acc.w);
        f = __half22float2(a1); acc.x = fmaf(v1, f.x, acc.x); acc.y = fmaf(v1, f.y, acc.y);
        f = __half22float2(b1); acc.z = fmaf(v1, f.x, acc.z); acc.w = fmaf(v1, f.y, acc.w);
        f = __half22float2(a2); acc.x = fmaf(v2, f.x, acc.x); acc.y = fmaf(v2, f.y, acc.y);
        f = __half22float2(b2); acc.z = fmaf(v2, f.x, acc.z); acc.w = fmaf(v2, f.y, acc.w);
        f = __half22float2(a3); acc.x = fmaf(v3, f.x, acc.x); acc.y = fmaf(v3, f.y, acc.y);
        f = __half22float2(b3); acc.z = fmaf(v3, f.x, acc.z); acc.w = fmaf(v3, f.y, acc.w);
        f = __half22float2(a4); acc.x = fmaf(v4, f.x, acc.x); acc.y = fmaf(v4, f.y, acc.y);
        f = __half22float2(b4); acc.z = fmaf(v4, f.x, acc.z); acc.w = fmaf(v4, f.y, acc.w);
        f = __half22float2(a5); acc.x = fmaf(v5, f.x, acc.x); acc.y = fmaf(v5, f.y, acc.y);
        f = __half22float2(b5); acc.z = fmaf(v5, f.x, acc.z); acc.w = fmaf(v5, f.y, acc.w);
        f = __half22float2(a6); acc.x = fmaf(v6, f.x, acc.x); acc.y = fmaf(v6, f.y, acc.y);
        f = __half22float2(b6); acc.z = fmaf(v6, f.x, acc.z); acc.w = fmaf(v6, f.y, acc.w);
        f = __half22float2(a7); acc.x = fmaf(v7, f.x, acc.x); acc.y = fmaf(v7, f.y, acc.y);
        f = __half22float2(b7); acc.z = fmaf(v7, f.x, acc.z); acc.w = fmaf(v7, f.y, acc.w);
    }
    for (; i + 2 <= end; i += 2) {
        int4 pA = *reinterpret_cast<const int4*>(&g_pair[i]);
        float v0 = __int_as_float(pA.y), v1 = __int_as_float(pA.w);
        const __half2* q0 = reinterpret_cast<const __half2*>(Zl + (size_t)pA.x * DD);
        const __half2* q1 = reinterpret_cast<const __half2*>(Zl + (size_t)pA.z * DD);
        __half2 a0 = q0[0], b0 = q0[1];
        __half2 a1 = q1[0], b1 = q1[1];
        float2 f;
        f = __half22float2(a0); acc.x = fmaf(v0, f.x, acc.x); acc.y = fmaf(v0, f.y, acc.y);
        f = __half22float2(b0); acc.z = fmaf(v0, f.x, acc.z); acc.w = fmaf(v0, f.y, acc.w);
        f = __half22float2(a1); acc.x = fmaf(v1, f.x, acc.x); acc.y = fmaf(v1, f.y, acc.y);
        f = __half22float2(b1); acc.z = fmaf(v1, f.x, acc.z); acc.w = fmaf(v1, f.y, acc.w);
    }
    if (i < end) {
        int2 p = g_pair[i];
        float v = __int_as_float(p.y);
        const __half2* q = reinterpret_cast<const __half2*>(Zl + (size_t)p.x * DD);
        __half2 a = q[0], d = q[1];
        float2 f;
        f = __half22float2(a); acc.x = fmaf(v, f.x, acc.x); acc.y = fmaf(v, f.y, acc.y);
        f = __half22float2(d); acc.z = fmaf(v, f.x, acc.z); acc.w = fmaf(v, f.y, acc.w);
    }
    return acc;
}

// ------------- sparse aggregation: H[n] = relu(dinv[n]*sum + b) --------------
__global__ __launch_bounds__(256) void agg_kernel(const __half* __restrict__ Z,
                                                  const float* __restrict__ b,
                                                  __half* __restrict__ out) {
    int warp = (blockIdx.x * blockDim.x + threadIdx.x) >> 5;
    if (warp >= NN) return;
    int lane = threadIdx.x & 31;
    float dv = g_deg[warp];
    float4 acc = warp_agg_node(Z + lane * 4, g_rowptr[warp], g_rowptr[warp + 1]);
    const float4 bb = *reinterpret_cast<const float4*>(b + lane * 4);
    acc.x = fmaxf(fmaf(dv, acc.x, bb.x), 0.f);
    acc.y = fmaxf(fmaf(dv, acc.y, bb.y), 0.f);
    acc.z = fmaxf(fmaf(dv, acc.z, bb.z), 0.f);
    acc.w = fmaxf(fmaf(dv, acc.w, bb.w), 0.f);
    __half2 lo = __floats2half2_rn(acc.x, acc.y);
    __half2 hi = __floats2half2_rn(acc.z, acc.w);
    uint2 pk;
    pk.x = *reinterpret_cast<uint32_t*>(&lo);
    pk.y = *reinterpret_cast<uint32_t*>(&hi);
    *reinterpret_cast<uint2*>(out + (size_t)warp * DD + lane * 4) = pk;
}

// -- fused agg4 + gemm5: Z5s[n] = dinv[n] * ((dinv[n]*sum + b4) @ W5) ---------
__global__ __launch_bounds__(256) void agg_gemm5_kernel(const __half* __restrict__ Z,
                                                        const float* __restrict__ b4,
                                                        const float* __restrict__ W5,
                                                        float* __restrict__ Z5) {
    int warp = (blockIdx.x * blockDim.x + threadIdx.x) >> 5;
    if (warp >= NN) return;
    int lane = threadIdx.x & 31;
    float dv = g_deg[warp];
    float4 acc = warp_agg_node(Z + lane * 4, g_rowptr[warp], g_rowptr[warp + 1]);
    const float4 bb = *reinterpret_cast<const float4*>(b4 + lane * 4);
    acc.x = fmaf(dv, acc.x, bb.x);
    acc.y = fmaf(dv, acc.y, bb.y);
    acc.z = fmaf(dv, acc.z, bb.z);
    acc.w = fmaf(dv, acc.w, bb.w);
    const float4 w0 = *reinterpret_cast<const float4*>(W5 + lane * 8);
    const float4 w1 = *reinterpret_cast<const float4*>(W5 + lane * 8 + 4);
    float p0 = acc.x * w0.x + acc.y * w0.z + acc.z * w1.x + acc.w * w1.z;
    float p1 = acc.x * w0.y + acc.y * w0.w + acc.z * w1.y + acc.w * w1.w;
#pragma unroll
    for (int off = 16; off > 0; off >>= 1) {
        p0 += __shfl_down_sync(0xffffffffu, p0, off);
        p1 += __shfl_down_sync(0xffffffffu, p1, off);
    }
    if (lane == 0) {
        Z5[(size_t)warp * 2]     = p0 * dv;   // pre-scale for final aggregation
        Z5[(size_t)warp * 2 + 1] = p1 * dv;
    }
}

// -------- final aggregation: out[n] = dinv[n] * sum w*Z5s[src] + b5 ----------
__global__ __launch_bounds__(256) void agg5_kernel(const float* __restrict__ Z5,
                                                   const float* __restrict__ b5,
                                                   float* __restrict__ out) {
    int n = blockIdx.x * blockDim.x + threadIdx.x;
    if (n >= NN) return;
    float a0 = 0.f, a1 = 0.f;
    int i = g_rowptr[n];
    int end = g_rowptr[n + 1];
    for (; i < end; i++) {
        int2 p = g_pair[i];
        float v = __int_as_float(p.y);
        const float2 z = *reinterpret_cast<const float2*>(Z5 + (size_t)p.x * 2);
        a0 = fmaf(v, z.x, a0);
        a1 = fmaf(v, z.y, a1);
    }
    float dv = g_deg[n];
    out[(size_t)n * 2]     = fmaf(dv, a0, b5[0]);
    out[(size_t)n * 2 + 1] = fmaf(dv, a1, b5[1]);
}

// ---------------- driver ----------------
extern "C" void kernel_launch(void* const* d_in, const int* in_sizes, int n_in,
                              void* d_out, int out_size) {
    const float* x  = (const float*)d_in[0];
    const int*   ei = (const int*)d_in[1];       // int32 (JAX default, x64 disabled)
    const float* ew = (const float*)d_in[2];
    const float* W1 = (const float*)d_in[3];  const float* b1 = (const float*)d_in[4];
    const float* W2 = (const float*)d_in[5];  const float* b2 = (const float*)d_in[6];
    const float* W3 = (const float*)d_in[7];  const float* b3 = (const float*)d_in[8];
    const float* W4 = (const float*)d_in[9];  const float* b4 = (const float*)d_in[10];
    const float* W5 = (const float*)d_in[11]; const float* b5 = (const float*)d_in[12];
    float* out = (float*)d_out;

    __half *Zh, *HA, *HB, *Wh; float *Z5;
    cudaGetSymbolAddress((void**)&Zh, g_Zh);
    cudaGetSymbolAddress((void**)&HA, g_HA);
    cudaGetSymbolAddress((void**)&HB, g_HB);
    cudaGetSymbolAddress((void**)&Wh, g_Wh);
    cudaGetSymbolAddress((void**)&Z5, g_Z5);

    cudaFuncSetAttribute(gemm_h16_kernel<float>,
                         cudaFuncAttributeMaxDynamicSharedMemorySize, GEMM_SMEM);
    cudaFuncSetAttribute(gemm_h16_kernel<__half>,
                         cudaFuncAttributeMaxDynamicSharedMemorySize, GEMM_SMEM);

    // one-time side stream + fork/join events
    static cudaStream_t s_side = nullptr;
    static cudaEvent_t  s_ev0  = nullptr;   // fork at entry (convW)
    static cudaEvent_t  s_evA  = nullptr;   // after scanA (dinv ready)
    static cudaEvent_t  s_evB  = nullptr;   // after gemm1
    if (s_side == nullptr) {
        cudaStreamCreateWithFlags(&s_side, cudaStreamNonBlocking);
        cudaEventCreateWithFlags(&s_ev0, cudaEventDisableTiming);
        cudaEventCreateWithFlags(&s_evA, cudaEventDisableTiming);
        cudaEventCreateWithFlags(&s_evB, cudaEventDisableTiming);
    }

    const int TB = 256;
    const int gemm_blocks = (NN + GBM - 1) / GBM;
    const int agg_blocks  = (int)(((size_t)NN * 32 + TB - 1) / TB);

    // ---- fork at entry: convW on side stream (no dependencies) --------------
    cudaEventRecord(s_ev0, 0);
    cudaStreamWaitEvent(s_side, s_ev0, 0);
    convW_kernel<<<64, TB, 0, s_side>>>(W1, W2, W3, W4);

    // ---- main: deg_cnt -> scanA (produces dinv) -----------------------------
    deg_cnt_kernel<<<(EE + TB - 1) / TB, TB>>>(ei, ew);
    scanA_dinv_kernel<<<SCAN_NB, SCAN_CH>>>();
    cudaEventRecord(s_evA, 0);

    // ---- side: gemm1 (needs dinv + Wh); overlaps scanC + csr_fill -----------
    cudaStreamWaitEvent(s_side, s_evA, 0);
    gemm_h16_kernel<float><<<gemm_blocks, 256, GEMM_SMEM, s_side>>>(x, Wh, Zh, NN);
    cudaEventRecord(s_evB, s_side);

    // ---- main: scanC -> csr_fill (disjoint from gemm1's footprint) ----------
    scanC_kernel<<<SCAN_NB, SCAN_CH>>>();
    csr_fill_kernel<<<(EE + TB - 1) / TB, TB>>>(ei, ew);

    // ---- join, then the layer pipeline --------------------------------------
    cudaStreamWaitEvent(0, s_evB, 0);
    agg_kernel<<<agg_blocks, TB>>>(Zh, b1, HA);
    // layer 2
    gemm_h16_kernel<__half><<<gemm_blocks, 256, GEMM_SMEM>>>(HA, Wh + DD * DD, Zh, NN);
    agg_kernel<<<agg_blocks, TB>>>(Zh, b2, HB);
    // layer 3
    gemm_h16_kernel<__half><<<gemm_blocks, 256, GEMM_SMEM>>>(HB, Wh + 2 * DD * DD, Zh, NN);
    agg_kernel<<<agg_blocks, TB>>>(Zh, b3, HA);
    // layer 4 gemm, then fused agg4+gemm5
    gemm_h16_kernel<__half><<<gemm_blocks, 256, GEMM_SMEM>>>(HA, Wh + 3 * DD * DD, Zh, NN);
    agg_gemm5_kernel<<<agg_blocks, TB>>>(Zh, b4, W5, Z5);
    // final 2-wide aggregation
    agg5_kernel<<<(NN + TB - 1) / TB, TB>>>(Z5, b5, out);
}

// round 17
// speedup vs baseline: 1.9725x; 1.0126x over previous
#include <cuda_runtime.h>
#include <cuda_fp16.h>
#include <stdint.h>

#define NN 100000
#define EE 1600000
#define DD 128

#define SCAN_CH  1024
#define SCAN_NB  ((NN + SCAN_CH - 1) / SCAN_CH)   // 98

// ---------------- scratch (static __device__, no allocation) ----------------
__device__ unsigned long long g_degcnt[NN];  // packed {cnt[52:64), wsum_q32[0:52)}; zeroed by scanC
__device__ float  g_deg[NN];                 // dinv (pure scanA output)
__device__ int    g_cnt[NN];                 // decoded counts (scanA -> scanC)
__device__ int    g_seq[EE];                 // per-edge slot within dst row
__device__ int    g_rowptr[NN + 1];
__device__ int    g_bsum[SCAN_NB];
__device__ __align__(16) int2 g_pair[EE + NN];   // packed {col, w_bits}  (no dinv)
__device__ __half g_Wh[4 * DD * DD];    // fp16-converted W1..W4
__device__ __half g_Zh[NN * DD];        // post-GEMM features, PRE-SCALED by dinv[row]
__device__ __half g_HA[NN * DD];        // post-agg features, fp16
__device__ __half g_HB[NN * DD];
__device__ float  g_Z5[NN * 2];         // layer-5 logits, PRE-SCALED by dinv[row]

// ---------------- graph preprocessing ----------------
__global__ void deg_cnt_kernel(const int* __restrict__ ei,
                               const float* __restrict__ w) {
    int e = blockIdx.x * blockDim.x + threadIdx.x;
    if (e >= EE) return;
    int d = ei[EE + e];
    unsigned long long wq = (unsigned long long)((double)w[e] * 4294967296.0);
    unsigned long long old = atomicAdd(&g_degcnt[d], (1ull << 52) | wq);
    g_seq[e] = (int)(old >> 52);
}

__global__ __launch_bounds__(SCAN_CH) void scanA_dinv_kernel() {
    __shared__ int s[SCAN_CH];
    int t = threadIdx.x;
    int idx = blockIdx.x * SCAN_CH + t;
    int c = 0;
    if (idx < NN) {
        unsigned long long dc = g_degcnt[idx];
        c = (int)(dc >> 52);
        float wsum = (float)((double)(dc & ((1ull << 52) - 1ull)) * (1.0 / 4294967296.0));
        g_deg[idx] = rsqrtf(wsum + 1.0f);   // +1 = self-loop weight
        g_cnt[idx] = c;
    }
    s[t] = c;
    __syncthreads();
    for (int off = SCAN_CH >> 1; off > 0; off >>= 1) {
        if (t < off) s[t] += s[t + off];
        __syncthreads();
    }
    if (t == 0) g_bsum[blockIdx.x] = s[0];
}

__global__ __launch_bounds__(SCAN_CH) void scanC_kernel() {
    __shared__ int s[SCAN_CH];
    __shared__ int bpre[SCAN_NB];
    int t = threadIdx.x;
    int idx = blockIdx.x * SCAN_CH + t;
    int my = (idx < NN) ? g_cnt[idx] : 0;
    s[t] = my;
    if (t < SCAN_NB) bpre[t] = g_bsum[t];
    __syncthreads();
    for (int off = 1; off < SCAN_NB; off <<= 1) {
        int u = 0;
        if (t >= off && t < SCAN_NB) u = bpre[t - off];
        __syncthreads();
        if (t < SCAN_NB) bpre[t] += u;
        __syncthreads();
    }
    for (int off = 1; off < SCAN_CH; off <<= 1) {
        int u = 0;
        if (t >= off) u = s[t - off];
        __syncthreads();
        s[t] += u;
        __syncthreads();
    }
    int boff = (blockIdx.x == 0) ? 0 : bpre[blockIdx.x - 1];
    if (idx < NN) {
        int rp = boff + (s[t] - my) + idx;       // +idx = self-loop slots
        g_rowptr[idx] = rp;
        g_pair[rp] = make_int2(idx, __float_as_int(1.0f));   // self-loop weight 1
        g_degcnt[idx] = 0ull;                    // re-zero for next call
    }
    if (idx == NN - 1) g_rowptr[NN] = EE + NN;   // known total
}

__global__ void csr_fill_kernel(const int* __restrict__ ei,
                                const float* __restrict__ w) {
    int e = blockIdx.x * blockDim.x + threadIdx.x;
    if (e >= EE) return;
    int s = ei[e];
    int d = ei[EE + e];
    int pos = g_rowptr[d] + 1 + g_seq[e];
    g_pair[pos] = make_int2(s, __float_as_int(w[e]));
}

__global__ __launch_bounds__(256) void convW_kernel(const float* __restrict__ W1,
                                                    const float* __restrict__ W2,
                                                    const float* __restrict__ W3,
                                                    const float* __restrict__ W4) {
    int idx = blockIdx.x * blockDim.x + threadIdx.x;
    int which = idx >> 12;
    int off   = (idx & 4095) * 4;
    const float* W = (which == 0) ? W1 : (which == 1) ? W2 : (which == 2) ? W3 : W4;
    float4 f = *reinterpret_cast<const float4*>(W + off);
    __half2 h0 = __floats2half2_rn(f.x, f.y);
    __half2 h1 = __floats2half2_rn(f.z, f.w);
    uint2 pk;
    pk.x = *reinterpret_cast<uint32_t*>(&h0);
    pk.y = *reinterpret_cast<uint32_t*>(&h1);
    *reinterpret_cast<uint2*>(&g_Wh[which * DD * DD + off]) = pk;
}

// ---------------- fp16 tensor-core GEMM infrastructure ----------------
#define GBM 128
#define LDH 136
#define GEMM_SMEM (2 * GBM * LDH * (int)sizeof(__half))   // 69632

__device__ __forceinline__ uint32_t smem_u32(const void* p) {
    return (uint32_t)__cvta_generic_to_shared(p);
}

__device__ __forceinline__ void cp_async16(uint32_t dst, const void* src, bool valid) {
    int sz = valid ? 16 : 0;
    asm volatile("cp.async.cg.shared.global [%0], [%1], 16, %2;"
                 :: "r"(dst), "l"(src), "r"(sz));
}

// compute 4 consecutive k-steps (k16 each) of the warp tile
__device__ __forceinline__ void gemm_ks4(const __half* As, const __half* Bs,
                                         int warp_m, int warp_n, int lane,
                                         int ks0, float acc[2][8][4]) {
#pragma unroll
    for (int ks = ks0; ks < ks0 + 4; ks++) {
        const int kk = ks * 16;
        uint32_t a[2][4], b[8][2];
#pragma unroll
        for (int mi = 0; mi < 2; mi++) {
            uint32_t addr = smem_u32(&As[(warp_m * 32 + mi * 16 + (lane & 15)) * LDH
                                         + kk + (lane >> 4) * 8]);
            asm volatile("ldmatrix.sync.aligned.m8n8.x4.shared.b16 {%0,%1,%2,%3}, [%4];"
                         : "=r"(a[mi][0]), "=r"(a[mi][1]), "=r"(a[mi][2]), "=r"(a[mi][3])
                         : "r"(addr));
        }
#pragma unroll
        for (int nb = 0; nb < 4; nb++) {
            uint32_t addr = smem_u32(&Bs[(kk + (lane & 15)) * LDH
                                         + warp_n * 64 + nb * 16 + (lane >> 4) * 8]);
            asm volatile("ldmatrix.sync.aligned.m8n8.x4.trans.shared.b16 {%0,%1,%2,%3}, [%4];"
                         : "=r"(b[nb * 2][0]), "=r"(b[nb * 2][1]),
                           "=r"(b[nb * 2 + 1][0]), "=r"(b[nb * 2 + 1][1])
                         : "r"(addr));
        }
#pragma unroll
        for (int mi = 0; mi < 2; mi++)
#pragma unroll
            for (int ni = 0; ni < 8; ni++) {
                asm volatile(
                    "mma.sync.aligned.m16n8k16.row.col.f32.f16.f16.f32 "
                    "{%0,%1,%2,%3}, {%4,%5,%6,%7}, {%8,%9}, {%0,%1,%2,%3};\n"
                    : "+f"(acc[mi][ni][0]), "+f"(acc[mi][ni][1]),
                      "+f"(acc[mi][ni][2]), "+f"(acc[mi][ni][3])
                    : "r"(a[mi][0]), "r"(a[mi][1]), "r"(a[mi][2]), "r"(a[mi][3]),
                      "r"(b[ni][0]), "r"(b[ni][1]));
            }
    }
}

__device__ __forceinline__ void gemm_epilogue(float acc[2][8][4], __half* C,
                                              int m0, int warp_m, int warp_n,
                                              int lane, int M) {
    const int g   = lane >> 2;
    const int tig = lane & 3;
#pragma unroll
    for (int mi = 0; mi < 2; mi++) {
        int row0 = m0 + warp_m * 32 + mi * 16 + g;
        float dv0 = (row0 < M)     ? g_deg[row0]     : 0.0f;
        float dv1 = (row0 + 8 < M) ? g_deg[row0 + 8] : 0.0f;
#pragma unroll
        for (int ni = 0; ni < 8; ni++) {
            int col = warp_n * 64 + ni * 8 + tig * 2;
            if (row0 < M)
                *reinterpret_cast<__half2*>(C + (size_t)row0 * DD + col) =
                    __floats2half2_rn(acc[mi][ni][0] * dv0, acc[mi][ni][1] * dv0);
            if (row0 + 8 < M)
                *reinterpret_cast<__half2*>(C + (size_t)(row0 + 8) * DD + col) =
                    __floats2half2_rn(acc[mi][ni][2] * dv1, acc[mi][ni][3] * dv1);
        }
    }
}

// ---- layer-1 GEMM: A fp32, synchronous convert loads (runs under preproc overlap)
__global__ __launch_bounds__(256) void gemm_f32_kernel(const float* __restrict__ A,
                                                       const __half* __restrict__ W,
                                                       __half* __restrict__ C, int M) {
    extern __shared__ __half smh[];
    __half* As = smh;
    __half* Bs = smh + GBM * LDH;
    const int tid  = threadIdx.x;
    const int wid  = tid >> 5;
    const int lane = tid & 31;
    const int warp_m = wid & 3;
    const int warp_n = wid >> 2;
    const int m0 = blockIdx.x * GBM;

#pragma unroll
    for (int it = 0; it < 8; it++) {
        int idx = tid + it * 256;
        int row = idx >> 4;
        int hg  = (idx & 15) * 8;
        uint4 pk = make_uint4(0u, 0u, 0u, 0u);
        if (m0 + row < M) {
            const float* src = A + (size_t)(m0 + row) * DD + hg;
            const float4 f0 = *reinterpret_cast<const float4*>(src);
            const float4 f1 = *reinterpret_cast<const float4*>(src + 4);
            __half2 h0 = __floats2half2_rn(f0.x, f0.y);
            __half2 h1 = __floats2half2_rn(f0.z, f0.w);
            __half2 h2 = __floats2half2_rn(f1.x, f1.y);
            __half2 h3 = __floats2half2_rn(f1.z, f1.w);
            pk.x = *reinterpret_cast<uint32_t*>(&h0);
            pk.y = *reinterpret_cast<uint32_t*>(&h1);
            pk.z = *reinterpret_cast<uint32_t*>(&h2);
            pk.w = *reinterpret_cast<uint32_t*>(&h3);
        }
        *reinterpret_cast<uint4*>(&As[row * LDH + hg]) = pk;
    }
#pragma unroll
    for (int it = 0; it < 8; it++) {
        int idx = tid + it * 256;
        int row = idx >> 4;
        int hg  = (idx & 15) * 8;
        uint4 pk = *reinterpret_cast<const uint4*>(W + (size_t)row * DD + hg);
        *reinterpret_cast<uint4*>(&Bs[row * LDH + hg]) = pk;
    }
    __syncthreads();

    float acc[2][8][4];
#pragma unroll
    for (int mi = 0; mi < 2; mi++)
#pragma unroll
        for (int ni = 0; ni < 8; ni++)
#pragma unroll
            for (int q = 0; q < 4; q++) acc[mi][ni][q] = 0.0f;

    gemm_ks4(As, Bs, warp_m, warp_n, lane, 0, acc);
    gemm_ks4(As, Bs, warp_m, warp_n, lane, 4, acc);
    gemm_epilogue(acc, C, m0, warp_m, warp_n, lane, M);
}

// ---- layers 2-4 GEMM: A fp16, cp.async 2-stage K pipeline -------------------
__global__ __launch_bounds__(256) void gemm_h16_pipe_kernel(const __half* __restrict__ A,
                                                            const __half* __restrict__ W,
                                                            __half* __restrict__ C, int M) {
    extern __shared__ __half smh[];
    __half* As = smh;
    __half* Bs = smh + GBM * LDH;
    const int tid  = threadIdx.x;
    const int wid  = tid >> 5;
    const int lane = tid & 31;
    const int warp_m = wid & 3;
    const int warp_n = wid >> 2;
    const int m0 = blockIdx.x * GBM;

    // ---- stage 0: A cols 0-63, W rows 0-63 ----
#pragma unroll
    for (int it = 0; it < 4; it++) {
        int idx = tid + it * 256;            // 0..1023
        int row = idx >> 3;                  // 0..127
        int hg  = (idx & 7) * 8;             // 0..56  (cols 0-63)
        bool v = (m0 + row < M);
        cp_async16(smem_u32(&As[row * LDH + hg]),
                   A + (size_t)(m0 + row) * DD + hg, v);
    }
#pragma unroll
    for (int it = 0; it < 4; it++) {
        int idx = tid + it * 256;
        int row = idx >> 4;                  // 0..63
        int hg  = (idx & 15) * 8;            // 0..120
        cp_async16(smem_u32(&Bs[row * LDH + hg]),
                   W + (size_t)row * DD + hg, true);
    }
    asm volatile("cp.async.commit_group;" ::: "memory");
    // ---- stage 1: A cols 64-127, W rows 64-127 ----
#pragma unroll
    for (int it = 0; it < 4; it++) {
        int idx = tid + it * 256;
        int row = idx >> 3;
        int hg  = (idx & 7) * 8 + 64;
        bool v = (m0 + row < M);
        cp_async16(smem_u32(&As[row * LDH + hg]),
                   A + (size_t)(m0 + row) * DD + hg, v);
    }
#pragma unroll
    for (int it = 0; it < 4; it++) {
        int idx = tid + it * 256;
        int row = (idx >> 4) + 64;
        int hg  = (idx & 15) * 8;
        cp_async16(smem_u32(&Bs[row * LDH + hg]),
                   W + (size_t)row * DD + hg, true);
    }
    asm volatile("cp.async.commit_group;" ::: "memory");

    float acc[2][8][4];
#pragma unroll
    for (int mi = 0; mi < 2; mi++)
#pragma unroll
        for (int ni = 0; ni < 8; ni++)
#pragma unroll
            for (int q = 0; q < 4; q++) acc[mi][ni][q] = 0.0f;

    asm volatile("cp.async.wait_group 1;" ::: "memory");
    __syncthreads();
    gemm_ks4(As, Bs, warp_m, warp_n, lane, 0, acc);   // k 0-63 while stage 1 lands
    asm volatile("cp.async.wait_group 0;" ::: "memory");
    __syncthreads();
    gemm_ks4(As, Bs, warp_m, warp_n, lane, 4, acc);   // k 64-127
    gemm_epilogue(acc, C, m0, warp_m, warp_n, lane, M);
}

// ---- warp-aggregate one node into a float4 (lane's 4-channel slice) ----------
__device__ __forceinline__ float4 warp_agg_node(const __half* __restrict__ Zl,
                                                int i, int end) {
    float4 acc = make_float4(0.f, 0.f, 0.f, 0.f);
    if ((i & 1) && i < end) {
        int2 p = g_pair[i];
        float v = __int_as_float(p.y);
        const __half2* q = reinterpret_cast<const __half2*>(Zl + (size_t)p.x * DD);
        __half2 a = q[0], d = q[1];
        float2 f;
        f = __half22float2(a); acc.x = fmaf(v, f.x, acc.x); acc.y = fmaf(v, f.y, acc.y);
        f = __half22float2(d); acc.z = fmaf(v, f.x, acc.z); acc.w = fmaf(v, f.y, acc.w);
        i++;
    }
    for (; i + 8 <= end; i += 8) {
        int4 pA = *reinterpret_cast<const int4*>(&g_pair[i]);
        int4 pB = *reinterpret_cast<const int4*>(&g_pair[i + 2]);
        int4 pC = *reinterpret_cast<const int4*>(&g_pair[i + 4]);
        int4 pD = *reinterpret_cast<const int4*>(&g_pair[i + 6]);
        const __half2* q0 = reinterpret_cast<const __half2*>(Zl + (size_t)pA.x * DD);
        const __half2* q1 = reinterpret_cast<const __half2*>(Zl + (size_t)pA.z * DD);
        const __half2* q2 = reinterpret_cast<const __half2*>(Zl + (size_t)pB.x * DD);
        const __half2* q3 = reinterpret_cast<const __half2*>(Zl + (size_t)pB.z * DD);
        const __half2* q4 = reinterpret_cast<const __half2*>(Zl + (size_t)pC.x * DD);
        const __half2* q5 = reinterpret_cast<const __half2*>(Zl + (size_t)pC.z * DD);
        const __half2* q6 = reinterpret_cast<const __half2*>(Zl + (size_t)pD.x * DD);
        const __half2* q7 = reinterpret_cast<const __half2*>(Zl + (size_t)pD.z * DD);
        __half2 a0 = q0[0], b0 = q0[1];
        __half2 a1 = q1[0], b1 = q1[1];
        __half2 a2 = q2[0], b2 = q2[1];
        __half2 a3 = q3[0], b3 = q3[1];
        __half2 a4 = q4[0], b4 = q4[1];
        __half2 a5 = q5[0], b5 = q5[1];
        __half2 a6 = q6[0], b6 = q6[1];
        __half2 a7 = q7[0], b7 = q7[1];
        float v0 = __int_as_float(pA.y), v1 = __int_as_float(pA.w);
        float v2 = __int_as_float(pB.y), v3 = __int_as_float(pB.w);
        float v4 = __int_as_float(pC.y), v5 = __int_as_float(pC.w);
        float v6 = __int_as_float(pD.y), v7 = __int_as_float(pD.w);
        float2 f;
        f = __half22float2(a0); acc.x = fmaf(v0, f.x, acc.x); acc.y = fmaf(v0, f.y, acc.y);
        f = __half22float2(b0); acc.z = fmaf(v0, f.x, acc.z); acc.w = fmaf(v0, f.y, acc.w);
        f = __half22float2(a1); acc.x = fmaf(v1, f.x, acc.x); acc.y = fmaf(v1, f.y, acc.y);
        f = __half22float2(b1); acc.z = fmaf(v1, f.x, acc.z); acc.w = fmaf(v1, f.y, acc.w);
        f = __half22float2(a2); acc.x = fmaf(v2, f.x, acc.x); acc.y = fmaf(v2, f.y, acc.y);
        f = __half22float2(b2); acc.z = fmaf(v2, f.x, acc.z); acc.w = fmaf(v2, f.y, acc.w);
        f = __half22float2(a3); acc.x = fmaf(v3, f.x, acc.x); acc.y = fmaf(v3, f.y, acc.y);
        f = __half22float2(b3); acc.z = fmaf(v3, f.x, acc.z); acc.w = fmaf(v3, f.y, acc.w);
        f = __half22float2(a4); acc.x = fmaf(v4, f.x, acc.x); acc.y = fmaf(v4, f.y, acc.y);
        f = __half22float2(b4); acc.z = fmaf(v4, f.x, acc.z); acc.w = fmaf(v4, f.y, acc.w);
        f = __half22float2(a5); acc.x = fmaf(v5, f.x, acc.x); acc.y = fmaf(v5, f.y, acc.y);
        f = __half22float2(b5); acc.z = fmaf(v5, f.x, acc.z); acc.w = fmaf(v5, f.y, acc.w);
        f = __half22float2(a6); acc.x = fmaf(v6, f.x, acc.x); acc.y = fmaf(v6, f.y, acc.y);
        f = __half22float2(b6); acc.z = fmaf(v6, f.x, acc.z); acc.w = fmaf(v6, f.y, acc.w);
        f = __half22float2(a7); acc.x = fmaf(v7, f.x, acc.x); acc.y = fmaf(v7, f.y, acc.y);
        f = __half22float2(b7); acc.z = fmaf(v7, f.x, acc.z); acc.w = fmaf(v7, f.y, acc.w);
    }
    for (; i + 2 <= end; i += 2) {
        int4 pA = *reinterpret_cast<const int4*>(&g_pair[i]);
        float v0 = __int_as_float(pA.y), v1 = __int_as_float(pA.w);
        const __half2* q0 = reinterpret_cast<const __half2*>(Zl + (size_t)pA.x * DD);
        const __half2* q1 = reinterpret_cast<const __half2*>(Zl + (size_t)pA.z * DD);
        __half2 a0 = q0[0], b0 = q0[1];
        __half2 a1 = q1[0], b1 = q1[1];
        float2 f;
        f = __half22float2(a0); acc.x = fmaf(v0, f.x, acc.x); acc.y = fmaf(v0, f.y, acc.y);
        f = __half22float2(b0); acc.z = fmaf(v0, f.x, acc.z); acc.w = fmaf(v0, f.y, acc.w);
        f = __half22float2(a1); acc.x = fmaf(v1, f.x, acc.x); acc.y = fmaf(v1, f.y, acc.y);
        f = __half22float2(b1); acc.z = fmaf(v1, f.x, acc.z); acc.w = fmaf(v1, f.y, acc.w);
    }
    if (i < end) {
        int2 p = g_pair[i];
        float v = __int_as_float(p.y);
        const __half2* q = reinterpret_cast<const __half2*>(Zl + (size_t)p.x * DD);
        __half2 a = q[0], d = q[1];
        float2 f;
        f = __half22float2(a); acc.x = fmaf(v, f.x, acc.x); acc.y = fmaf(v, f.y, acc.y);
        f = __half22float2(d); acc.z = fmaf(v, f.x, acc.z); acc.w = fmaf(v, f.y, acc.w);
    }
    return acc;
}

// ------------- sparse aggregation: H[n] = relu(dinv[n]*sum + b) --------------
__global__ __launch_bounds__(256) void agg_kernel(const __half* __restrict__ Z,
                                                  const float* __restrict__ b,
                                                  __half* __restrict__ out) {
    int warp = (blockIdx.x * blockDim.x + threadIdx.x) >> 5;
    if (warp >= NN) return;
    int lane = threadIdx.x & 31;
    float dv = g_deg[warp];
    float4 acc = warp_agg_node(Z + lane * 4, g_rowptr[warp], g_rowptr[warp + 1]);
    const float4 bb = *reinterpret_cast<const float4*>(b + lane * 4);
    acc.x = fmaxf(fmaf(dv, acc.x, bb.x), 0.f);
    acc.y = fmaxf(fmaf(dv, acc.y, bb.y), 0.f);
    acc.z = fmaxf(fmaf(dv, acc.z, bb.z), 0.f);
    acc.w = fmaxf(fmaf(dv, acc.w, bb.w), 0.f);
    __half2 lo = __floats2half2_rn(acc.x, acc.y);
    __half2 hi = __floats2half2_rn(acc.z, acc.w);
    uint2 pk;
    pk.x = *reinterpret_cast<uint32_t*>(&lo);
    pk.y = *reinterpret_cast<uint32_t*>(&hi);
    *reinterpret_cast<uint2*>(out + (size_t)warp * DD + lane * 4) = pk;
}

// -- fused agg4 + gemm5: Z5s[n] = dinv[n] * ((dinv[n]*sum + b4) @ W5) ---------
__global__ __launch_bounds__(256) void agg_gemm5_kernel(const __half* __restrict__ Z,
                                                        const float* __restrict__ b4,
                                                        const float* __restrict__ W5,
                                                        float* __restrict__ Z5) {
    int warp = (blockIdx.x * blockDim.x + threadIdx.x) >> 5;
    if (warp >= NN) return;
    int lane = threadIdx.x & 31;
    float dv = g_deg[warp];
    float4 acc = warp_agg_node(Z + lane * 4, g_rowptr[warp], g_rowptr[warp + 1]);
    const float4 bb = *reinterpret_cast<const float4*>(b4 + lane * 4);
    acc.x = fmaf(dv, acc.x, bb.x);
    acc.y = fmaf(dv, acc.y, bb.y);
    acc.z = fmaf(dv, acc.z, bb.z);
    acc.w = fmaf(dv, acc.w, bb.w);
    const float4 w0 = *reinterpret_cast<const float4*>(W5 + lane * 8);
    const float4 w1 = *reinterpret_cast<const float4*>(W5 + lane * 8 + 4);
    float p0 = acc.x * w0.x + acc.y * w0.z + acc.z * w1.x + acc.w * w1.z;
    float p1 = acc.x * w0.y + acc.y * w0.w + acc.z * w1.y + acc.w * w1.w;
#pragma unroll
    for (int off = 16; off > 0; off >>= 1) {
        p0 += __shfl_down_sync(0xffffffffu, p0, off);
        p1 += __shfl_down_sync(0xffffffffu, p1, off);
    }
    if (lane == 0) {
        Z5[(size_t)warp * 2]     = p0 * dv;
        Z5[(size_t)warp * 2 + 1] = p1 * dv;
    }
}

// -------- final aggregation: out[n] = dinv[n] * sum w*Z5s[src] + b5 ----------
__global__ __launch_bounds__(256) void agg5_kernel(const float* __restrict__ Z5,
                                                   const float* __restrict__ b5,
                                                   float* __restrict__ out) {
    int n = blockIdx.x * blockDim.x + threadIdx.x;
    if (n >= NN) return;
    float a0 = 0.f, a1 = 0.f;
    int i = g_rowptr[n];
    int end = g_rowptr[n + 1];
    for (; i < end; i++) {
        int2 p = g_pair[i];
        float v = __int_as_float(p.y);
        const float2 z = *reinterpret_cast<const float2*>(Z5 + (size_t)p.x * 2);
        a0 = fmaf(v, z.x, a0);
        a1 = fmaf(v, z.y, a1);
    }
    float dv = g_deg[n];
    out[(size_t)n * 2]     = fmaf(dv, a0, b5[0]);
    out[(size_t)n * 2 + 1] = fmaf(dv, a1, b5[1]);
}

// ---------------- driver ----------------
extern "C" void kernel_launch(void* const* d_in, const int* in_sizes, int n_in,
                              void* d_out, int out_size) {
    const float* x  = (const float*)d_in[0];
    const int*   ei = (const int*)d_in[1];       // int32 (JAX default, x64 disabled)
    const float* ew = (const float*)d_in[2];
    const float* W1 = (const float*)d_in[3];  const float* b1 = (const float*)d_in[4];
    const float* W2 = (const float*)d_in[5];  const float* b2 = (const float*)d_in[6];
    const float* W3 = (const float*)d_in[7];  const float* b3 = (const float*)d_in[8];
    const float* W4 = (const float*)d_in[9];  const float* b4 = (const float*)d_in[10];
    const float* W5 = (const float*)d_in[11]; const float* b5 = (const float*)d_in[12];
    float* out = (float*)d_out;

    __half *Zh, *HA, *HB, *Wh; float *Z5;
    cudaGetSymbolAddress((void**)&Zh, g_Zh);
    cudaGetSymbolAddress((void**)&HA, g_HA);
    cudaGetSymbolAddress((void**)&HB, g_HB);
    cudaGetSymbolAddress((void**)&Wh, g_Wh);
    cudaGetSymbolAddress((void**)&Z5, g_Z5);

    cudaFuncSetAttribute(gemm_f32_kernel,
                         cudaFuncAttributeMaxDynamicSharedMemorySize, GEMM_SMEM);
    cudaFuncSetAttribute(gemm_h16_pipe_kernel,
                         cudaFuncAttributeMaxDynamicSharedMemorySize, GEMM_SMEM);

    static cudaStream_t s_side = nullptr;
    static cudaEvent_t  s_ev0  = nullptr;
    static cudaEvent_t  s_evA  = nullptr;
    static cudaEvent_t  s_evB  = nullptr;
    if (s_side == nullptr) {
        cudaStreamCreateWithFlags(&s_side, cudaStreamNonBlocking);
        cudaEventCreateWithFlags(&s_ev0, cudaEventDisableTiming);
        cudaEventCreateWithFlags(&s_evA, cudaEventDisableTiming);
        cudaEventCreateWithFlags(&s_evB, cudaEventDisableTiming);
    }

    const int TB = 256;
    const int gemm_blocks = (NN + GBM - 1) / GBM;
    const int agg_blocks  = (int)(((size_t)NN * 32 + TB - 1) / TB);

    // ---- fork at entry: convW on side stream (no dependencies) --------------
    cudaEventRecord(s_ev0, 0);
    cudaStreamWaitEvent(s_side, s_ev0, 0);
    convW_kernel<<<64, TB, 0, s_side>>>(W1, W2, W3, W4);

    // ---- main: deg_cnt -> scanA (produces dinv) -----------------------------
    deg_cnt_kernel<<<(EE + TB - 1) / TB, TB>>>(ei, ew);
    scanA_dinv_kernel<<<SCAN_NB, SCAN_CH>>>();
    cudaEventRecord(s_evA, 0);

    // ---- side: gemm1 (needs dinv + Wh); overlaps scanC + csr_fill -----------
    cudaStreamWaitEvent(s_side, s_evA, 0);
    gemm_f32_kernel<<<gemm_blocks, 256, GEMM_SMEM, s_side>>>(x, Wh, Zh, NN);
    cudaEventRecord(s_evB, s_side);

    // ---- main: scanC -> csr_fill (disjoint from gemm1's footprint) ----------
    scanC_kernel<<<SCAN_NB, SCAN_CH>>>();
    csr_fill_kernel<<<(EE + TB - 1) / TB, TB>>>(ei, ew);

    // ---- join, then the layer pipeline --------------------------------------
    cudaStreamWaitEvent(0, s_evB, 0);
    agg_kernel<<<agg_blocks, TB>>>(Zh, b1, HA);
    // layer 2
    gemm_h16_pipe_kernel<<<gemm_blocks, 256, GEMM_SMEM>>>(HA, Wh + DD * DD, Zh, NN);
    agg_kernel<<<agg_blocks, TB>>>(Zh, b2, HB);
    // layer 3
    gemm_h16_pipe_kernel<<<gemm_blocks, 256, GEMM_SMEM>>>(HB, Wh + 2 * DD * DD, Zh, NN);
    agg_kernel<<<agg_blocks, TB>>>(Zh, b3, HA);
    // layer 4 gemm, then fused agg4+gemm5
    gemm_h16_pipe_kernel<<<gemm_blocks, 256, GEMM_SMEM>>>(HA, Wh + 3 * DD * DD, Zh, NN);
    agg_gemm5_kernel<<<agg_blocks, TB>>>(Zh, b4, W5, Z5);
    // final 2-wide aggregation
    agg5_kernel<<<(NN + TB - 1) / TB, TB>>>(Z5, b5, out);
}